// round 2
// baseline (speedup 1.0000x reference)
#include <cuda_runtime.h>
#include <math.h>

// ---------------- problem constants ----------------
#define N_BATCH 64
#define SLOPE 0.01f

// conv1: in [64,1,92,92,92] w[16,1,6,6,6] s2 -> [64,16,44,44,44]
// conv2: in [64,16,44,44,44] w[32,16,5,5,5] s3 -> [64,32,14,14,14]
// conv3: in [64,32,14,14,14] w[48,32,5,5,5] s3 -> [64,48,4,4,4]
// conv4: in [64,48,4,4,4]  w[64,48,3,3,3] s1 -> [64,64,2,2,2]
// feature [64,512]; M = feature@T -> [64,1024] -> [64,64,16]
// outT[i,c] = sum_j exp(sum_k |M[i,c,k]-M[j,c,k]|)
// z = [feature|outT] @ Wm + bm ; sigmoid

// ---------------- scratch (static device globals; no cudaMalloc allowed) ---
__device__ float g_c1[64ull * 16 * 44 * 44 * 44];   // 349 MB
__device__ float g_c2[64 * 32 * 14 * 14 * 14];      // 22.5 MB
__device__ float g_c3[64 * 48 * 64];
__device__ float g_feat[64 * 512];
__device__ float g_M[64 * 1024];
__device__ float g_outT[64 * 64];

__device__ __forceinline__ float leaky(float v) {
    return v >= 0.f ? v : SLOPE * v;
}

// =======================================================================
// conv1: tile Td=4,Th=4,Tw=16 per block; 256 thr; thread = 1 voxel x 16ch
// =======================================================================
__global__ __launch_bounds__(256) void conv1_kernel(
    const float* __restrict__ x, const float* __restrict__ w1,
    const float* __restrict__ b1)
{
    const int wt = blockIdx.x % 3;     // w tile (0..2), 16 wide
    const int ht = blockIdx.x / 3;     // h tile (0..10), 4 tall
    const int dt = blockIdx.y;         // d tile (0..10), 4 deep
    const int n  = blockIdx.z;

    __shared__ float sIn[12 * 12 * 36];   // input tile
    __shared__ float sW[216 * 16];        // weights tap-major

    const int tid = threadIdx.x;

    // load weights transposed: sW[tap*16 + c]
    for (int idx = tid; idx < 16 * 216; idx += 256) {
        int c = idx / 216, tap = idx % 216;
        sW[tap * 16 + c] = w1[idx];
    }

    // load input tile [12][12][36]
    const int id0 = dt * 8, ih0 = ht * 8, iw0 = wt * 32;
    const float* xb = x + (size_t)n * 778688;  // 92^3
    for (int idx = tid; idx < 12 * 12 * 36; idx += 256) {
        int ld = idx / 432;
        int r  = idx % 432;
        int lh = r / 36, lw = r % 36;
        int gw = iw0 + lw;
        float v = 0.f;
        if (gw < 92)
            v = xb[(id0 + ld) * 8464 + (ih0 + lh) * 92 + gw];
        sIn[idx] = v;
    }
    __syncthreads();

    const int tw = tid & 15;
    const int th = (tid >> 4) & 3;
    const int td = tid >> 6;
    const int ow = wt * 16 + tw;
    if (ow >= 44) return;
    const int oh = ht * 4 + th;
    const int od = dt * 4 + td;

    float acc[16];
    #pragma unroll
    for (int c = 0; c < 16; c++) acc[c] = b1[c];

    const float4* sW4 = (const float4*)sW;
    #pragma unroll
    for (int kd = 0; kd < 6; kd++) {
        #pragma unroll
        for (int kh = 0; kh < 6; kh++) {
            #pragma unroll
            for (int kw = 0; kw < 6; kw++) {
                float v = sIn[(2 * td + kd) * 432 + (2 * th + kh) * 36 + (2 * tw + kw)];
                int tap = (kd * 6 + kh) * 6 + kw;
                #pragma unroll
                for (int q = 0; q < 4; q++) {
                    float4 w = sW4[tap * 4 + q];
                    acc[q * 4 + 0] = fmaf(v, w.x, acc[q * 4 + 0]);
                    acc[q * 4 + 1] = fmaf(v, w.y, acc[q * 4 + 1]);
                    acc[q * 4 + 2] = fmaf(v, w.z, acc[q * 4 + 2]);
                    acc[q * 4 + 3] = fmaf(v, w.w, acc[q * 4 + 3]);
                }
            }
        }
    }

    size_t obase = ((size_t)n * 16) * 85184 + (size_t)od * 1936 + oh * 44 + ow;
    #pragma unroll
    for (int c = 0; c < 16; c++)
        g_c1[obase + (size_t)c * 85184] = leaky(acc[c]);
}

// =======================================================================
// conv2: block = (n, od, h-half). 98 positions x 32ch; thread = pos x 16ch
// =======================================================================
__global__ __launch_bounds__(256) void conv2_kernel(
    const float* __restrict__ w2, const float* __restrict__ b2)
{
    const int od = blockIdx.x >> 1;
    const int hh = blockIdx.x & 1;
    const int n  = blockIdx.y;

    __shared__ float sIn[5 * 23 * 44];    // one cin tile
    __shared__ float sW[125 * 32];        // one cin weights, tap-major

    const int tid = threadIdx.x;
    const int active = (tid < 196);
    const int pos = tid % 98;
    const int chalf = tid / 98;           // 0 or 1 (tid<196)
    const int l  = pos / 14;              // local oh (0..6)
    const int ow = pos % 14;
    const int oh = hh * 7 + l;

    float acc[16];
    #pragma unroll
    for (int c = 0; c < 16; c++) acc[c] = 0.f;

    const int id0 = 3 * od;
    const int ih0 = 21 * hh;
    const float4* sW4 = (const float4*)sW;

    for (int cin = 0; cin < 16; cin++) {
        __syncthreads();
        // input tile [5][23][44]
        const float* src = g_c1 + ((size_t)(n * 16 + cin)) * 85184;
        for (int idx = tid; idx < 5 * 23 * 44; idx += 256) {
            int ld = idx / (23 * 44);
            int r  = idx % (23 * 44);
            int lh = r / 44, lw = r % 44;
            sIn[idx] = src[(size_t)(id0 + ld) * 1936 + (ih0 + lh) * 44 + lw];
        }
        // weights: sW[tap*32 + c] = w2[(c*16+cin)*125 + tap]
        for (int idx = tid; idx < 125 * 32; idx += 256) {
            int tap = idx >> 5, c = idx & 31;
            sW[idx] = w2[(c * 16 + cin) * 125 + tap];
        }
        __syncthreads();
        if (!active) continue;

        #pragma unroll
        for (int kd = 0; kd < 5; kd++) {
            #pragma unroll
            for (int kh = 0; kh < 5; kh++) {
                #pragma unroll
                for (int kw = 0; kw < 5; kw++) {
                    float v = sIn[kd * (23 * 44) + (3 * l + kh) * 44 + (3 * ow + kw)];
                    int tap = (kd * 5 + kh) * 5 + kw;
                    #pragma unroll
                    for (int q = 0; q < 4; q++) {
                        float4 w = sW4[tap * 8 + chalf * 4 + q];
                        acc[q * 4 + 0] = fmaf(v, w.x, acc[q * 4 + 0]);
                        acc[q * 4 + 1] = fmaf(v, w.y, acc[q * 4 + 1]);
                        acc[q * 4 + 2] = fmaf(v, w.z, acc[q * 4 + 2]);
                        acc[q * 4 + 3] = fmaf(v, w.w, acc[q * 4 + 3]);
                    }
                }
            }
        }
    }
    if (!active) return;

    #pragma unroll
    for (int cc = 0; cc < 16; cc++) {
        int c = chalf * 16 + cc;
        size_t o = ((size_t)(n * 32 + c) * 14 + od) * 196 + oh * 14 + ow;
        g_c2[o] = leaky(acc[cc] + b2[c]);
    }
}

// =======================================================================
// conv3: grid(4,64): 12-channel group per bx. thread = pos(64) x tap-slice(4)
// =======================================================================
__global__ __launch_bounds__(256) void conv3_kernel(
    const float* __restrict__ w3, const float* __restrict__ b3)
{
    const int c0 = blockIdx.x * 12;
    const int n  = blockIdx.y;

    __shared__ float sIn[2744];        // 14^3, one cin
    __shared__ float sW[125 * 12];
    __shared__ float sStage[4 * 64 * 12];

    const int tid = threadIdx.x;
    const int pos = tid & 63;
    const int sub = tid >> 6;
    const int od = pos >> 4, oh = (pos >> 2) & 3, ow = pos & 3;

    float acc[12];
    #pragma unroll
    for (int c = 0; c < 12; c++) acc[c] = 0.f;

    const float4* sW4 = (const float4*)sW;

    for (int cin = 0; cin < 32; cin++) {
        __syncthreads();
        const float* src = g_c2 + (size_t)(n * 32 + cin) * 2744;
        for (int idx = tid; idx < 2744; idx += 256) sIn[idx] = src[idx];
        for (int idx = tid; idx < 125 * 12; idx += 256) {
            int tap = idx / 12, cc = idx % 12;
            sW[idx] = w3[((c0 + cc) * 32 + cin) * 125 + tap];
        }
        __syncthreads();

        for (int tap = sub; tap < 125; tap += 4) {
            int kd = tap / 25, r = tap % 25;
            int kh = r / 5, kw = r % 5;
            float v = sIn[(3 * od + kd) * 196 + (3 * oh + kh) * 14 + (3 * ow + kw)];
            #pragma unroll
            for (int q = 0; q < 3; q++) {
                float4 w = sW4[tap * 3 + q];
                acc[q * 4 + 0] = fmaf(v, w.x, acc[q * 4 + 0]);
                acc[q * 4 + 1] = fmaf(v, w.y, acc[q * 4 + 1]);
                acc[q * 4 + 2] = fmaf(v, w.z, acc[q * 4 + 2]);
                acc[q * 4 + 3] = fmaf(v, w.w, acc[q * 4 + 3]);
            }
        }
    }
    __syncthreads();
    #pragma unroll
    for (int c = 0; c < 12; c++)
        sStage[(sub * 64 + pos) * 12 + c] = acc[c];
    __syncthreads();
    if (sub == 0) {
        #pragma unroll
        for (int c = 0; c < 12; c++) {
            float s = sStage[pos * 12 + c] + sStage[(64 + pos) * 12 + c]
                    + sStage[(128 + pos) * 12 + c] + sStage[(192 + pos) * 12 + c];
            g_c3[(size_t)(n * 48 + c0 + c) * 64 + pos] = leaky(s + b3[c0 + c]);
        }
    }
}

// =======================================================================
// conv4 + feature: block per n; 512 outputs; thread does 2
// =======================================================================
__global__ __launch_bounds__(256) void conv4_kernel(
    const float* __restrict__ w4, const float* __restrict__ b4)
{
    const int n = blockIdx.x;
    __shared__ float sIn[48 * 64];
    const int tid = threadIdx.x;

    const float* src = g_c3 + (size_t)n * 3072;
    for (int idx = tid; idx < 3072; idx += 256) sIn[idx] = src[idx];
    __syncthreads();

    for (int o = tid; o < 512; o += 256) {
        int c = o >> 3, p = o & 7;
        int od = p >> 2, oh = (p >> 1) & 1, ow = p & 1;
        float acc = 0.f;
        const float* wb = w4 + c * 48 * 27;
        for (int cin = 0; cin < 48; cin++) {
            const float* s = sIn + cin * 64;
            const float* wk = wb + cin * 27;
            #pragma unroll
            for (int kd = 0; kd < 3; kd++)
                #pragma unroll
                for (int kh = 0; kh < 3; kh++)
                    #pragma unroll
                    for (int kw = 0; kw < 3; kw++)
                        acc = fmaf(s[(od + kd) * 16 + (oh + kh) * 4 + (ow + kw)],
                                   wk[kd * 9 + kh * 3 + kw], acc);
        }
        g_feat[n * 512 + o] = leaky(acc + b4[c]);
    }
}

// =======================================================================
// M = feature @ T : block per row i; thread = 4 cols
// =======================================================================
__global__ __launch_bounds__(256) void mmul_kernel(const float* __restrict__ T)
{
    const int i = blockIdx.x;
    __shared__ float sF[512];
    const int tid = threadIdx.x;
    for (int k = tid; k < 512; k += 256) sF[k] = g_feat[i * 512 + k];
    __syncthreads();

    float acc0 = 0.f, acc1 = 0.f, acc2 = 0.f, acc3 = 0.f;
    for (int k = 0; k < 512; k++) {
        float v = sF[k];
        const float* tr = T + (size_t)k * 1024;
        acc0 = fmaf(v, tr[tid], acc0);
        acc1 = fmaf(v, tr[tid + 256], acc1);
        acc2 = fmaf(v, tr[tid + 512], acc2);
        acc3 = fmaf(v, tr[tid + 768], acc3);
    }
    g_M[i * 1024 + tid] = acc0;
    g_M[i * 1024 + tid + 256] = acc1;
    g_M[i * 1024 + tid + 512] = acc2;
    g_M[i * 1024 + tid + 768] = acc3;
}

// =======================================================================
// out_T[i,c] = sum_j exp( sum_k |M[i,c,k]-M[j,c,k]| )
// =======================================================================
__global__ __launch_bounds__(256) void mbd_kernel()
{
    const int i = blockIdx.x;
    __shared__ float sMi[1024];
    __shared__ float sRed[256];
    const int tid = threadIdx.x;
    const int c = tid & 63;
    const int js = tid >> 6;

    for (int k = tid; k < 1024; k += 256) sMi[k] = g_M[i * 1024 + k];
    __syncthreads();

    const float4* mi4 = (const float4*)(sMi + c * 16);
    float4 a0 = mi4[0], a1 = mi4[1], a2 = mi4[2], a3 = mi4[3];

    float acc = 0.f;
    for (int j = js; j < 64; j += 4) {
        const float4* mj4 = (const float4*)(g_M + j * 1024 + c * 16);
        float4 b0 = mj4[0], b1 = mj4[1], b2 = mj4[2], b3 = mj4[3];
        float d =
            fabsf(a0.x - b0.x) + fabsf(a0.y - b0.y) + fabsf(a0.z - b0.z) + fabsf(a0.w - b0.w) +
            fabsf(a1.x - b1.x) + fabsf(a1.y - b1.y) + fabsf(a1.z - b1.z) + fabsf(a1.w - b1.w) +
            fabsf(a2.x - b2.x) + fabsf(a2.y - b2.y) + fabsf(a2.z - b2.z) + fabsf(a2.w - b2.w) +
            fabsf(a3.x - b3.x) + fabsf(a3.y - b3.y) + fabsf(a3.z - b3.z) + fabsf(a3.w - b3.w);
        acc += expf(d);
    }
    sRed[tid] = acc;
    __syncthreads();
    if (js == 0) {
        float s = sRed[c] + sRed[c + 64] + sRed[c + 128] + sRed[c + 192];
        g_outT[i * 64 + c] = s;
    }
}

// =======================================================================
// final: z = [feature|outT] @ Wm + bm ; sigmoid
// =======================================================================
__global__ __launch_bounds__(64) void final_kernel(
    const float* __restrict__ Wm, const float* __restrict__ bm,
    float* __restrict__ out)
{
    const int i = threadIdx.x;
    float z = bm[0];
    const float* f = g_feat + i * 512;
    #pragma unroll 8
    for (int k = 0; k < 512; k++) z = fmaf(f[k], Wm[k], z);
    const float* t = g_outT + i * 64;
    #pragma unroll 8
    for (int c = 0; c < 64; c++) z = fmaf(t[c], Wm[512 + c], z);
    out[i] = 1.f / (1.f + expf(-z));
}

// =======================================================================
extern "C" void kernel_launch(void* const* d_in, const int* in_sizes, int n_in,
                              void* d_out, int out_size)
{
    const float* x  = (const float*)d_in[0];
    const float* w1 = (const float*)d_in[1];
    const float* b1 = (const float*)d_in[2];
    const float* w2 = (const float*)d_in[3];
    const float* b2 = (const float*)d_in[4];
    const float* w3 = (const float*)d_in[5];
    const float* b3 = (const float*)d_in[6];
    const float* w4 = (const float*)d_in[7];
    const float* b4 = (const float*)d_in[8];
    const float* T  = (const float*)d_in[9];
    const float* Wm = (const float*)d_in[10];
    const float* bm = (const float*)d_in[11];
    float* out = (float*)d_out;

    conv1_kernel<<<dim3(33, 11, 64), 256>>>(x, w1, b1);
    conv2_kernel<<<dim3(28, 64), 256>>>(w2, b2);
    conv3_kernel<<<dim3(4, 64), 256>>>(w3, b3);
    conv4_kernel<<<64, 256>>>(w4, b4);
    mmul_kernel<<<64, 256>>>(T);
    mbd_kernel<<<64, 256>>>();
    final_kernel<<<1, 64>>>(Wm, bm, out);
}

// round 3
// speedup vs baseline: 1.1262x; 1.1262x over previous
#include <cuda_runtime.h>
#include <math.h>

// ---------------- problem constants ----------------
#define SLOPE 0.01f

// conv1: in [64,1,92,92,92] w[16,1,6,6,6] s2 -> [64,16,44,44,44]
// conv2: in [64,16,44,44,44] w[32,16,5,5,5] s3 -> [64,32,14,14,14]
// conv3: in [64,32,14,14,14] w[48,32,5,5,5] s3 -> [64,48,4,4,4]
// conv4: in [64,48,4,4,4]  w[64,48,3,3,3] s1 -> [64,64,2,2,2]

// ---------------- scratch (static device globals; no cudaMalloc) ----------
__device__ __align__(128) float g_c1[64ull * 16 * 44 * 44 * 44];   // 349 MB
__device__ __align__(128) float g_c2[64 * 32 * 14 * 14 * 14];      // 22.5 MB
__device__ __align__(128) float g_c3[64 * 48 * 64];
__device__ __align__(128) float g_feat[64 * 512];
__device__ __align__(128) float g_M[64 * 1024];
__device__ __align__(128) float g_outT[64 * 64];
__device__ __align__(128) float g_w2t[16 * 4000];   // [cin][tap*32+c]

__device__ __forceinline__ float leaky(float v) {
    return v >= 0.f ? v : SLOPE * v;
}

__device__ __forceinline__ void cp16(void* dst, const void* src) {
    unsigned d = (unsigned)__cvta_generic_to_shared(dst);
    asm volatile("cp.async.cg.shared.global [%0], [%1], 16;" :: "r"(d), "l"(src));
}
#define CP_COMMIT() asm volatile("cp.async.commit_group;")
#define CP_WAIT1()  asm volatile("cp.async.wait_group 1;")
#define CP_WAIT0()  asm volatile("cp.async.wait_group 0;")

// =======================================================================
// conv1: tile Td=4,Th=4,Tw=16 per block; 256 thr; thread = 1 voxel x 16ch
// =======================================================================
__global__ __launch_bounds__(256) void conv1_kernel(
    const float* __restrict__ x, const float* __restrict__ w1,
    const float* __restrict__ b1)
{
    const int wt = blockIdx.x % 3;
    const int ht = blockIdx.x / 3;
    const int dt = blockIdx.y;
    const int n  = blockIdx.z;

    __shared__ float sIn[12 * 12 * 36];
    __shared__ float sW[216 * 16];

    const int tid = threadIdx.x;

    for (int idx = tid; idx < 16 * 216; idx += 256) {
        int c = idx / 216, tap = idx % 216;
        sW[tap * 16 + c] = w1[idx];
    }

    const int id0 = dt * 8, ih0 = ht * 8, iw0 = wt * 32;
    const float* xb = x + (size_t)n * 778688;
    for (int idx = tid; idx < 12 * 12 * 36; idx += 256) {
        int ld = idx / 432;
        int r  = idx % 432;
        int lh = r / 36, lw = r % 36;
        int gw = iw0 + lw;
        float v = 0.f;
        if (gw < 92)
            v = xb[(id0 + ld) * 8464 + (ih0 + lh) * 92 + gw];
        sIn[idx] = v;
    }
    __syncthreads();

    const int tw = tid & 15;
    const int th = (tid >> 4) & 3;
    const int td = tid >> 6;
    const int ow = wt * 16 + tw;
    if (ow >= 44) return;
    const int oh = ht * 4 + th;
    const int od = dt * 4 + td;

    float acc[16];
    #pragma unroll
    for (int c = 0; c < 16; c++) acc[c] = b1[c];

    const float4* sW4 = (const float4*)sW;
    #pragma unroll
    for (int kd = 0; kd < 6; kd++) {
        #pragma unroll
        for (int kh = 0; kh < 6; kh++) {
            #pragma unroll
            for (int kw = 0; kw < 6; kw++) {
                float v = sIn[(2 * td + kd) * 432 + (2 * th + kh) * 36 + (2 * tw + kw)];
                int tap = (kd * 6 + kh) * 6 + kw;
                #pragma unroll
                for (int q = 0; q < 4; q++) {
                    float4 w = sW4[tap * 4 + q];
                    acc[q * 4 + 0] = fmaf(v, w.x, acc[q * 4 + 0]);
                    acc[q * 4 + 1] = fmaf(v, w.y, acc[q * 4 + 1]);
                    acc[q * 4 + 2] = fmaf(v, w.z, acc[q * 4 + 2]);
                    acc[q * 4 + 3] = fmaf(v, w.w, acc[q * 4 + 3]);
                }
            }
        }
    }

    size_t obase = ((size_t)n * 16) * 85184 + (size_t)od * 1936 + oh * 44 + ow;
    #pragma unroll
    for (int c = 0; c < 16; c++)
        g_c1[obase + (size_t)c * 85184] = leaky(acc[c]);
}

// =======================================================================
// prep_w2: transpose conv2 weights to [cin][tap*32 + c] for bulk cp.async
// =======================================================================
__global__ __launch_bounds__(256) void prep_w2_kernel(const float* __restrict__ w2)
{
    int idx = blockIdx.x * 256 + threadIdx.x;
    if (idx >= 16 * 4000) return;
    int cin = idx / 4000;
    int r   = idx % 4000;
    int tap = r >> 5, c = r & 31;
    g_w2t[idx] = w2[(c * 16 + cin) * 125 + tap];
}

// =======================================================================
// conv2: block = (n, od, h-half); double-buffered cp.async pipeline over cin
// dynamic smem: sIn[2][5060] + sW[2][4000] = 72480 B
// =======================================================================
__global__ __launch_bounds__(256) void conv2_kernel(const float* __restrict__ b2)
{
    extern __shared__ float smem[];
    // layout: sIn buf0 @0, buf1 @5060, sW buf0 @10120, buf1 @14120

    const int od = blockIdx.x >> 1;
    const int hh = blockIdx.x & 1;
    const int n  = blockIdx.y;

    const int tid = threadIdx.x;
    const int active = (tid < 196);
    const int pos = tid % 98;
    const int chalf = tid / 98;
    const int l  = pos / 14;
    const int ow = pos % 14;
    const int oh = hh * 7 + l;

    const int id0 = 3 * od;
    const int ih0 = 21 * hh;

    auto issue = [&](int cin) {
        int buf = cin & 1;
        float* dI = smem + buf * 5060;
        float* dW = smem + 10120 + buf * 4000;
        const float* srcI = g_c1 + (size_t)(n * 16 + cin) * 85184;
        // input tile [5][23][44]: 115 rows of 11 float4
        for (int f = tid; f < 1265; f += 256) {
            int row = f / 11, q = f % 11;
            int ld = row / 23, lh = row % 23;
            cp16(dI + row * 44 + q * 4,
                 srcI + (size_t)(id0 + ld) * 1936 + (ih0 + lh) * 44 + q * 4);
        }
        const float* srcW = g_w2t + cin * 4000;
        for (int f = tid; f < 1000; f += 256)
            cp16(dW + f * 4, srcW + f * 4);
    };

    float acc[16];
    #pragma unroll
    for (int c = 0; c < 16; c++) acc[c] = 0.f;

    issue(0);
    CP_COMMIT();

    for (int cin = 0; cin < 16; cin++) {
        if (cin < 15) {
            issue(cin + 1);
            CP_COMMIT();
            CP_WAIT1();
        } else {
            CP_WAIT0();
        }
        __syncthreads();

        if (active) {
            const int buf = cin & 1;
            const float* sIn = smem + buf * 5060;
            const float4* sW4 = (const float4*)(smem + 10120 + buf * 4000);
            #pragma unroll
            for (int kd = 0; kd < 5; kd++) {
                #pragma unroll
                for (int kh = 0; kh < 5; kh++) {
                    #pragma unroll
                    for (int kw = 0; kw < 5; kw++) {
                        float v = sIn[kd * 1012 + (3 * l + kh) * 44 + (3 * ow + kw)];
                        int tap = (kd * 5 + kh) * 5 + kw;
                        #pragma unroll
                        for (int q = 0; q < 4; q++) {
                            float4 w = sW4[tap * 8 + chalf * 4 + q];
                            acc[q * 4 + 0] = fmaf(v, w.x, acc[q * 4 + 0]);
                            acc[q * 4 + 1] = fmaf(v, w.y, acc[q * 4 + 1]);
                            acc[q * 4 + 2] = fmaf(v, w.z, acc[q * 4 + 2]);
                            acc[q * 4 + 3] = fmaf(v, w.w, acc[q * 4 + 3]);
                        }
                    }
                }
            }
        }
        __syncthreads();
    }
    if (!active) return;

    #pragma unroll
    for (int cc = 0; cc < 16; cc++) {
        int c = chalf * 16 + cc;
        size_t o = ((size_t)(n * 32 + c) * 14 + od) * 196 + oh * 14 + ow;
        g_c2[o] = leaky(acc[cc] + b2[c]);
    }
}

// =======================================================================
// conv3: grid(4,64): 12-channel group per bx. thread = pos(64) x tap-slice(4)
// =======================================================================
__global__ __launch_bounds__(256) void conv3_kernel(
    const float* __restrict__ w3, const float* __restrict__ b3)
{
    const int c0 = blockIdx.x * 12;
    const int n  = blockIdx.y;

    __shared__ float sIn[2744];
    __shared__ float sW[125 * 12];
    __shared__ float sStage[4 * 64 * 12];

    const int tid = threadIdx.x;
    const int pos = tid & 63;
    const int sub = tid >> 6;
    const int od = pos >> 4, oh = (pos >> 2) & 3, ow = pos & 3;

    float acc[12];
    #pragma unroll
    for (int c = 0; c < 12; c++) acc[c] = 0.f;

    const float4* sW4 = (const float4*)sW;

    for (int cin = 0; cin < 32; cin++) {
        __syncthreads();
        const float* src = g_c2 + (size_t)(n * 32 + cin) * 2744;
        for (int idx = tid; idx < 2744; idx += 256) sIn[idx] = src[idx];
        for (int idx = tid; idx < 125 * 12; idx += 256) {
            int tap = idx / 12, cc = idx % 12;
            sW[idx] = w3[((c0 + cc) * 32 + cin) * 125 + tap];
        }
        __syncthreads();

        for (int tap = sub; tap < 125; tap += 4) {
            int kd = tap / 25, r = tap % 25;
            int kh = r / 5, kw = r % 5;
            float v = sIn[(3 * od + kd) * 196 + (3 * oh + kh) * 14 + (3 * ow + kw)];
            #pragma unroll
            for (int q = 0; q < 3; q++) {
                float4 w = sW4[tap * 3 + q];
                acc[q * 4 + 0] = fmaf(v, w.x, acc[q * 4 + 0]);
                acc[q * 4 + 1] = fmaf(v, w.y, acc[q * 4 + 1]);
                acc[q * 4 + 2] = fmaf(v, w.z, acc[q * 4 + 2]);
                acc[q * 4 + 3] = fmaf(v, w.w, acc[q * 4 + 3]);
            }
        }
    }
    __syncthreads();
    #pragma unroll
    for (int c = 0; c < 12; c++)
        sStage[(sub * 64 + pos) * 12 + c] = acc[c];
    __syncthreads();
    if (sub == 0) {
        #pragma unroll
        for (int c = 0; c < 12; c++) {
            float s = sStage[pos * 12 + c] + sStage[(64 + pos) * 12 + c]
                    + sStage[(128 + pos) * 12 + c] + sStage[(192 + pos) * 12 + c];
            g_c3[(size_t)(n * 48 + c0 + c) * 64 + pos] = leaky(s + b3[c0 + c]);
        }
    }
}

// =======================================================================
// conv4 + feature: grid(64, 8); block = n x 8 cout; 4-way cin split per out
// =======================================================================
__global__ __launch_bounds__(256) void conv4_kernel(
    const float* __restrict__ w4, const float* __restrict__ b4)
{
    const int n  = blockIdx.x;
    const int c0 = blockIdx.y * 8;

    __shared__ float sIn[48 * 64];
    __shared__ float sRed[256];

    const int tid = threadIdx.x;
    const float* src = g_c3 + (size_t)n * 3072;
    for (int idx = tid; idx < 3072; idx += 256) sIn[idx] = src[idx];
    __syncthreads();

    const int sub = tid >> 6;          // cin quarter (0..3)
    const int loc = tid & 63;
    const int c   = loc >> 3;          // local cout (0..7)
    const int p   = loc & 7;
    const int od = p >> 2, oh = (p >> 1) & 1, ow = p & 1;

    float acc = 0.f;
    const float* wb = w4 + (size_t)(c0 + c) * 48 * 27;
    #pragma unroll
    for (int ci = 0; ci < 12; ci++) {
        int cin = sub * 12 + ci;
        const float* s  = sIn + cin * 64;
        const float* wk = wb + cin * 27;
        #pragma unroll
        for (int kd = 0; kd < 3; kd++)
            #pragma unroll
            for (int kh = 0; kh < 3; kh++)
                #pragma unroll
                for (int kw = 0; kw < 3; kw++)
                    acc = fmaf(s[(od + kd) * 16 + (oh + kh) * 4 + (ow + kw)],
                               __ldg(wk + kd * 9 + kh * 3 + kw), acc);
    }
    sRed[tid] = acc;
    __syncthreads();
    if (sub == 0) {
        float v = sRed[loc] + sRed[loc + 64] + sRed[loc + 128] + sRed[loc + 192];
        g_feat[n * 512 + (c0 + c) * 8 + p] = leaky(v + b4[c0 + c]);
    }
}

// =======================================================================
// M = feature @ T : block per row i; thread = 4 cols
// =======================================================================
__global__ __launch_bounds__(256) void mmul_kernel(const float* __restrict__ T)
{
    const int i = blockIdx.x;
    __shared__ float sF[512];
    const int tid = threadIdx.x;
    for (int k = tid; k < 512; k += 256) sF[k] = g_feat[i * 512 + k];
    __syncthreads();

    float acc0 = 0.f, acc1 = 0.f, acc2 = 0.f, acc3 = 0.f;
    for (int k = 0; k < 512; k++) {
        float v = sF[k];
        const float* tr = T + (size_t)k * 1024;
        acc0 = fmaf(v, tr[tid], acc0);
        acc1 = fmaf(v, tr[tid + 256], acc1);
        acc2 = fmaf(v, tr[tid + 512], acc2);
        acc3 = fmaf(v, tr[tid + 768], acc3);
    }
    g_M[i * 1024 + tid] = acc0;
    g_M[i * 1024 + tid + 256] = acc1;
    g_M[i * 1024 + tid + 512] = acc2;
    g_M[i * 1024 + tid + 768] = acc3;
}

// =======================================================================
// out_T[i,c] = sum_j exp( sum_k |M[i,c,k]-M[j,c,k]| )
// =======================================================================
__global__ __launch_bounds__(256) void mbd_kernel()
{
    const int i = blockIdx.x;
    __shared__ float sMi[1024];
    __shared__ float sRed[256];
    const int tid = threadIdx.x;
    const int c = tid & 63;
    const int js = tid >> 6;

    for (int k = tid; k < 1024; k += 256) sMi[k] = g_M[i * 1024 + k];
    __syncthreads();

    const float4* mi4 = (const float4*)(sMi + c * 16);
    float4 a0 = mi4[0], a1 = mi4[1], a2 = mi4[2], a3 = mi4[3];

    float acc = 0.f;
    for (int j = js; j < 64; j += 4) {
        const float4* mj4 = (const float4*)(g_M + j * 1024 + c * 16);
        float4 b0 = mj4[0], b1 = mj4[1], b2 = mj4[2], b3 = mj4[3];
        float d =
            fabsf(a0.x - b0.x) + fabsf(a0.y - b0.y) + fabsf(a0.z - b0.z) + fabsf(a0.w - b0.w) +
            fabsf(a1.x - b1.x) + fabsf(a1.y - b1.y) + fabsf(a1.z - b1.z) + fabsf(a1.w - b1.w) +
            fabsf(a2.x - b2.x) + fabsf(a2.y - b2.y) + fabsf(a2.z - b2.z) + fabsf(a2.w - b2.w) +
            fabsf(a3.x - b3.x) + fabsf(a3.y - b3.y) + fabsf(a3.z - b3.z) + fabsf(a3.w - b3.w);
        acc += expf(d);
    }
    sRed[tid] = acc;
    __syncthreads();
    if (js == 0) {
        float s = sRed[c] + sRed[c + 64] + sRed[c + 128] + sRed[c + 192];
        g_outT[i * 64 + c] = s;
    }
}

// =======================================================================
// final: z = [feature|outT] @ Wm + bm ; sigmoid
// =======================================================================
__global__ __launch_bounds__(64) void final_kernel(
    const float* __restrict__ Wm, const float* __restrict__ bm,
    float* __restrict__ out)
{
    const int i = threadIdx.x;
    float z = bm[0];
    const float* f = g_feat + i * 512;
    #pragma unroll 8
    for (int k = 0; k < 512; k++) z = fmaf(f[k], Wm[k], z);
    const float* t = g_outT + i * 64;
    #pragma unroll 8
    for (int c = 0; c < 64; c++) z = fmaf(t[c], Wm[512 + c], z);
    out[i] = 1.f / (1.f + expf(-z));
}

// =======================================================================
extern "C" void kernel_launch(void* const* d_in, const int* in_sizes, int n_in,
                              void* d_out, int out_size)
{
    const float* x  = (const float*)d_in[0];
    const float* w1 = (const float*)d_in[1];
    const float* b1 = (const float*)d_in[2];
    const float* w2 = (const float*)d_in[3];
    const float* b2 = (const float*)d_in[4];
    const float* w3 = (const float*)d_in[5];
    const float* b3 = (const float*)d_in[6];
    const float* w4 = (const float*)d_in[7];
    const float* b4 = (const float*)d_in[8];
    const float* T  = (const float*)d_in[9];
    const float* Wm = (const float*)d_in[10];
    const float* bm = (const float*)d_in[11];
    float* out = (float*)d_out;

    const int conv2_smem = (2 * 5060 + 2 * 4000) * (int)sizeof(float);  // 72480
    cudaFuncSetAttribute(conv2_kernel,
                         cudaFuncAttributeMaxDynamicSharedMemorySize, conv2_smem);

    prep_w2_kernel<<<250, 256>>>(w2);
    conv1_kernel<<<dim3(33, 11, 64), 256>>>(x, w1, b1);
    conv2_kernel<<<dim3(28, 64), 256, conv2_smem>>>(b2);
    conv3_kernel<<<dim3(4, 64), 256>>>(w3, b3);
    conv4_kernel<<<dim3(64, 8), 256>>>(w4, b4);
    mmul_kernel<<<64, 256>>>(T);
    mbd_kernel<<<64, 256>>>();
    final_kernel<<<1, 64>>>(Wm, bm, out);
}

// round 7
// speedup vs baseline: 1.3290x; 1.1800x over previous
#include <cuda_runtime.h>
#include <math.h>

// ---------------- problem constants ----------------
#define SLOPE 0.01f

// conv1: in [64,1,92,92,92] w[16,1,6,6,6] s2 -> [64,16,44,44,44]
// conv2: in [64,16,44,44,44] w[32,16,5,5,5] s3 -> [64,32,14,14,14]
// conv3: in [64,32,14,14,14] w[48,32,5,5,5] s3 -> [64,48,4,4,4]
// conv4: in [64,48,4,4,4]  w[64,48,3,3,3] s1 -> [64,64,2,2,2]

// ---------------- scratch (static device globals; no cudaMalloc) ----------
__device__ __align__(128) float g_c1[64ull * 16 * 44 * 44 * 44];   // 349 MB
__device__ __align__(128) float g_c2[64 * 32 * 14 * 14 * 14];      // 22.5 MB
__device__ __align__(128) float g_c3[64 * 48 * 64];
__device__ __align__(128) float g_feat[64 * 512];
__device__ __align__(128) float g_M[64 * 1024];
__device__ __align__(128) float g_outT[64 * 64];
__device__ __align__(128) float g_w2t[16 * 4000];        // [cin][tap*32+c]
__device__ __align__(128) float g_w3t[4 * 32 * 1500];    // [(g*32+cin)][tap*12+cc]

__device__ __forceinline__ float leaky(float v) {
    return v >= 0.f ? v : SLOPE * v;
}

__device__ __forceinline__ void cp16(void* dst, const void* src) {
    unsigned d = (unsigned)__cvta_generic_to_shared(dst);
    asm volatile("cp.async.cg.shared.global [%0], [%1], 16;" :: "r"(d), "l"(src));
}
#define CP_COMMIT() asm volatile("cp.async.commit_group;")
#define CP_WAIT1()  asm volatile("cp.async.wait_group 1;")
#define CP_WAIT0()  asm volatile("cp.async.wait_group 0;")

// =======================================================================
// conv1: tile 4d x 4h x 44w (full row). 192 thr (176 active).
// thread = 4 consecutive w voxels x 16 channels (64 accumulators).
// dynamic smem: sIn 12*12*92 + sW 216*16 = 16704 floats = 66816 B
// =======================================================================
__global__ __launch_bounds__(192) void conv1_kernel(
    const float* __restrict__ x, const float* __restrict__ w1,
    const float* __restrict__ b1)
{
    extern __shared__ float smem[];
    float* sIn = smem;            // 13248
    float* sW  = smem + 13248;    // 3456

    const int ht = blockIdx.x;
    const int dt = blockIdx.y;
    const int n  = blockIdx.z;
    const int tid = threadIdx.x;

    // weights: sW[tap*16 + c]
    for (int idx = tid; idx < 3456; idx += 192) {
        int c = idx / 216, tap = idx % 216;
        sW[tap * 16 + c] = w1[idx];
    }
    // input tile [12][12][92] via float4 (all offsets 16B aligned)
    const float* xb = x + (size_t)n * 778688 + (size_t)(dt * 8) * 8464 + (ht * 8) * 92;
    float4* sIn4 = (float4*)sIn;
    for (int f = tid; f < 3312; f += 192) {
        int row = f / 23, q = f % 23;
        int ld = row / 12, lh = row % 12;
        sIn4[f] = ((const float4*)(xb + (size_t)ld * 8464 + lh * 92))[q];
    }
    __syncthreads();
    if (tid >= 176) return;

    const int tw4 = tid % 11;          // w group: ow = 4*tw4 + i
    const int th  = (tid / 11) & 3;
    const int td  = tid / 44;

    float acc[64];
    {
        float bb[16];
        #pragma unroll
        for (int c = 0; c < 16; c++) bb[c] = b1[c];
        #pragma unroll
        for (int i = 0; i < 4; i++)
            #pragma unroll
            for (int c = 0; c < 16; c++) acc[i * 16 + c] = bb[c];
    }

    const float4* sW4 = (const float4*)sW;

    #pragma unroll 1
    for (int kd = 0; kd < 6; kd++) {
        #pragma unroll 1
        for (int kh = 0; kh < 6; kh++) {
            const float* sr = sIn + (2 * td + kd) * 1104 + (2 * th + kh) * 92 + 8 * tw4;
            // 12 input values cover all 6 kw taps for 4 stride-2 voxels
            float r[12];
            float4 t0 = *(const float4*)(sr);
            float4 t1 = *(const float4*)(sr + 4);
            float4 t2 = *(const float4*)(sr + 8);
            r[0]=t0.x; r[1]=t0.y; r[2]=t0.z; r[3]=t0.w;
            r[4]=t1.x; r[5]=t1.y; r[6]=t1.z; r[7]=t1.w;
            r[8]=t2.x; r[9]=t2.y; r[10]=t2.z; r[11]=t2.w;
            #pragma unroll
            for (int kw = 0; kw < 6; kw++) {
                const int tap = (kd * 6 + kh) * 6 + kw;
                float v[4];
                #pragma unroll
                for (int i = 0; i < 4; i++) v[i] = r[kw + 2 * i];
                #pragma unroll
                for (int q = 0; q < 4; q++) {
                    float4 w = sW4[tap * 4 + q];
                    #pragma unroll
                    for (int i = 0; i < 4; i++) {
                        acc[i * 16 + q * 4 + 0] = fmaf(v[i], w.x, acc[i * 16 + q * 4 + 0]);
                        acc[i * 16 + q * 4 + 1] = fmaf(v[i], w.y, acc[i * 16 + q * 4 + 1]);
                        acc[i * 16 + q * 4 + 2] = fmaf(v[i], w.z, acc[i * 16 + q * 4 + 2]);
                        acc[i * 16 + q * 4 + 3] = fmaf(v[i], w.w, acc[i * 16 + q * 4 + 3]);
                    }
                }
            }
        }
    }

    // store: 4 consecutive w per channel as float4
    size_t obase = (size_t)(n * 16) * 85184 + (size_t)(dt * 4 + td) * 1936
                 + (ht * 4 + th) * 44 + tw4 * 4;
    #pragma unroll
    for (int c = 0; c < 16; c++) {
        float4 rr = make_float4(leaky(acc[c]), leaky(acc[16 + c]),
                                leaky(acc[32 + c]), leaky(acc[48 + c]));
        *(float4*)(g_c1 + obase + (size_t)c * 85184) = rr;
    }
}

// =======================================================================
// prep_w2: transpose conv2 weights to [cin][tap*32 + c]
// =======================================================================
__global__ __launch_bounds__(256) void prep_w2_kernel(const float* __restrict__ w2)
{
    int idx = blockIdx.x * 256 + threadIdx.x;
    if (idx >= 16 * 4000) return;
    int cin = idx / 4000;
    int r   = idx % 4000;
    int tap = r >> 5, c = r & 31;
    g_w2t[idx] = w2[(c * 16 + cin) * 125 + tap];
}

// =======================================================================
// prep_w3: g_w3t[(g*32+cin)*1500 + tap*12 + cc] = w3[((g*12+cc)*32+cin)*125+tap]
// =======================================================================
__global__ __launch_bounds__(256) void prep_w3_kernel(const float* __restrict__ w3)
{
    int idx = blockIdx.x * 256 + threadIdx.x;
    if (idx >= 192000) return;
    int gcin = idx / 1500;
    int r    = idx % 1500;
    int tap = r / 12, cc = r % 12;
    int g = gcin / 32, cin = gcin % 32;
    g_w3t[idx] = w3[((g * 12 + cc) * 32 + cin) * 125 + tap];
}

// =======================================================================
// conv2: block = (n, od, h-half); double-buffered cp.async pipeline over cin
// dynamic smem: sIn[2][5060] + sW[2][4000] = 72480 B
// =======================================================================
__global__ __launch_bounds__(256) void conv2_kernel(const float* __restrict__ b2)
{
    extern __shared__ float smem[];

    const int od = blockIdx.x >> 1;
    const int hh = blockIdx.x & 1;
    const int n  = blockIdx.y;

    const int tid = threadIdx.x;
    const int active = (tid < 196);
    const int pos = tid % 98;
    const int chalf = tid / 98;
    const int l  = pos / 14;
    const int ow = pos % 14;
    const int oh = hh * 7 + l;

    const int id0 = 3 * od;
    const int ih0 = 21 * hh;

    auto issue = [&](int cin) {
        int buf = cin & 1;
        float* dI = smem + buf * 5060;
        float* dW = smem + 10120 + buf * 4000;
        const float* srcI = g_c1 + (size_t)(n * 16 + cin) * 85184;
        for (int f = tid; f < 1265; f += 256) {
            int row = f / 11, q = f % 11;
            int ld = row / 23, lh = row % 23;
            cp16(dI + row * 44 + q * 4,
                 srcI + (size_t)(id0 + ld) * 1936 + (ih0 + lh) * 44 + q * 4);
        }
        const float* srcW = g_w2t + cin * 4000;
        for (int f = tid; f < 1000; f += 256)
            cp16(dW + f * 4, srcW + f * 4);
    };

    float acc[16];
    #pragma unroll
    for (int c = 0; c < 16; c++) acc[c] = 0.f;

    issue(0);
    CP_COMMIT();

    for (int cin = 0; cin < 16; cin++) {
        if (cin < 15) {
            issue(cin + 1);
            CP_COMMIT();
            CP_WAIT1();
        } else {
            CP_WAIT0();
        }
        __syncthreads();

        if (active) {
            const int buf = cin & 1;
            const float* sIn = smem + buf * 5060;
            const float4* sW4 = (const float4*)(smem + 10120 + buf * 4000);
            #pragma unroll
            for (int kd = 0; kd < 5; kd++) {
                #pragma unroll
                for (int kh = 0; kh < 5; kh++) {
                    #pragma unroll
                    for (int kw = 0; kw < 5; kw++) {
                        float v = sIn[kd * 1012 + (3 * l + kh) * 44 + (3 * ow + kw)];
                        int tap = (kd * 5 + kh) * 5 + kw;
                        #pragma unroll
                        for (int q = 0; q < 4; q++) {
                            float4 w = sW4[tap * 8 + chalf * 4 + q];
                            acc[q * 4 + 0] = fmaf(v, w.x, acc[q * 4 + 0]);
                            acc[q * 4 + 1] = fmaf(v, w.y, acc[q * 4 + 1]);
                            acc[q * 4 + 2] = fmaf(v, w.z, acc[q * 4 + 2]);
                            acc[q * 4 + 3] = fmaf(v, w.w, acc[q * 4 + 3]);
                        }
                    }
                }
            }
        }
        __syncthreads();
    }
    if (!active) return;

    #pragma unroll
    for (int cc = 0; cc < 16; cc++) {
        int c = chalf * 16 + cc;
        size_t o = ((size_t)(n * 32 + c) * 14 + od) * 196 + oh * 14 + ow;
        g_c2[o] = leaky(acc[cc] + b2[c]);
    }
}

// =======================================================================
// conv3: grid(4 cout-groups, 64 n); block 256 = pos(64) x cin-quarter(4).
// taps fully unrolled (compile-time offsets, no div/mod in hot loop).
// dynamic smem: sIn 4*2744 + sW 4*1500 = 16976 floats = 67904 B
// (sStage aliases sIn after final compute)
// =======================================================================
__global__ __launch_bounds__(256) void conv3_kernel(const float* __restrict__ b3)
{
    extern __shared__ float smem[];

    const int g = blockIdx.x;
    const int n = blockIdx.y;
    const int tid = threadIdx.x;
    const int pos = tid & 63;
    const int sub = tid >> 6;
    const int od = pos >> 4, oh = (pos >> 2) & 3, ow = pos & 3;

    float* myIn = smem + sub * 2744;
    const float4* sW4 = (const float4*)(smem + 10976 + sub * 1500);

    float acc[12];
    #pragma unroll
    for (int c = 0; c < 12; c++) acc[c] = 0.f;

    for (int ci = 0; ci < 8; ci++) {
        const int cin = sub * 8 + ci;
        // stage this sub's cin tile + weights (16B cp.async)
        {
            const float* sI = g_c2 + (size_t)(n * 32 + cin) * 2744;
            for (int f = pos; f < 686; f += 64) cp16(myIn + f * 4, sI + f * 4);
            float* dW = smem + 10976 + sub * 1500;
            const float* sWsrc = g_w3t + (size_t)(g * 32 + cin) * 1500;
            for (int f = pos; f < 375; f += 64) cp16(dW + f * 4, sWsrc + f * 4);
        }
        CP_COMMIT();
        CP_WAIT0();
        __syncthreads();

        #pragma unroll 1
        for (int kd = 0; kd < 5; kd++) {
            const float* sr = myIn + (3 * od + kd) * 196 + 3 * oh * 14 + 3 * ow;
            #pragma unroll
            for (int kh = 0; kh < 5; kh++) {
                #pragma unroll
                for (int kw = 0; kw < 5; kw++) {
                    float v = sr[kh * 14 + kw];   // FIX: kh stride is 14, not 42
                    const int tap = (kd * 5 + kh) * 5 + kw;
                    #pragma unroll
                    for (int q = 0; q < 3; q++) {
                        float4 w = sW4[tap * 3 + q];
                        acc[q * 4 + 0] = fmaf(v, w.x, acc[q * 4 + 0]);
                        acc[q * 4 + 1] = fmaf(v, w.y, acc[q * 4 + 1]);
                        acc[q * 4 + 2] = fmaf(v, w.z, acc[q * 4 + 2]);
                        acc[q * 4 + 3] = fmaf(v, w.w, acc[q * 4 + 3]);
                    }
                }
            }
        }
        __syncthreads();
    }

    // reduce across cin-quarters (sStage aliases smem start)
    float* sStage = smem;
    #pragma unroll
    for (int c = 0; c < 12; c++) sStage[tid * 12 + c] = acc[c];
    __syncthreads();
    if (sub == 0) {
        #pragma unroll
        for (int c = 0; c < 12; c++) {
            float s = sStage[pos * 12 + c] + sStage[(64 + pos) * 12 + c]
                    + sStage[(128 + pos) * 12 + c] + sStage[(192 + pos) * 12 + c];
            g_c3[(size_t)(n * 48 + g * 12 + c) * 64 + pos] = leaky(s + b3[g * 12 + c]);
        }
    }
}

// =======================================================================
// conv4 + feature: grid(64, 8); block = n x 8 cout; 4-way cin split per out
// =======================================================================
__global__ __launch_bounds__(256) void conv4_kernel(
    const float* __restrict__ w4, const float* __restrict__ b4)
{
    const int n  = blockIdx.x;
    const int c0 = blockIdx.y * 8;

    __shared__ float sIn[48 * 64];
    __shared__ float sRed[256];

    const int tid = threadIdx.x;
    const float* src = g_c3 + (size_t)n * 3072;
    for (int idx = tid; idx < 3072; idx += 256) sIn[idx] = src[idx];
    __syncthreads();

    const int sub = tid >> 6;
    const int loc = tid & 63;
    const int c   = loc >> 3;
    const int p   = loc & 7;
    const int od = p >> 2, oh = (p >> 1) & 1, ow = p & 1;

    float acc = 0.f;
    const float* wb = w4 + (size_t)(c0 + c) * 48 * 27;
    #pragma unroll
    for (int ci = 0; ci < 12; ci++) {
        int cin = sub * 12 + ci;
        const float* s  = sIn + cin * 64;
        const float* wk = wb + cin * 27;
        #pragma unroll
        for (int kd = 0; kd < 3; kd++)
            #pragma unroll
            for (int kh = 0; kh < 3; kh++)
                #pragma unroll
                for (int kw = 0; kw < 3; kw++)
                    acc = fmaf(s[(od + kd) * 16 + (oh + kh) * 4 + (ow + kw)],
                               __ldg(wk + kd * 9 + kh * 3 + kw), acc);
    }
    sRed[tid] = acc;
    __syncthreads();
    if (sub == 0) {
        float v = sRed[loc] + sRed[loc + 64] + sRed[loc + 128] + sRed[loc + 192];
        g_feat[n * 512 + (c0 + c) * 8 + p] = leaky(v + b4[c0 + c]);
    }
}

// =======================================================================
// M = feature @ T : block per row i; thread = 4 cols
// =======================================================================
__global__ __launch_bounds__(256) void mmul_kernel(const float* __restrict__ T)
{
    const int i = blockIdx.x;
    __shared__ float sF[512];
    const int tid = threadIdx.x;
    for (int k = tid; k < 512; k += 256) sF[k] = g_feat[i * 512 + k];
    __syncthreads();

    float acc0 = 0.f, acc1 = 0.f, acc2 = 0.f, acc3 = 0.f;
    for (int k = 0; k < 512; k++) {
        float v = sF[k];
        const float* tr = T + (size_t)k * 1024;
        acc0 = fmaf(v, tr[tid], acc0);
        acc1 = fmaf(v, tr[tid + 256], acc1);
        acc2 = fmaf(v, tr[tid + 512], acc2);
        acc3 = fmaf(v, tr[tid + 768], acc3);
    }
    g_M[i * 1024 + tid] = acc0;
    g_M[i * 1024 + tid + 256] = acc1;
    g_M[i * 1024 + tid + 512] = acc2;
    g_M[i * 1024 + tid + 768] = acc3;
}

// =======================================================================
// out_T[i,c] = sum_j exp( sum_k |M[i,c,k]-M[j,c,k]| )
// =======================================================================
__global__ __launch_bounds__(256) void mbd_kernel()
{
    const int i = blockIdx.x;
    __shared__ float sMi[1024];
    __shared__ float sRed[256];
    const int tid = threadIdx.x;
    const int c = tid & 63;
    const int js = tid >> 6;

    for (int k = tid; k < 1024; k += 256) sMi[k] = g_M[i * 1024 + k];
    __syncthreads();

    const float4* mi4 = (const float4*)(sMi + c * 16);
    float4 a0 = mi4[0], a1 = mi4[1], a2 = mi4[2], a3 = mi4[3];

    float acc = 0.f;
    for (int j = js; j < 64; j += 4) {
        const float4* mj4 = (const float4*)(g_M + j * 1024 + c * 16);
        float4 b0 = mj4[0], b1 = mj4[1], b2 = mj4[2], b3 = mj4[3];
        float d =
            fabsf(a0.x - b0.x) + fabsf(a0.y - b0.y) + fabsf(a0.z - b0.z) + fabsf(a0.w - b0.w) +
            fabsf(a1.x - b1.x) + fabsf(a1.y - b1.y) + fabsf(a1.z - b1.z) + fabsf(a1.w - b1.w) +
            fabsf(a2.x - b2.x) + fabsf(a2.y - b2.y) + fabsf(a2.z - b2.z) + fabsf(a2.w - b2.w) +
            fabsf(a3.x - b3.x) + fabsf(a3.y - b3.y) + fabsf(a3.z - b3.z) + fabsf(a3.w - b3.w);
        acc += expf(d);
    }
    sRed[tid] = acc;
    __syncthreads();
    if (js == 0) {
        float s = sRed[c] + sRed[c + 64] + sRed[c + 128] + sRed[c + 192];
        g_outT[i * 64 + c] = s;
    }
}

// =======================================================================
// final: z = [feature|outT] @ Wm + bm ; sigmoid
// =======================================================================
__global__ __launch_bounds__(64) void final_kernel(
    const float* __restrict__ Wm, const float* __restrict__ bm,
    float* __restrict__ out)
{
    const int i = threadIdx.x;
    float z = bm[0];
    const float* f = g_feat + i * 512;
    #pragma unroll 8
    for (int k = 0; k < 512; k++) z = fmaf(f[k], Wm[k], z);
    const float* t = g_outT + i * 64;
    #pragma unroll 8
    for (int c = 0; c < 64; c++) z = fmaf(t[c], Wm[512 + c], z);
    out[i] = 1.f / (1.f + expf(-z));
}

// =======================================================================
extern "C" void kernel_launch(void* const* d_in, const int* in_sizes, int n_in,
                              void* d_out, int out_size)
{
    const float* x  = (const float*)d_in[0];
    const float* w1 = (const float*)d_in[1];
    const float* b1 = (const float*)d_in[2];
    const float* w2 = (const float*)d_in[3];
    const float* b2 = (const float*)d_in[4];
    const float* w3 = (const float*)d_in[5];
    const float* b3 = (const float*)d_in[6];
    const float* w4 = (const float*)d_in[7];
    const float* b4 = (const float*)d_in[8];
    const float* T  = (const float*)d_in[9];
    const float* Wm = (const float*)d_in[10];
    const float* bm = (const float*)d_in[11];
    float* out = (float*)d_out;

    const int conv1_smem = 16704 * (int)sizeof(float);  // 66816
    const int conv2_smem = (2 * 5060 + 2 * 4000) * (int)sizeof(float);  // 72480
    const int conv3_smem = 16976 * (int)sizeof(float);  // 67904
    cudaFuncSetAttribute(conv1_kernel,
                         cudaFuncAttributeMaxDynamicSharedMemorySize, conv1_smem);
    cudaFuncSetAttribute(conv2_kernel,
                         cudaFuncAttributeMaxDynamicSharedMemorySize, conv2_smem);
    cudaFuncSetAttribute(conv3_kernel,
                         cudaFuncAttributeMaxDynamicSharedMemorySize, conv3_smem);

    prep_w2_kernel<<<250, 256>>>(w2);
    prep_w3_kernel<<<750, 256>>>(w3);
    conv1_kernel<<<dim3(11, 11, 64), 192, conv1_smem>>>(x, w1, b1);
    conv2_kernel<<<dim3(28, 64), 256, conv2_smem>>>(b2);
    conv3_kernel<<<dim3(4, 64), 256, conv3_smem>>>(b3);
    conv4_kernel<<<dim3(64, 8), 256>>>(w4, b4);
    mmul_kernel<<<64, 256>>>(T);
    mbd_kernel<<<64, 256>>>();
    final_kernel<<<1, 64>>>(Wm, bm, out);
}

// round 8
// speedup vs baseline: 1.4239x; 1.0714x over previous
#include <cuda_runtime.h>
#include <math.h>

// ---------------- problem constants ----------------
#define SLOPE 0.01f

// conv1: in [64,1,92,92,92] w[16,1,6,6,6] s2 -> [64,16,44,44,44]
// conv2: in [64,16,44,44,44] w[32,16,5,5,5] s3 -> [64,32,14,14,14]
// conv3: in [64,32,14,14,14] w[48,32,5,5,5] s3 -> [64,48,4,4,4]
// conv4: in [64,48,4,4,4]  w[64,48,3,3,3] s1 -> [64,64,2,2,2]

// ---------------- scratch (static device globals; no cudaMalloc) ----------
__device__ __align__(128) float g_c1[64ull * 16 * 44 * 44 * 44];   // 349 MB
__device__ __align__(128) float g_c2[64 * 32 * 14 * 14 * 14];      // 22.5 MB
__device__ __align__(128) float g_c3[64 * 48 * 64];
__device__ __align__(128) float g_feat[64 * 512];
__device__ __align__(128) float g_M[64 * 1024];
__device__ __align__(128) float g_outT[64 * 64];
__device__ __align__(128) float g_w2t[16 * 4000];        // [cin][tap*32+c]
__device__ __align__(128) float g_w3t[4 * 32 * 1500];    // [(g*32+cin)][tap*12+cc]

__device__ __forceinline__ float leaky(float v) {
    return v >= 0.f ? v : SLOPE * v;
}

// ---- packed fp32x2 FMA (sm_103a FFMA2; bit-exact fp32 per component) ----
__device__ __forceinline__ void ffma2(unsigned long long& d,
                                      unsigned long long a,
                                      unsigned long long b) {
    asm("fma.rn.f32x2 %0, %1, %2, %0;" : "+l"(d) : "l"(a), "l"(b));
}
__device__ __forceinline__ unsigned long long f2u(float lo, float hi) {
    unsigned long long v;
    asm("mov.b64 %0, {%1, %2};" : "=l"(v) : "f"(lo), "f"(hi));
    return v;
}
__device__ __forceinline__ float2 u2f(unsigned long long v) {
    float2 f;
    asm("mov.b64 {%0, %1}, %2;" : "=f"(f.x), "=f"(f.y) : "l"(v));
    return f;
}

__device__ __forceinline__ void cp16(void* dst, const void* src) {
    unsigned d = (unsigned)__cvta_generic_to_shared(dst);
    asm volatile("cp.async.cg.shared.global [%0], [%1], 16;" :: "r"(d), "l"(src));
}
#define CP_COMMIT() asm volatile("cp.async.commit_group;")
#define CP_WAIT1()  asm volatile("cp.async.wait_group 1;")
#define CP_WAIT0()  asm volatile("cp.async.wait_group 0;")

// =======================================================================
// conv1: tile 4d x 4h x 44w (full row). 192 thr (176 active).
// thread = 4 consecutive w voxels x 16 channels, packed f32x2 (32 ull acc).
// dynamic smem: sIn 12*12*92 + sW 216*16 = 16704 floats = 66816 B
// =======================================================================
__global__ __launch_bounds__(192) void conv1_kernel(
    const float* __restrict__ x, const float* __restrict__ w1,
    const float* __restrict__ b1)
{
    extern __shared__ float smem[];
    float* sIn = smem;            // 13248
    float* sW  = smem + 13248;    // 3456

    const int ht = blockIdx.x;
    const int dt = blockIdx.y;
    const int n  = blockIdx.z;
    const int tid = threadIdx.x;

    // weights: sW[tap*16 + c]
    for (int idx = tid; idx < 3456; idx += 192) {
        int c = idx / 216, tap = idx % 216;
        sW[tap * 16 + c] = w1[idx];
    }
    // input tile [12][12][92] via float4 (all offsets 16B aligned)
    const float* xb = x + (size_t)n * 778688 + (size_t)(dt * 8) * 8464 + (ht * 8) * 92;
    float4* sIn4 = (float4*)sIn;
    for (int f = tid; f < 3312; f += 192) {
        int row = f / 23, q = f % 23;
        int ld = row / 12, lh = row % 12;
        sIn4[f] = ((const float4*)(xb + (size_t)ld * 8464 + lh * 92))[q];
    }
    __syncthreads();
    if (tid >= 176) return;

    const int tw4 = tid % 11;          // w group: ow = 4*tw4 + i
    const int th  = (tid / 11) & 3;
    const int td  = tid / 44;

    // pacc[i*8+p] = channels (2p, 2p+1) for voxel i
    unsigned long long pacc[32];
    {
        #pragma unroll
        for (int p = 0; p < 8; p++) {
            unsigned long long bp = f2u(b1[2 * p], b1[2 * p + 1]);
            #pragma unroll
            for (int i = 0; i < 4; i++) pacc[i * 8 + p] = bp;
        }
    }

    const ulonglong2* sW2 = (const ulonglong2*)sW;

    #pragma unroll 1
    for (int kd = 0; kd < 6; kd++) {
        #pragma unroll 1
        for (int kh = 0; kh < 6; kh++) {
            const float* sr = sIn + (2 * td + kd) * 1104 + (2 * th + kh) * 92 + 8 * tw4;
            // 12 input values cover all 6 kw taps for 4 stride-2 voxels
            float r[12];
            float4 t0 = *(const float4*)(sr);
            float4 t1 = *(const float4*)(sr + 4);
            float4 t2 = *(const float4*)(sr + 8);
            r[0]=t0.x; r[1]=t0.y; r[2]=t0.z; r[3]=t0.w;
            r[4]=t1.x; r[5]=t1.y; r[6]=t1.z; r[7]=t1.w;
            r[8]=t2.x; r[9]=t2.y; r[10]=t2.z; r[11]=t2.w;
            unsigned long long rr[12];
            #pragma unroll
            for (int j = 0; j < 12; j++) rr[j] = f2u(r[j], r[j]);

            #pragma unroll
            for (int kw = 0; kw < 6; kw++) {
                const int tap = (kd * 6 + kh) * 6 + kw;
                unsigned long long vv[4];
                #pragma unroll
                for (int i = 0; i < 4; i++) vv[i] = rr[kw + 2 * i];
                #pragma unroll
                for (int q = 0; q < 4; q++) {
                    ulonglong2 w = sW2[tap * 4 + q];   // channels 4q..4q+3
                    #pragma unroll
                    for (int i = 0; i < 4; i++) {
                        ffma2(pacc[i * 8 + 2 * q + 0], vv[i], w.x);
                        ffma2(pacc[i * 8 + 2 * q + 1], vv[i], w.y);
                    }
                }
            }
        }
    }

    // store: 4 consecutive w per channel as float4
    size_t obase = (size_t)(n * 16) * 85184 + (size_t)(dt * 4 + td) * 1936
                 + (ht * 4 + th) * 44 + tw4 * 4;
    #pragma unroll
    for (int p = 0; p < 8; p++) {
        float2 f0 = u2f(pacc[p]);
        float2 f1 = u2f(pacc[8 + p]);
        float2 f2 = u2f(pacc[16 + p]);
        float2 f3 = u2f(pacc[24 + p]);
        float4 lo = make_float4(leaky(f0.x), leaky(f1.x), leaky(f2.x), leaky(f3.x));
        float4 hi = make_float4(leaky(f0.y), leaky(f1.y), leaky(f2.y), leaky(f3.y));
        *(float4*)(g_c1 + obase + (size_t)(2 * p) * 85184) = lo;
        *(float4*)(g_c1 + obase + (size_t)(2 * p + 1) * 85184) = hi;
    }
}

// =======================================================================
// prep_w2: transpose conv2 weights to [cin][tap*32 + c]
// =======================================================================
__global__ __launch_bounds__(256) void prep_w2_kernel(const float* __restrict__ w2)
{
    int idx = blockIdx.x * 256 + threadIdx.x;
    if (idx >= 16 * 4000) return;
    int cin = idx / 4000;
    int r   = idx % 4000;
    int tap = r >> 5, c = r & 31;
    g_w2t[idx] = w2[(c * 16 + cin) * 125 + tap];
}

// =======================================================================
// prep_w3: g_w3t[(g*32+cin)*1500 + tap*12 + cc] = w3[((g*12+cc)*32+cin)*125+tap]
// =======================================================================
__global__ __launch_bounds__(256) void prep_w3_kernel(const float* __restrict__ w3)
{
    int idx = blockIdx.x * 256 + threadIdx.x;
    if (idx >= 192000) return;
    int gcin = idx / 1500;
    int r    = idx % 1500;
    int tap = r / 12, cc = r % 12;
    int g = gcin / 32, cin = gcin % 32;
    g_w3t[idx] = w3[((g * 12 + cc) * 32 + cin) * 125 + tap];
}

// =======================================================================
// conv2: block = (n, od, h-half); double-buffered cp.async pipeline over cin
// inner loop packed f32x2 (8 ull acc per thread = 16 channels).
// dynamic smem: sIn[2][5060] + sW[2][4000] = 72480 B
// =======================================================================
__global__ __launch_bounds__(256) void conv2_kernel(const float* __restrict__ b2)
{
    extern __shared__ float smem[];

    const int od = blockIdx.x >> 1;
    const int hh = blockIdx.x & 1;
    const int n  = blockIdx.y;

    const int tid = threadIdx.x;
    const int active = (tid < 196);
    const int pos = tid % 98;
    const int chalf = tid / 98;
    const int l  = pos / 14;
    const int ow = pos % 14;
    const int oh = hh * 7 + l;

    const int id0 = 3 * od;
    const int ih0 = 21 * hh;

    auto issue = [&](int cin) {
        int buf = cin & 1;
        float* dI = smem + buf * 5060;
        float* dW = smem + 10120 + buf * 4000;
        const float* srcI = g_c1 + (size_t)(n * 16 + cin) * 85184;
        for (int f = tid; f < 1265; f += 256) {
            int row = f / 11, q = f % 11;
            int ld = row / 23, lh = row % 23;
            cp16(dI + row * 44 + q * 4,
                 srcI + (size_t)(id0 + ld) * 1936 + (ih0 + lh) * 44 + q * 4);
        }
        const float* srcW = g_w2t + cin * 4000;
        for (int f = tid; f < 1000; f += 256)
            cp16(dW + f * 4, srcW + f * 4);
    };

    unsigned long long pacc[8];
    #pragma unroll
    for (int p = 0; p < 8; p++) pacc[p] = 0ull;

    issue(0);
    CP_COMMIT();

    for (int cin = 0; cin < 16; cin++) {
        if (cin < 15) {
            issue(cin + 1);
            CP_COMMIT();
            CP_WAIT1();
        } else {
            CP_WAIT0();
        }
        __syncthreads();

        if (active) {
            const int buf = cin & 1;
            const float* sIn = smem + buf * 5060;
            const ulonglong2* sW2 = (const ulonglong2*)(smem + 10120 + buf * 4000);
            #pragma unroll 1
            for (int kd = 0; kd < 5; kd++) {
                #pragma unroll
                for (int kh = 0; kh < 5; kh++) {
                    #pragma unroll
                    for (int kw = 0; kw < 5; kw++) {
                        float v = sIn[kd * 1012 + (3 * l + kh) * 44 + (3 * ow + kw)];
                        unsigned long long vv = f2u(v, v);
                        int tap = (kd * 5 + kh) * 5 + kw;
                        #pragma unroll
                        for (int q = 0; q < 4; q++) {
                            ulonglong2 w = sW2[tap * 8 + chalf * 4 + q];
                            ffma2(pacc[2 * q + 0], vv, w.x);
                            ffma2(pacc[2 * q + 1], vv, w.y);
                        }
                    }
                }
            }
        }
        __syncthreads();
    }
    if (!active) return;

    #pragma unroll
    for (int p = 0; p < 8; p++) {
        float2 f = u2f(pacc[p]);
        int c0 = chalf * 16 + 2 * p;
        size_t o0 = ((size_t)(n * 32 + c0) * 14 + od) * 196 + oh * 14 + ow;
        size_t o1 = ((size_t)(n * 32 + c0 + 1) * 14 + od) * 196 + oh * 14 + ow;
        g_c2[o0] = leaky(f.x + b2[c0]);
        g_c2[o1] = leaky(f.y + b2[c0 + 1]);
    }
}

// =======================================================================
// conv3: grid(4 cout-groups, 64 n); block 256 = pos(64) x cin-quarter(4).
// dynamic smem: sIn 4*2744 + sW 4*1500 = 16976 floats = 67904 B
// =======================================================================
__global__ __launch_bounds__(256) void conv3_kernel(const float* __restrict__ b3)
{
    extern __shared__ float smem[];

    const int g = blockIdx.x;
    const int n = blockIdx.y;
    const int tid = threadIdx.x;
    const int pos = tid & 63;
    const int sub = tid >> 6;
    const int od = pos >> 4, oh = (pos >> 2) & 3, ow = pos & 3;

    float* myIn = smem + sub * 2744;
    const float4* sW4 = (const float4*)(smem + 10976 + sub * 1500);

    float acc[12];
    #pragma unroll
    for (int c = 0; c < 12; c++) acc[c] = 0.f;

    for (int ci = 0; ci < 8; ci++) {
        const int cin = sub * 8 + ci;
        {
            const float* sI = g_c2 + (size_t)(n * 32 + cin) * 2744;
            for (int f = pos; f < 686; f += 64) cp16(myIn + f * 4, sI + f * 4);
            float* dW = smem + 10976 + sub * 1500;
            const float* sWsrc = g_w3t + (size_t)(g * 32 + cin) * 1500;
            for (int f = pos; f < 375; f += 64) cp16(dW + f * 4, sWsrc + f * 4);
        }
        CP_COMMIT();
        CP_WAIT0();
        __syncthreads();

        #pragma unroll 1
        for (int kd = 0; kd < 5; kd++) {
            const float* sr = myIn + (3 * od + kd) * 196 + 3 * oh * 14 + 3 * ow;
            #pragma unroll
            for (int kh = 0; kh < 5; kh++) {
                #pragma unroll
                for (int kw = 0; kw < 5; kw++) {
                    float v = sr[kh * 14 + kw];
                    const int tap = (kd * 5 + kh) * 5 + kw;
                    #pragma unroll
                    for (int q = 0; q < 3; q++) {
                        float4 w = sW4[tap * 3 + q];
                        acc[q * 4 + 0] = fmaf(v, w.x, acc[q * 4 + 0]);
                        acc[q * 4 + 1] = fmaf(v, w.y, acc[q * 4 + 1]);
                        acc[q * 4 + 2] = fmaf(v, w.z, acc[q * 4 + 2]);
                        acc[q * 4 + 3] = fmaf(v, w.w, acc[q * 4 + 3]);
                    }
                }
            }
        }
        __syncthreads();
    }

    float* sStage = smem;
    #pragma unroll
    for (int c = 0; c < 12; c++) sStage[tid * 12 + c] = acc[c];
    __syncthreads();
    if (sub == 0) {
        #pragma unroll
        for (int c = 0; c < 12; c++) {
            float s = sStage[pos * 12 + c] + sStage[(64 + pos) * 12 + c]
                    + sStage[(128 + pos) * 12 + c] + sStage[(192 + pos) * 12 + c];
            g_c3[(size_t)(n * 48 + g * 12 + c) * 64 + pos] = leaky(s + b3[g * 12 + c]);
        }
    }
}

// =======================================================================
// conv4 + feature: grid(64, 8); block = n x 8 cout; 4-way cin split per out
// =======================================================================
__global__ __launch_bounds__(256) void conv4_kernel(
    const float* __restrict__ w4, const float* __restrict__ b4)
{
    const int n  = blockIdx.x;
    const int c0 = blockIdx.y * 8;

    __shared__ float sIn[48 * 64];
    __shared__ float sRed[256];

    const int tid = threadIdx.x;
    const float* src = g_c3 + (size_t)n * 3072;
    for (int idx = tid; idx < 3072; idx += 256) sIn[idx] = src[idx];
    __syncthreads();

    const int sub = tid >> 6;
    const int loc = tid & 63;
    const int c   = loc >> 3;
    const int p   = loc & 7;
    const int od = p >> 2, oh = (p >> 1) & 1, ow = p & 1;

    float acc = 0.f;
    const float* wb = w4 + (size_t)(c0 + c) * 48 * 27;
    #pragma unroll
    for (int ci = 0; ci < 12; ci++) {
        int cin = sub * 12 + ci;
        const float* s  = sIn + cin * 64;
        const float* wk = wb + cin * 27;
        #pragma unroll
        for (int kd = 0; kd < 3; kd++)
            #pragma unroll
            for (int kh = 0; kh < 3; kh++)
                #pragma unroll
                for (int kw = 0; kw < 3; kw++)
                    acc = fmaf(s[(od + kd) * 16 + (oh + kh) * 4 + (ow + kw)],
                               __ldg(wk + kd * 9 + kh * 3 + kw), acc);
    }
    sRed[tid] = acc;
    __syncthreads();
    if (sub == 0) {
        float v = sRed[loc] + sRed[loc + 64] + sRed[loc + 128] + sRed[loc + 192];
        g_feat[n * 512 + (c0 + c) * 8 + p] = leaky(v + b4[c0 + c]);
    }
}

// =======================================================================
// M = feature @ T : block per row i; thread = 4 cols
// =======================================================================
__global__ __launch_bounds__(256) void mmul_kernel(const float* __restrict__ T)
{
    const int i = blockIdx.x;
    __shared__ float sF[512];
    const int tid = threadIdx.x;
    for (int k = tid; k < 512; k += 256) sF[k] = g_feat[i * 512 + k];
    __syncthreads();

    float acc0 = 0.f, acc1 = 0.f, acc2 = 0.f, acc3 = 0.f;
    for (int k = 0; k < 512; k++) {
        float v = sF[k];
        const float* tr = T + (size_t)k * 1024;
        acc0 = fmaf(v, tr[tid], acc0);
        acc1 = fmaf(v, tr[tid + 256], acc1);
        acc2 = fmaf(v, tr[tid + 512], acc2);
        acc3 = fmaf(v, tr[tid + 768], acc3);
    }
    g_M[i * 1024 + tid] = acc0;
    g_M[i * 1024 + tid + 256] = acc1;
    g_M[i * 1024 + tid + 512] = acc2;
    g_M[i * 1024 + tid + 768] = acc3;
}

// =======================================================================
// out_T[i,c] = sum_j exp( sum_k |M[i,c,k]-M[j,c,k]| )
// =======================================================================
__global__ __launch_bounds__(256) void mbd_kernel()
{
    const int i = blockIdx.x;
    __shared__ float sMi[1024];
    __shared__ float sRed[256];
    const int tid = threadIdx.x;
    const int c = tid & 63;
    const int js = tid >> 6;

    for (int k = tid; k < 1024; k += 256) sMi[k] = g_M[i * 1024 + k];
    __syncthreads();

    const float4* mi4 = (const float4*)(sMi + c * 16);
    float4 a0 = mi4[0], a1 = mi4[1], a2 = mi4[2], a3 = mi4[3];

    float acc = 0.f;
    for (int j = js; j < 64; j += 4) {
        const float4* mj4 = (const float4*)(g_M + j * 1024 + c * 16);
        float4 b0 = mj4[0], b1 = mj4[1], b2 = mj4[2], b3 = mj4[3];
        float d =
            fabsf(a0.x - b0.x) + fabsf(a0.y - b0.y) + fabsf(a0.z - b0.z) + fabsf(a0.w - b0.w) +
            fabsf(a1.x - b1.x) + fabsf(a1.y - b1.y) + fabsf(a1.z - b1.z) + fabsf(a1.w - b1.w) +
            fabsf(a2.x - b2.x) + fabsf(a2.y - b2.y) + fabsf(a2.z - b2.z) + fabsf(a2.w - b2.w) +
            fabsf(a3.x - b3.x) + fabsf(a3.y - b3.y) + fabsf(a3.z - b3.z) + fabsf(a3.w - b3.w);
        acc += expf(d);
    }
    sRed[tid] = acc;
    __syncthreads();
    if (js == 0) {
        float s = sRed[c] + sRed[c + 64] + sRed[c + 128] + sRed[c + 192];
        g_outT[i * 64 + c] = s;
    }
}

// =======================================================================
// final: z = [feature|outT] @ Wm + bm ; sigmoid
// =======================================================================
__global__ __launch_bounds__(64) void final_kernel(
    const float* __restrict__ Wm, const float* __restrict__ bm,
    float* __restrict__ out)
{
    const int i = threadIdx.x;
    float z = bm[0];
    const float* f = g_feat + i * 512;
    #pragma unroll 8
    for (int k = 0; k < 512; k++) z = fmaf(f[k], Wm[k], z);
    const float* t = g_outT + i * 64;
    #pragma unroll 8
    for (int c = 0; c < 64; c++) z = fmaf(t[c], Wm[512 + c], z);
    out[i] = 1.f / (1.f + expf(-z));
}

// =======================================================================
extern "C" void kernel_launch(void* const* d_in, const int* in_sizes, int n_in,
                              void* d_out, int out_size)
{
    const float* x  = (const float*)d_in[0];
    const float* w1 = (const float*)d_in[1];
    const float* b1 = (const float*)d_in[2];
    const float* w2 = (const float*)d_in[3];
    const float* b2 = (const float*)d_in[4];
    const float* w3 = (const float*)d_in[5];
    const float* b3 = (const float*)d_in[6];
    const float* w4 = (const float*)d_in[7];
    const float* b4 = (const float*)d_in[8];
    const float* T  = (const float*)d_in[9];
    const float* Wm = (const float*)d_in[10];
    const float* bm = (const float*)d_in[11];
    float* out = (float*)d_out;

    const int conv1_smem = 16704 * (int)sizeof(float);  // 66816
    const int conv2_smem = (2 * 5060 + 2 * 4000) * (int)sizeof(float);  // 72480
    const int conv3_smem = 16976 * (int)sizeof(float);  // 67904
    cudaFuncSetAttribute(conv1_kernel,
                         cudaFuncAttributeMaxDynamicSharedMemorySize, conv1_smem);
    cudaFuncSetAttribute(conv2_kernel,
                         cudaFuncAttributeMaxDynamicSharedMemorySize, conv2_smem);
    cudaFuncSetAttribute(conv3_kernel,
                         cudaFuncAttributeMaxDynamicSharedMemorySize, conv3_smem);

    prep_w2_kernel<<<250, 256>>>(w2);
    prep_w3_kernel<<<750, 256>>>(w3);
    conv1_kernel<<<dim3(11, 11, 64), 192, conv1_smem>>>(x, w1, b1);
    conv2_kernel<<<dim3(28, 64), 256, conv2_smem>>>(b2);
    conv3_kernel<<<dim3(4, 64), 256, conv3_smem>>>(b3);
    conv4_kernel<<<dim3(64, 8), 256>>>(w4, b4);
    mmul_kernel<<<64, 256>>>(T);
    mbd_kernel<<<64, 256>>>();
    final_kernel<<<1, 64>>>(Wm, bm, out);
}

// round 10
// speedup vs baseline: 1.9215x; 1.3494x over previous
#include <cuda_runtime.h>
#include <math.h>
#include <stdint.h>

// ---------------- problem constants ----------------
#define SLOPE 0.01f

// conv1: in [64,1,92,92,92] w[16,1,6,6,6] s2 -> [64,16,44,44,44]
// conv2: in [64,16,44,44,44] w[32,16,5,5,5] s3 -> [64,32,14,14,14]
// conv3: in [64,32,14,14,14] w[48,32,5,5,5] s3 -> [64,48,4,4,4]
// conv4: in [64,48,4,4,4]  w[64,48,3,3,3] s1 -> [64,64,2,2,2]

// ---------------- scratch (static device globals; no cudaMalloc) ----------
__device__ __align__(128) float g_c1[64ull * 16 * 44 * 44 * 44];   // 349 MB
__device__ __align__(128) float g_c2[64 * 32 * 14 * 14 * 14];      // 22.5 MB
__device__ __align__(128) float g_c3[64 * 48 * 64];
__device__ __align__(128) float g_feat[64 * 512];
__device__ __align__(128) float g_M[64 * 1024];
__device__ __align__(128) float g_outT[64 * 64];
__device__ __align__(128) float g_w2t[16 * 4000];        // [cin][tap*32+c]
__device__ __align__(128) float g_w3t[4 * 32 * 1500];    // [(g*32+cin)][tap*12+cc]
__device__ __align__(128) uint32_t g_w1f[1792];          // bf16x2 B-fragments [chunk][nt][lane][2]

__device__ __forceinline__ float leaky(float v) {
    return v >= 0.f ? v : SLOPE * v;
}

__device__ __forceinline__ void cp16(void* dst, const void* src) {
    unsigned d = (unsigned)__cvta_generic_to_shared(dst);
    asm volatile("cp.async.cg.shared.global [%0], [%1], 16;" :: "r"(d), "l"(src));
}
#define CP_COMMIT() asm volatile("cp.async.commit_group;")
#define CP_WAIT1()  asm volatile("cp.async.wait_group 1;")
#define CP_WAIT0()  asm volatile("cp.async.wait_group 0;")

__device__ __forceinline__ uint32_t packbf(float hi, float lo) {
    uint32_t r;
    asm("cvt.rn.bf16x2.f32 %0, %1, %2;" : "=r"(r) : "f"(hi), "f"(lo));
    return r;
}

// d += A(16x16 bf16, row) @ B(16x8 bf16, col)
__device__ __forceinline__ void mma16816(float* d,
    uint32_t a0, uint32_t a1, uint32_t a2, uint32_t a3,
    uint32_t b0, uint32_t b1) {
    asm volatile(
        "mma.sync.aligned.m16n8k16.row.col.f32.bf16.bf16.f32 "
        "{%0,%1,%2,%3}, {%4,%5,%6,%7}, {%8,%9}, {%0,%1,%2,%3};"
        : "+f"(d[0]), "+f"(d[1]), "+f"(d[2]), "+f"(d[3])
        : "r"(a0), "r"(a1), "r"(a2), "r"(a3), "r"(b0), "r"(b1));
}

// =======================================================================
// prep_w1f: B-fragments for mma.sync. idx = chunk*64 + nt*32 + lane.
// b0 = {W[k0][n], W[k0+1][n]}, b1 = {W[k0+8][n], W[k0+9][n]}; zero for k>=216.
// =======================================================================
__global__ __launch_bounds__(256) void prep_w1f_kernel(const float* __restrict__ w1)
{
    int idx = blockIdx.x * 256 + threadIdx.x;
    if (idx >= 896) return;
    int lane = idx & 31;
    int nt = (idx >> 5) & 1;
    int chunk = idx >> 6;
    int g = lane >> 2, c = lane & 3;
    int n = nt * 8 + g;
    int k0 = chunk * 16 + 2 * c;
    int k2 = k0 + 8;
    float v00 = (k0     < 216) ? w1[n * 216 + k0]     : 0.f;
    float v01 = (k0 + 1 < 216) ? w1[n * 216 + k0 + 1] : 0.f;
    float v10 = (k2     < 216) ? w1[n * 216 + k2]     : 0.f;
    float v11 = (k2 + 1 < 216) ? w1[n * 216 + k2 + 1] : 0.f;
    g_w1f[idx * 2]     = packbf(v01, v00);
    g_w1f[idx * 2 + 1] = packbf(v11, v10);
}

// =======================================================================
// conv1 via mma.sync bf16: block = (od-pair, n). 352 positions (2 od x 4 oh
// x 44 w per group), 11 oh-groups, 22 m16-tiles per group across 8 warps.
// D[pos, cout16] = gather(x)[pos, K=224] @ W^T  (K taps, zero-padded).
// =======================================================================
__global__ __launch_bounds__(256) void conv1_mma_kernel(
    const float* __restrict__ x, const float* __restrict__ b1)
{
    __shared__ int      sGoff[224];
    __shared__ uint32_t sBfrag[1792];
    __shared__ float    sWin[8832];   // [8 d][12 h][92 w]

    const int bx = blockIdx.x;        // od pair: od = 2*bx + odl
    const int n  = blockIdx.y;
    const int tid = threadIdx.x;
    const int wid = tid >> 5, lane = tid & 31;
    const int g = lane >> 2, c4 = lane & 3;

    // goff table: window-relative float offset per tap k (0 for padding)
    if (tid < 224) {
        int k = tid, o = 0;
        if (k < 216) {
            int kd = k / 36, r = k % 36;
            o = kd * 1104 + (r / 6) * 92 + (r % 6);
        }
        sGoff[tid] = o;
    }
    // B fragments (7 KB)
    for (int f = tid; f < 448; f += 256)
        cp16(sBfrag + f * 4, g_w1f + f * 4);
    CP_COMMIT();

    // bias (per-thread couts)
    const float bv00 = __ldg(b1 + 2 * c4),     bv01 = __ldg(b1 + 2 * c4 + 1);
    const float bv10 = __ldg(b1 + 2 * c4 + 8), bv11 = __ldg(b1 + 2 * c4 + 9);

    const float* xb = x + (size_t)n * 778688 + (size_t)(4 * bx) * 8464;
    const size_t nBase = (size_t)(n * 16) * 85184;
    const int go0 = 2 * c4, go1 = 2 * c4 + 1, go2 = 2 * c4 + 8, go3 = 2 * c4 + 9;

    for (int grp = 0; grp < 11; grp++) {
        // stage fp32 window [8][12][92]: 96 rows x 23 float4
        const float* xs = xb + (8 * grp) * 92;
        for (int f = tid; f < 2208; f += 256) {
            int row = f / 23, q = f - row * 23;
            int ld = row / 12, lh = row - ld * 12;
            cp16(sWin + row * 92 + q * 4, xs + (size_t)ld * 8464 + lh * 92 + q * 4);
        }
        CP_COMMIT(); CP_WAIT0();
        __syncthreads();

        for (int tt = wid; tt < 22; tt += 8) {
            const int pr0 = tt * 16 + g, pr1 = pr0 + 8;
            // window base offsets for the two A rows
            int odl0 = pr0 / 176, r0 = pr0 % 176, ohr0 = r0 / 44, ow0 = r0 % 44;
            int odl1 = pr1 / 176, r1 = pr1 % 176, ohr1 = r1 / 44, ow1 = r1 % 44;
            const int wb0 = odl0 * 2208 + ohr0 * 184 + 2 * ow0;
            const int wb1 = odl1 * 2208 + ohr1 * 184 + 2 * ow1;

            float d[8];
            #pragma unroll
            for (int i = 0; i < 8; i++) d[i] = 0.f;

            #pragma unroll
            for (int ch = 0; ch < 14; ch++) {
                const int kb = ch * 16;
                int o0 = sGoff[kb + go0], o1 = sGoff[kb + go1];
                int o2 = sGoff[kb + go2], o3 = sGoff[kb + go3];
                uint32_t a0 = packbf(sWin[wb0 + o1], sWin[wb0 + o0]);
                uint32_t a1 = packbf(sWin[wb1 + o1], sWin[wb1 + o0]);
                uint32_t a2 = packbf(sWin[wb0 + o3], sWin[wb0 + o2]);
                uint32_t a3 = packbf(sWin[wb1 + o3], sWin[wb1 + o2]);
                uint2 bb0 = *(const uint2*)&sBfrag[(ch * 2 + 0) * 64 + lane * 2];
                uint2 bb1 = *(const uint2*)&sBfrag[(ch * 2 + 1) * 64 + lane * 2];
                mma16816(d,     a0, a1, a2, a3, bb0.x, bb0.y);
                mma16816(d + 4, a0, a1, a2, a3, bb1.x, bb1.y);
            }

            // store: rows pr0/pr1, couts {2c,2c+1} (nt0) and {2c+8,2c+9} (nt1)
            size_t ob0 = nBase + (size_t)(2 * bx + odl0) * 1936
                       + (4 * grp + ohr0) * 44 + ow0;
            size_t ob1 = nBase + (size_t)(2 * bx + odl1) * 1936
                       + (4 * grp + ohr1) * 44 + ow1;
            const int co = 2 * c4;
            g_c1[ob0 + (size_t)(co)     * 85184] = leaky(d[0] + bv00);
            g_c1[ob0 + (size_t)(co + 1) * 85184] = leaky(d[1] + bv01);
            g_c1[ob1 + (size_t)(co)     * 85184] = leaky(d[2] + bv00);
            g_c1[ob1 + (size_t)(co + 1) * 85184] = leaky(d[3] + bv01);
            g_c1[ob0 + (size_t)(co + 8) * 85184] = leaky(d[4] + bv10);
            g_c1[ob0 + (size_t)(co + 9) * 85184] = leaky(d[5] + bv11);
            g_c1[ob1 + (size_t)(co + 8) * 85184] = leaky(d[6] + bv10);
            g_c1[ob1 + (size_t)(co + 9) * 85184] = leaky(d[7] + bv11);
        }
        __syncthreads();
    }
}

// =======================================================================
// prep_w2: transpose conv2 weights to [cin][tap*32 + c]
// =======================================================================
__global__ __launch_bounds__(256) void prep_w2_kernel(const float* __restrict__ w2)
{
    int idx = blockIdx.x * 256 + threadIdx.x;
    if (idx >= 16 * 4000) return;
    int cin = idx / 4000;
    int r   = idx % 4000;
    int tap = r >> 5, c = r & 31;
    g_w2t[idx] = w2[(c * 16 + cin) * 125 + tap];
}

// =======================================================================
// prep_w3
// =======================================================================
__global__ __launch_bounds__(256) void prep_w3_kernel(const float* __restrict__ w3)
{
    int idx = blockIdx.x * 256 + threadIdx.x;
    if (idx >= 192000) return;
    int gcin = idx / 1500;
    int r    = idx % 1500;
    int tap = r / 12, cc = r % 12;
    int g = gcin / 32, cin = gcin % 32;
    g_w3t[idx] = w3[((g * 12 + cc) * 32 + cin) * 125 + tap];
}

// =======================================================================
// conv2: double-buffered cp.async pipeline over cin (FFMA2 inner)
// =======================================================================
__device__ __forceinline__ void ffma2(unsigned long long& d,
                                      unsigned long long a,
                                      unsigned long long b) {
    asm("fma.rn.f32x2 %0, %1, %2, %0;" : "+l"(d) : "l"(a), "l"(b));
}
__device__ __forceinline__ unsigned long long f2u(float lo, float hi) {
    unsigned long long v;
    asm("mov.b64 %0, {%1, %2};" : "=l"(v) : "f"(lo), "f"(hi));
    return v;
}
__device__ __forceinline__ float2 u2f(unsigned long long v) {
    float2 f;
    asm("mov.b64 {%0, %1}, %2;" : "=f"(f.x), "=f"(f.y) : "l"(v));
    return f;
}

__global__ __launch_bounds__(256) void conv2_kernel(const float* __restrict__ b2)
{
    extern __shared__ float smemf[];

    const int od = blockIdx.x >> 1;
    const int hh = blockIdx.x & 1;
    const int n  = blockIdx.y;

    const int tid = threadIdx.x;
    const int active = (tid < 196);
    const int pos = tid % 98;
    const int chalf = tid / 98;
    const int l  = pos / 14;
    const int ow = pos % 14;
    const int oh = hh * 7 + l;

    const int id0 = 3 * od;
    const int ih0 = 21 * hh;

    auto issue = [&](int cin) {
        int buf = cin & 1;
        float* dI = smemf + buf * 5060;
        float* dW = smemf + 10120 + buf * 4000;
        const float* srcI = g_c1 + (size_t)(n * 16 + cin) * 85184;
        for (int f = tid; f < 1265; f += 256) {
            int row = f / 11, q = f % 11;
            int ld = row / 23, lh = row % 23;
            cp16(dI + row * 44 + q * 4,
                 srcI + (size_t)(id0 + ld) * 1936 + (ih0 + lh) * 44 + q * 4);
        }
        const float* srcW = g_w2t + cin * 4000;
        for (int f = tid; f < 1000; f += 256)
            cp16(dW + f * 4, srcW + f * 4);
    };

    unsigned long long pacc[8];
    #pragma unroll
    for (int p = 0; p < 8; p++) pacc[p] = 0ull;

    issue(0);
    CP_COMMIT();

    for (int cin = 0; cin < 16; cin++) {
        if (cin < 15) {
            issue(cin + 1);
            CP_COMMIT();
            CP_WAIT1();
        } else {
            CP_WAIT0();
        }
        __syncthreads();

        if (active) {
            const int buf = cin & 1;
            const float* sIn = smemf + buf * 5060;
            const ulonglong2* sW2 = (const ulonglong2*)(smemf + 10120 + buf * 4000);
            #pragma unroll 1
            for (int kd = 0; kd < 5; kd++) {
                #pragma unroll
                for (int kh = 0; kh < 5; kh++) {
                    #pragma unroll
                    for (int kw = 0; kw < 5; kw++) {
                        float v = sIn[kd * 1012 + (3 * l + kh) * 44 + (3 * ow + kw)];
                        unsigned long long vv = f2u(v, v);
                        int tap = (kd * 5 + kh) * 5 + kw;
                        #pragma unroll
                        for (int q = 0; q < 4; q++) {
                            ulonglong2 w = sW2[tap * 8 + chalf * 4 + q];
                            ffma2(pacc[2 * q + 0], vv, w.x);
                            ffma2(pacc[2 * q + 1], vv, w.y);
                        }
                    }
                }
            }
        }
        __syncthreads();
    }
    if (!active) return;

    #pragma unroll
    for (int p = 0; p < 8; p++) {
        float2 f = u2f(pacc[p]);
        int c0 = chalf * 16 + 2 * p;
        size_t o0 = ((size_t)(n * 32 + c0) * 14 + od) * 196 + oh * 14 + ow;
        size_t o1 = ((size_t)(n * 32 + c0 + 1) * 14 + od) * 196 + oh * 14 + ow;
        g_c2[o0] = leaky(f.x + b2[c0]);
        g_c2[o1] = leaky(f.y + b2[c0 + 1]);
    }
}

// =======================================================================
// conv3: grid(4, 64); block 256 = pos(64) x cin-quarter(4)
// =======================================================================
__global__ __launch_bounds__(256) void conv3_kernel(const float* __restrict__ b3)
{
    extern __shared__ float smemf[];

    const int g = blockIdx.x;
    const int n = blockIdx.y;
    const int tid = threadIdx.x;
    const int pos = tid & 63;
    const int sub = tid >> 6;
    const int od = pos >> 4, oh = (pos >> 2) & 3, ow = pos & 3;

    float* myIn = smemf + sub * 2744;
    const float4* sW4 = (const float4*)(smemf + 10976 + sub * 1500);

    float acc[12];
    #pragma unroll
    for (int c = 0; c < 12; c++) acc[c] = 0.f;

    for (int ci = 0; ci < 8; ci++) {
        const int cin = sub * 8 + ci;
        {
            const float* sI = g_c2 + (size_t)(n * 32 + cin) * 2744;
            for (int f = pos; f < 686; f += 64) cp16(myIn + f * 4, sI + f * 4);
            float* dW = smemf + 10976 + sub * 1500;
            const float* sWsrc = g_w3t + (size_t)(g * 32 + cin) * 1500;
            for (int f = pos; f < 375; f += 64) cp16(dW + f * 4, sWsrc + f * 4);
        }
        CP_COMMIT();
        CP_WAIT0();
        __syncthreads();

        #pragma unroll 1
        for (int kd = 0; kd < 5; kd++) {
            const float* sr = myIn + (3 * od + kd) * 196 + 3 * oh * 14 + 3 * ow;
            #pragma unroll
            for (int kh = 0; kh < 5; kh++) {
                #pragma unroll
                for (int kw = 0; kw < 5; kw++) {
                    float v = sr[kh * 14 + kw];
                    const int tap = (kd * 5 + kh) * 5 + kw;
                    #pragma unroll
                    for (int q = 0; q < 3; q++) {
                        float4 w = sW4[tap * 3 + q];
                        acc[q * 4 + 0] = fmaf(v, w.x, acc[q * 4 + 0]);
                        acc[q * 4 + 1] = fmaf(v, w.y, acc[q * 4 + 1]);
                        acc[q * 4 + 2] = fmaf(v, w.z, acc[q * 4 + 2]);
                        acc[q * 4 + 3] = fmaf(v, w.w, acc[q * 4 + 3]);
                    }
                }
            }
        }
        __syncthreads();
    }

    float* sStage = smemf;
    #pragma unroll
    for (int c = 0; c < 12; c++) sStage[tid * 12 + c] = acc[c];
    __syncthreads();
    if (sub == 0) {
        #pragma unroll
        for (int c = 0; c < 12; c++) {
            float s = sStage[pos * 12 + c] + sStage[(64 + pos) * 12 + c]
                    + sStage[(128 + pos) * 12 + c] + sStage[(192 + pos) * 12 + c];
            g_c3[(size_t)(n * 48 + g * 12 + c) * 64 + pos] = leaky(s + b3[g * 12 + c]);
        }
    }
}

// =======================================================================
// conv4 + feature
// =======================================================================
__global__ __launch_bounds__(256) void conv4_kernel(
    const float* __restrict__ w4, const float* __restrict__ b4)
{
    const int n  = blockIdx.x;
    const int c0 = blockIdx.y * 8;

    __shared__ float sIn[48 * 64];
    __shared__ float sRed[256];

    const int tid = threadIdx.x;
    const float* src = g_c3 + (size_t)n * 3072;
    for (int idx = tid; idx < 3072; idx += 256) sIn[idx] = src[idx];
    __syncthreads();

    const int sub = tid >> 6;
    const int loc = tid & 63;
    const int c   = loc >> 3;
    const int p   = loc & 7;
    const int od = p >> 2, oh = (p >> 1) & 1, ow = p & 1;

    float acc = 0.f;
    const float* wb = w4 + (size_t)(c0 + c) * 48 * 27;
    #pragma unroll
    for (int ci = 0; ci < 12; ci++) {
        int cin = sub * 12 + ci;
        const float* s  = sIn + cin * 64;
        const float* wk = wb + cin * 27;
        #pragma unroll
        for (int kd = 0; kd < 3; kd++)
            #pragma unroll
            for (int kh = 0; kh < 3; kh++)
                #pragma unroll
                for (int kw = 0; kw < 3; kw++)
                    acc = fmaf(s[(od + kd) * 16 + (oh + kh) * 4 + (ow + kw)],
                               __ldg(wk + kd * 9 + kh * 3 + kw), acc);
    }
    sRed[tid] = acc;
    __syncthreads();
    if (sub == 0) {
        float v = sRed[loc] + sRed[loc + 64] + sRed[loc + 128] + sRed[loc + 192];
        g_feat[n * 512 + (c0 + c) * 8 + p] = leaky(v + b4[c0 + c]);
    }
}

// =======================================================================
// M = feature @ T
// =======================================================================
__global__ __launch_bounds__(256) void mmul_kernel(const float* __restrict__ T)
{
    const int i = blockIdx.x;
    __shared__ float sF[512];
    const int tid = threadIdx.x;
    for (int k = tid; k < 512; k += 256) sF[k] = g_feat[i * 512 + k];
    __syncthreads();

    float acc0 = 0.f, acc1 = 0.f, acc2 = 0.f, acc3 = 0.f;
    for (int k = 0; k < 512; k++) {
        float v = sF[k];
        const float* tr = T + (size_t)k * 1024;
        acc0 = fmaf(v, tr[tid], acc0);
        acc1 = fmaf(v, tr[tid + 256], acc1);
        acc2 = fmaf(v, tr[tid + 512], acc2);
        acc3 = fmaf(v, tr[tid + 768], acc3);
    }
    g_M[i * 1024 + tid] = acc0;
    g_M[i * 1024 + tid + 256] = acc1;
    g_M[i * 1024 + tid + 512] = acc2;
    g_M[i * 1024 + tid + 768] = acc3;
}

// =======================================================================
// out_T[i,c] = sum_j exp( sum_k |M[i,c,k]-M[j,c,k]| )
// =======================================================================
__global__ __launch_bounds__(256) void mbd_kernel()
{
    const int i = blockIdx.x;
    __shared__ float sMi[1024];
    __shared__ float sRed[256];
    const int tid = threadIdx.x;
    const int c = tid & 63;
    const int js = tid >> 6;

    for (int k = tid; k < 1024; k += 256) sMi[k] = g_M[i * 1024 + k];
    __syncthreads();

    const float4* mi4 = (const float4*)(sMi + c * 16);
    float4 a0 = mi4[0], a1 = mi4[1], a2 = mi4[2], a3 = mi4[3];

    float acc = 0.f;
    for (int j = js; j < 64; j += 4) {
        const float4* mj4 = (const float4*)(g_M + j * 1024 + c * 16);
        float4 b0 = mj4[0], b1 = mj4[1], b2 = mj4[2], b3 = mj4[3];
        float d =
            fabsf(a0.x - b0.x) + fabsf(a0.y - b0.y) + fabsf(a0.z - b0.z) + fabsf(a0.w - b0.w) +
            fabsf(a1.x - b1.x) + fabsf(a1.y - b1.y) + fabsf(a1.z - b1.z) + fabsf(a1.w - b1.w) +
            fabsf(a2.x - b2.x) + fabsf(a2.y - b2.y) + fabsf(a2.z - b2.z) + fabsf(a2.w - b2.w) +
            fabsf(a3.x - b3.x) + fabsf(a3.y - b3.y) + fabsf(a3.z - b3.z) + fabsf(a3.w - b3.w);
        acc += expf(d);
    }
    sRed[tid] = acc;
    __syncthreads();
    if (js == 0) {
        float s = sRed[c] + sRed[c + 64] + sRed[c + 128] + sRed[c + 192];
        g_outT[i * 64 + c] = s;
    }
}

// =======================================================================
// final
// =======================================================================
__global__ __launch_bounds__(64) void final_kernel(
    const float* __restrict__ Wm, const float* __restrict__ bm,
    float* __restrict__ out)
{
    const int i = threadIdx.x;
    float z = bm[0];
    const float* f = g_feat + i * 512;
    #pragma unroll 8
    for (int k = 0; k < 512; k++) z = fmaf(f[k], Wm[k], z);
    const float* t = g_outT + i * 64;
    #pragma unroll 8
    for (int c = 0; c < 64; c++) z = fmaf(t[c], Wm[512 + c], z);
    out[i] = 1.f / (1.f + expf(-z));
}

// =======================================================================
extern "C" void kernel_launch(void* const* d_in, const int* in_sizes, int n_in,
                              void* d_out, int out_size)
{
    const float* x  = (const float*)d_in[0];
    const float* w1 = (const float*)d_in[1];
    const float* b1 = (const float*)d_in[2];
    const float* w2 = (const float*)d_in[3];
    const float* b2 = (const float*)d_in[4];
    const float* w3 = (const float*)d_in[5];
    const float* b3 = (const float*)d_in[6];
    const float* w4 = (const float*)d_in[7];
    const float* b4 = (const float*)d_in[8];
    const float* T  = (const float*)d_in[9];
    const float* Wm = (const float*)d_in[10];
    const float* bm = (const float*)d_in[11];
    float* out = (float*)d_out;

    const int conv2_smem = (2 * 5060 + 2 * 4000) * (int)sizeof(float);  // 72480
    const int conv3_smem = 16976 * (int)sizeof(float);                  // 67904
    cudaFuncSetAttribute(conv2_kernel,
                         cudaFuncAttributeMaxDynamicSharedMemorySize, conv2_smem);
    cudaFuncSetAttribute(conv3_kernel,
                         cudaFuncAttributeMaxDynamicSharedMemorySize, conv3_smem);

    prep_w1f_kernel<<<4, 256>>>(w1);
    prep_w2_kernel<<<250, 256>>>(w2);
    prep_w3_kernel<<<750, 256>>>(w3);
    conv1_mma_kernel<<<dim3(22, 64), 256>>>(x, b1);
    conv2_kernel<<<dim3(28, 64), 256, conv2_smem>>>(b2);
    conv3_kernel<<<dim3(4, 64), 256, conv3_smem>>>(b3);
    conv4_kernel<<<dim3(64, 8), 256>>>(w4, b4);
    mmul_kernel<<<64, 256>>>(T);
    mbd_kernel<<<64, 256>>>();
    final_kernel<<<1, 64>>>(Wm, bm, out);
}

// round 11
// speedup vs baseline: 1.9989x; 1.0403x over previous
#include <cuda_runtime.h>
#include <cuda_bf16.h>
#include <math.h>
#include <stdint.h>

// ---------------- problem constants ----------------
#define SLOPE 0.01f

// conv1: in [64,1,92,92,92] w[16,1,6,6,6] s2 -> [64,16,44,44,44]
// conv2: in [64,16,44,44,44] w[32,16,5,5,5] s3 -> [64,32,14,14,14]
// conv3: in [64,32,14,14,14] w[48,32,5,5,5] s3 -> [64,48,4,4,4]
// conv4: in [64,48,4,4,4]  w[64,48,3,3,3] s1 -> [64,64,2,2,2]

// ---------------- scratch (static device globals; no cudaMalloc) ----------
__device__ __align__(128) __nv_bfloat16 g_c1b[64ull * 16 * 85184 + 64]; // 175 MB (+pad)
__device__ __align__(128) float g_c2[64 * 32 * 14 * 14 * 14];      // 22.5 MB
__device__ __align__(128) float g_c3[64 * 48 * 64];
__device__ __align__(128) float g_feat[64 * 512];
__device__ __align__(128) float g_M[64 * 1024];
__device__ __align__(128) float g_outT[64 * 64];
__device__ __align__(128) float g_w2t[16 * 4000];        // [cin][tap*32+c]
__device__ __align__(128) float g_w3t[4 * 32 * 1500];    // [(g*32+cin)][tap*12+cc]
__device__ __align__(128) uint32_t g_w1f[1792];          // bf16x2 B-fragments

__device__ __forceinline__ float leaky(float v) {
    return v >= 0.f ? v : SLOPE * v;
}

__device__ __forceinline__ void cp16(void* dst, const void* src) {
    unsigned d = (unsigned)__cvta_generic_to_shared(dst);
    asm volatile("cp.async.cg.shared.global [%0], [%1], 16;" :: "r"(d), "l"(src));
}
__device__ __forceinline__ void cp8(void* dst, const void* src) {
    unsigned d = (unsigned)__cvta_generic_to_shared(dst);
    asm volatile("cp.async.ca.shared.global [%0], [%1], 8;" :: "r"(d), "l"(src));
}
#define CP_COMMIT() asm volatile("cp.async.commit_group;")
#define CP_WAIT1()  asm volatile("cp.async.wait_group 1;")
#define CP_WAIT0()  asm volatile("cp.async.wait_group 0;")

__device__ __forceinline__ uint32_t packbf(float hi, float lo) {
    uint32_t r;
    asm("cvt.rn.bf16x2.f32 %0, %1, %2;" : "=r"(r) : "f"(hi), "f"(lo));
    return r;
}

// d += A(16x16 bf16, row) @ B(16x8 bf16, col)
__device__ __forceinline__ void mma16816(float* d,
    uint32_t a0, uint32_t a1, uint32_t a2, uint32_t a3,
    uint32_t b0, uint32_t b1) {
    asm volatile(
        "mma.sync.aligned.m16n8k16.row.col.f32.bf16.bf16.f32 "
        "{%0,%1,%2,%3}, {%4,%5,%6,%7}, {%8,%9}, {%0,%1,%2,%3};"
        : "+f"(d[0]), "+f"(d[1]), "+f"(d[2]), "+f"(d[3])
        : "r"(a0), "r"(a1), "r"(a2), "r"(a3), "r"(b0), "r"(b1));
}

// =======================================================================
// prep_w1f: B-fragments for mma.sync (zero for k>=216)
// =======================================================================
__global__ __launch_bounds__(256) void prep_w1f_kernel(const float* __restrict__ w1)
{
    int idx = blockIdx.x * 256 + threadIdx.x;
    if (idx >= 896) return;
    int lane = idx & 31;
    int nt = (idx >> 5) & 1;
    int chunk = idx >> 6;
    int g = lane >> 2, c = lane & 3;
    int n = nt * 8 + g;
    int k0 = chunk * 16 + 2 * c;
    int k2 = k0 + 8;
    float v00 = (k0     < 216) ? w1[n * 216 + k0]     : 0.f;
    float v01 = (k0 + 1 < 216) ? w1[n * 216 + k0 + 1] : 0.f;
    float v10 = (k2     < 216) ? w1[n * 216 + k2]     : 0.f;
    float v11 = (k2 + 1 < 216) ? w1[n * 216 + k2 + 1] : 0.f;
    g_w1f[idx * 2]     = packbf(v01, v00);
    g_w1f[idx * 2 + 1] = packbf(v11, v10);
}

// =======================================================================
// conv1 via mma.sync bf16. Paired gather: even-k tap pairs are contiguous
// floats (kernel width 6), so one LDS.64 feeds each bf16x2 A element.
// Output stored bf16 (g_c1b).
// =======================================================================
__global__ __launch_bounds__(256) void conv1_mma_kernel(
    const float* __restrict__ x, const float* __restrict__ b1)
{
    __shared__ int      sGoffE[112];   // window offset for even taps k=2t
    __shared__ uint32_t sBfrag[1792];
    __shared__ float    sWin[8832];    // [8 d][12 h][92 w]

    const int bx = blockIdx.x;         // od pair
    const int n  = blockIdx.y;
    const int tid = threadIdx.x;
    const int wid = tid >> 5, lane = tid & 31;
    const int g = lane >> 2, c4 = lane & 3;

    if (tid < 112) {
        int k = 2 * tid, o = 0;
        if (k < 216) {
            int kd = k / 36, r = k % 36;
            o = kd * 1104 + (r / 6) * 92 + (r % 6);
        }
        sGoffE[tid] = o;
    }
    for (int f = tid; f < 448; f += 256)
        cp16(sBfrag + f * 4, g_w1f + f * 4);
    CP_COMMIT();

    const float bv00 = __ldg(b1 + 2 * c4),     bv01 = __ldg(b1 + 2 * c4 + 1);
    const float bv10 = __ldg(b1 + 2 * c4 + 8), bv11 = __ldg(b1 + 2 * c4 + 9);

    const float* xb = x + (size_t)n * 778688 + (size_t)(4 * bx) * 8464;
    const size_t nBase = (size_t)(n * 16) * 85184;

    for (int grp = 0; grp < 11; grp++) {
        const float* xs = xb + (8 * grp) * 92;
        for (int f = tid; f < 2208; f += 256) {
            int row = f / 23, q = f - row * 23;
            int ld = row / 12, lh = row - ld * 12;
            cp16(sWin + row * 92 + q * 4, xs + (size_t)ld * 8464 + lh * 92 + q * 4);
        }
        CP_COMMIT(); CP_WAIT0();
        __syncthreads();

        for (int tt = wid; tt < 22; tt += 8) {
            const int pr0 = tt * 16 + g, pr1 = pr0 + 8;
            int odl0 = pr0 / 176, r0 = pr0 % 176, ohr0 = r0 / 44, ow0 = r0 % 44;
            int odl1 = pr1 / 176, r1 = pr1 % 176, ohr1 = r1 / 44, ow1 = r1 % 44;
            const int wb0 = odl0 * 2208 + ohr0 * 184 + 2 * ow0;
            const int wb1 = odl1 * 2208 + ohr1 * 184 + 2 * ow1;

            float d[8];
            #pragma unroll
            for (int i = 0; i < 8; i++) d[i] = 0.f;

            #pragma unroll
            for (int ch = 0; ch < 14; ch++) {
                int o0 = sGoffE[8 * ch + c4];       // taps kb+2c4, +1
                int o2 = sGoffE[8 * ch + c4 + 4];   // taps kb+2c4+8, +9
                float2 p00 = *(const float2*)(sWin + wb0 + o0);
                float2 p10 = *(const float2*)(sWin + wb1 + o0);
                float2 p02 = *(const float2*)(sWin + wb0 + o2);
                float2 p12 = *(const float2*)(sWin + wb1 + o2);
                uint32_t a0 = packbf(p00.y, p00.x);
                uint32_t a1 = packbf(p10.y, p10.x);
                uint32_t a2 = packbf(p02.y, p02.x);
                uint32_t a3 = packbf(p12.y, p12.x);
                uint2 bb0 = *(const uint2*)&sBfrag[(ch * 2 + 0) * 64 + lane * 2];
                uint2 bb1 = *(const uint2*)&sBfrag[(ch * 2 + 1) * 64 + lane * 2];
                mma16816(d,     a0, a1, a2, a3, bb0.x, bb0.y);
                mma16816(d + 4, a0, a1, a2, a3, bb1.x, bb1.y);
            }

            size_t ob0 = nBase + (size_t)(2 * bx + odl0) * 1936
                       + (4 * grp + ohr0) * 44 + ow0;
            size_t ob1 = nBase + (size_t)(2 * bx + odl1) * 1936
                       + (4 * grp + ohr1) * 44 + ow1;
            const int co = 2 * c4;
            g_c1b[ob0 + (size_t)(co)     * 85184] = __float2bfloat16(leaky(d[0] + bv00));
            g_c1b[ob0 + (size_t)(co + 1) * 85184] = __float2bfloat16(leaky(d[1] + bv01));
            g_c1b[ob1 + (size_t)(co)     * 85184] = __float2bfloat16(leaky(d[2] + bv00));
            g_c1b[ob1 + (size_t)(co + 1) * 85184] = __float2bfloat16(leaky(d[3] + bv01));
            g_c1b[ob0 + (size_t)(co + 8) * 85184] = __float2bfloat16(leaky(d[4] + bv10));
            g_c1b[ob0 + (size_t)(co + 9) * 85184] = __float2bfloat16(leaky(d[5] + bv11));
            g_c1b[ob1 + (size_t)(co + 8) * 85184] = __float2bfloat16(leaky(d[6] + bv10));
            g_c1b[ob1 + (size_t)(co + 9) * 85184] = __float2bfloat16(leaky(d[7] + bv11));
        }
        __syncthreads();
    }
}

// =======================================================================
// prep_w2: transpose conv2 weights to [cin][tap*32 + c]
// =======================================================================
__global__ __launch_bounds__(256) void prep_w2_kernel(const float* __restrict__ w2)
{
    int idx = blockIdx.x * 256 + threadIdx.x;
    if (idx >= 16 * 4000) return;
    int cin = idx / 4000;
    int r   = idx % 4000;
    int tap = r >> 5, c = r & 31;
    g_w2t[idx] = w2[(c * 16 + cin) * 125 + tap];
}

// =======================================================================
// prep_w3
// =======================================================================
__global__ __launch_bounds__(256) void prep_w3_kernel(const float* __restrict__ w3)
{
    int idx = blockIdx.x * 256 + threadIdx.x;
    if (idx >= 192000) return;
    int gcin = idx / 1500;
    int r    = idx % 1500;
    int tap = r / 12, cc = r % 12;
    int g = gcin / 32, cin = gcin % 32;
    g_w3t[idx] = w3[((g * 12 + cc) * 32 + cin) * 125 + tap];
}

// =======================================================================
// conv2: bf16 input tiles (halved smem -> 4 CTAs/SM), fp32 weights, FFMA2.
// smem: sIn bf16 2x5060 (20240 B) + sW f32 2x4000 (32000 B) = 52240 B
// =======================================================================
__device__ __forceinline__ void ffma2(unsigned long long& d,
                                      unsigned long long a,
                                      unsigned long long b) {
    asm("fma.rn.f32x2 %0, %1, %2, %0;" : "+l"(d) : "l"(a), "l"(b));
}
__device__ __forceinline__ float2 u2f(unsigned long long v) {
    float2 f;
    asm("mov.b64 {%0, %1}, %2;" : "=f"(f.x), "=f"(f.y) : "l"(v));
    return f;
}

__global__ __launch_bounds__(256) void conv2_kernel(const float* __restrict__ b2)
{
    extern __shared__ char smemc[];
    __nv_bfloat16* sInB = (__nv_bfloat16*)smemc;           // 2 x 5060 bf16
    float* sWf = (float*)(smemc + 20240);                  // 2 x 4000 f32

    const int od = blockIdx.x >> 1;
    const int hh = blockIdx.x & 1;
    const int n  = blockIdx.y;

    const int tid = threadIdx.x;
    const int active = (tid < 196);
    const int pos = tid % 98;
    const int chalf = tid / 98;
    const int l  = pos / 14;
    const int ow = pos % 14;
    const int oh = hh * 7 + l;

    const int id0 = 3 * od;
    const int ih0 = 21 * hh;

    auto issue = [&](int cin) {
        int buf = cin & 1;
        __nv_bfloat16* dI = sInB + buf * 5060;
        float* dW = sWf + buf * 4000;
        const __nv_bfloat16* srcI = g_c1b + (size_t)(n * 16 + cin) * 85184;
        // input tile [5][23][44] bf16: 115 rows x 11 chunks of 8B (4 bf16)
        for (int f = tid; f < 1265; f += 256) {
            int row = f / 11, q = f % 11;
            int ld = row / 23, lh = row % 23;
            cp8(dI + row * 44 + q * 4,
                srcI + (size_t)(id0 + ld) * 1936 + (ih0 + lh) * 44 + q * 4);
        }
        const float* srcW = g_w2t + cin * 4000;
        for (int f = tid; f < 1000; f += 256)
            cp16(dW + f * 4, srcW + f * 4);
    };

    unsigned long long pacc[8];
    #pragma unroll
    for (int p = 0; p < 8; p++) pacc[p] = 0ull;

    issue(0);
    CP_COMMIT();

    for (int cin = 0; cin < 16; cin++) {
        if (cin < 15) {
            issue(cin + 1);
            CP_COMMIT();
            CP_WAIT1();
        } else {
            CP_WAIT0();
        }
        __syncthreads();

        if (active) {
            const int buf = cin & 1;
            const __nv_bfloat16* sIn = sInB + buf * 5060;
            const ulonglong2* sW2 = (const ulonglong2*)(sWf + buf * 4000);
            #pragma unroll 1
            for (int kd = 0; kd < 5; kd++) {
                #pragma unroll
                for (int kh = 0; kh < 5; kh++) {
                    #pragma unroll
                    for (int kw = 0; kw < 5; kw++) {
                        unsigned short raw =
                            *(const unsigned short*)(sIn + kd * 1012 + (3 * l + kh) * 44 + (3 * ow + kw));
                        unsigned int bits = ((unsigned int)raw) << 16;
                        unsigned long long vv;
                        asm("mov.b64 %0, {%1, %1};" : "=l"(vv) : "r"(bits));
                        int tap = (kd * 5 + kh) * 5 + kw;
                        #pragma unroll
                        for (int q = 0; q < 4; q++) {
                            ulonglong2 w = sW2[tap * 8 + chalf * 4 + q];
                            ffma2(pacc[2 * q + 0], vv, w.x);
                            ffma2(pacc[2 * q + 1], vv, w.y);
                        }
                    }
                }
            }
        }
        __syncthreads();
    }
    if (!active) return;

    #pragma unroll
    for (int p = 0; p < 8; p++) {
        float2 f = u2f(pacc[p]);
        int c0 = chalf * 16 + 2 * p;
        size_t o0 = ((size_t)(n * 32 + c0) * 14 + od) * 196 + oh * 14 + ow;
        size_t o1 = ((size_t)(n * 32 + c0 + 1) * 14 + od) * 196 + oh * 14 + ow;
        g_c2[o0] = leaky(f.x + b2[c0]);
        g_c2[o1] = leaky(f.y + b2[c0 + 1]);
    }
}

// =======================================================================
// conv3: grid(4, 64); block 256 = pos(64) x cin-quarter(4)
// =======================================================================
__global__ __launch_bounds__(256) void conv3_kernel(const float* __restrict__ b3)
{
    extern __shared__ float smemf[];

    const int g = blockIdx.x;
    const int n = blockIdx.y;
    const int tid = threadIdx.x;
    const int pos = tid & 63;
    const int sub = tid >> 6;
    const int od = pos >> 4, oh = (pos >> 2) & 3, ow = pos & 3;

    float* myIn = smemf + sub * 2744;
    const float4* sW4 = (const float4*)(smemf + 10976 + sub * 1500);

    float acc[12];
    #pragma unroll
    for (int c = 0; c < 12; c++) acc[c] = 0.f;

    for (int ci = 0; ci < 8; ci++) {
        const int cin = sub * 8 + ci;
        {
            const float* sI = g_c2 + (size_t)(n * 32 + cin) * 2744;
            for (int f = pos; f < 686; f += 64) cp16(myIn + f * 4, sI + f * 4);
            float* dW = smemf + 10976 + sub * 1500;
            const float* sWsrc = g_w3t + (size_t)(g * 32 + cin) * 1500;
            for (int f = pos; f < 375; f += 64) cp16(dW + f * 4, sWsrc + f * 4);
        }
        CP_COMMIT();
        CP_WAIT0();
        __syncthreads();

        #pragma unroll 1
        for (int kd = 0; kd < 5; kd++) {
            const float* sr = myIn + (3 * od + kd) * 196 + 3 * oh * 14 + 3 * ow;
            #pragma unroll
            for (int kh = 0; kh < 5; kh++) {
                #pragma unroll
                for (int kw = 0; kw < 5; kw++) {
                    float v = sr[kh * 14 + kw];
                    const int tap = (kd * 5 + kh) * 5 + kw;
                    #pragma unroll
                    for (int q = 0; q < 3; q++) {
                        float4 w = sW4[tap * 3 + q];
                        acc[q * 4 + 0] = fmaf(v, w.x, acc[q * 4 + 0]);
                        acc[q * 4 + 1] = fmaf(v, w.y, acc[q * 4 + 1]);
                        acc[q * 4 + 2] = fmaf(v, w.z, acc[q * 4 + 2]);
                        acc[q * 4 + 3] = fmaf(v, w.w, acc[q * 4 + 3]);
                    }
                }
            }
        }
        __syncthreads();
    }

    float* sStage = smemf;
    #pragma unroll
    for (int c = 0; c < 12; c++) sStage[tid * 12 + c] = acc[c];
    __syncthreads();
    if (sub == 0) {
        #pragma unroll
        for (int c = 0; c < 12; c++) {
            float s = sStage[pos * 12 + c] + sStage[(64 + pos) * 12 + c]
                    + sStage[(128 + pos) * 12 + c] + sStage[(192 + pos) * 12 + c];
            g_c3[(size_t)(n * 48 + g * 12 + c) * 64 + pos] = leaky(s + b3[g * 12 + c]);
        }
    }
}

// =======================================================================
// conv4 + feature
// =======================================================================
__global__ __launch_bounds__(256) void conv4_kernel(
    const float* __restrict__ w4, const float* __restrict__ b4)
{
    const int n  = blockIdx.x;
    const int c0 = blockIdx.y * 8;

    __shared__ float sIn[48 * 64];
    __shared__ float sRed[256];

    const int tid = threadIdx.x;
    const float* src = g_c3 + (size_t)n * 3072;
    for (int idx = tid; idx < 3072; idx += 256) sIn[idx] = src[idx];
    __syncthreads();

    const int sub = tid >> 6;
    const int loc = tid & 63;
    const int c   = loc >> 3;
    const int p   = loc & 7;
    const int od = p >> 2, oh = (p >> 1) & 1, ow = p & 1;

    float acc = 0.f;
    const float* wb = w4 + (size_t)(c0 + c) * 48 * 27;
    #pragma unroll
    for (int ci = 0; ci < 12; ci++) {
        int cin = sub * 12 + ci;
        const float* s  = sIn + cin * 64;
        const float* wk = wb + cin * 27;
        #pragma unroll
        for (int kd = 0; kd < 3; kd++)
            #pragma unroll
            for (int kh = 0; kh < 3; kh++)
                #pragma unroll
                for (int kw = 0; kw < 3; kw++)
                    acc = fmaf(s[(od + kd) * 16 + (oh + kh) * 4 + (ow + kw)],
                               __ldg(wk + kd * 9 + kh * 3 + kw), acc);
    }
    sRed[tid] = acc;
    __syncthreads();
    if (sub == 0) {
        float v = sRed[loc] + sRed[loc + 64] + sRed[loc + 128] + sRed[loc + 192];
        g_feat[n * 512 + (c0 + c) * 8 + p] = leaky(v + b4[c0 + c]);
    }
}

// =======================================================================
// M = feature @ T
// =======================================================================
__global__ __launch_bounds__(256) void mmul_kernel(const float* __restrict__ T)
{
    const int i = blockIdx.x;
    __shared__ float sF[512];
    const int tid = threadIdx.x;
    for (int k = tid; k < 512; k += 256) sF[k] = g_feat[i * 512 + k];
    __syncthreads();

    float acc0 = 0.f, acc1 = 0.f, acc2 = 0.f, acc3 = 0.f;
    for (int k = 0; k < 512; k++) {
        float v = sF[k];
        const float* tr = T + (size_t)k * 1024;
        acc0 = fmaf(v, tr[tid], acc0);
        acc1 = fmaf(v, tr[tid + 256], acc1);
        acc2 = fmaf(v, tr[tid + 512], acc2);
        acc3 = fmaf(v, tr[tid + 768], acc3);
    }
    g_M[i * 1024 + tid] = acc0;
    g_M[i * 1024 + tid + 256] = acc1;
    g_M[i * 1024 + tid + 512] = acc2;
    g_M[i * 1024 + tid + 768] = acc3;
}

// =======================================================================
// out_T[i,c] = sum_j exp( sum_k |M[i,c,k]-M[j,c,k]| )
// =======================================================================
__global__ __launch_bounds__(256) void mbd_kernel()
{
    const int i = blockIdx.x;
    __shared__ float sMi[1024];
    __shared__ float sRed[256];
    const int tid = threadIdx.x;
    const int c = tid & 63;
    const int js = tid >> 6;

    for (int k = tid; k < 1024; k += 256) sMi[k] = g_M[i * 1024 + k];
    __syncthreads();

    const float4* mi4 = (const float4*)(sMi + c * 16);
    float4 a0 = mi4[0], a1 = mi4[1], a2 = mi4[2], a3 = mi4[3];

    float acc = 0.f;
    for (int j = js; j < 64; j += 4) {
        const float4* mj4 = (const float4*)(g_M + j * 1024 + c * 16);
        float4 b0 = mj4[0], b1 = mj4[1], b2 = mj4[2], b3 = mj4[3];
        float d =
            fabsf(a0.x - b0.x) + fabsf(a0.y - b0.y) + fabsf(a0.z - b0.z) + fabsf(a0.w - b0.w) +
            fabsf(a1.x - b1.x) + fabsf(a1.y - b1.y) + fabsf(a1.z - b1.z) + fabsf(a1.w - b1.w) +
            fabsf(a2.x - b2.x) + fabsf(a2.y - b2.y) + fabsf(a2.z - b2.z) + fabsf(a2.w - b2.w) +
            fabsf(a3.x - b3.x) + fabsf(a3.y - b3.y) + fabsf(a3.z - b3.z) + fabsf(a3.w - b3.w);
        acc += expf(d);
    }
    sRed[tid] = acc;
    __syncthreads();
    if (js == 0) {
        float s = sRed[c] + sRed[c + 64] + sRed[c + 128] + sRed[c + 192];
        g_outT[i * 64 + c] = s;
    }
}

// =======================================================================
// final
// =======================================================================
__global__ __launch_bounds__(64) void final_kernel(
    const float* __restrict__ Wm, const float* __restrict__ bm,
    float* __restrict__ out)
{
    const int i = threadIdx.x;
    float z = bm[0];
    const float* f = g_feat + i * 512;
    #pragma unroll 8
    for (int k = 0; k < 512; k++) z = fmaf(f[k], Wm[k], z);
    const float* t = g_outT + i * 64;
    #pragma unroll 8
    for (int c = 0; c < 64; c++) z = fmaf(t[c], Wm[512 + c], z);
    out[i] = 1.f / (1.f + expf(-z));
}

// =======================================================================
extern "C" void kernel_launch(void* const* d_in, const int* in_sizes, int n_in,
                              void* d_out, int out_size)
{
    const float* x  = (const float*)d_in[0];
    const float* w1 = (const float*)d_in[1];
    const float* b1 = (const float*)d_in[2];
    const float* w2 = (const float*)d_in[3];
    const float* b2 = (const float*)d_in[4];
    const float* w3 = (const float*)d_in[5];
    const float* b3 = (const float*)d_in[6];
    const float* w4 = (const float*)d_in[7];
    const float* b4 = (const float*)d_in[8];
    const float* T  = (const float*)d_in[9];
    const float* Wm = (const float*)d_in[10];
    const float* bm = (const float*)d_in[11];
    float* out = (float*)d_out;

    const int conv2_smem = 20240 + 32000;               // 52240 B
    const int conv3_smem = 16976 * (int)sizeof(float);  // 67904 B
    cudaFuncSetAttribute(conv2_kernel,
                         cudaFuncAttributeMaxDynamicSharedMemorySize, conv2_smem);
    cudaFuncSetAttribute(conv3_kernel,
                         cudaFuncAttributeMaxDynamicSharedMemorySize, conv3_smem);

    prep_w1f_kernel<<<4, 256>>>(w1);
    prep_w2_kernel<<<250, 256>>>(w2);
    prep_w3_kernel<<<750, 256>>>(w3);
    conv1_mma_kernel<<<dim3(22, 64), 256>>>(x, b1);
    conv2_kernel<<<dim3(28, 64), 256, conv2_smem>>>(b2);
    conv3_kernel<<<dim3(4, 64), 256, conv3_smem>>>(b3);
    conv4_kernel<<<dim3(64, 8), 256>>>(w4, b4);
    mmul_kernel<<<64, 256>>>(T);
    mbd_kernel<<<64, 256>>>();
    final_kernel<<<1, 64>>>(Wm, bm, out);
}

// round 13
// speedup vs baseline: 3.4555x; 1.7287x over previous
#include <cuda_runtime.h>
#include <cuda_bf16.h>
#include <math.h>
#include <stdint.h>

// ---------------- problem constants ----------------
#define SLOPE 0.01f

// conv1: in [64,1,92,92,92] w[16,1,6,6,6] s2 -> [64,16,44,44,44]
// conv2: in [64,16,44,44,44] w[32,16,5,5,5] s3 -> [64,32,14,14,14]
// conv3: in [64,32,14,14,14] w[48,32,5,5,5] s3 -> [64,48,4,4,4]
// conv4: in [64,48,4,4,4]  w[64,48,3,3,3] s1 -> [64,64,2,2,2]

// ---------------- scratch (static device globals; no cudaMalloc) ----------
__device__ __align__(128) __nv_bfloat16 g_c1b[64ull * 16 * 85184 + 64]; // 175 MB
__device__ __align__(128) float g_c2[64 * 32 * 14 * 14 * 14];      // 22.5 MB
__device__ __align__(128) float g_c3[64 * 48 * 64];
__device__ __align__(128) float g_feat[64 * 512];
__device__ __align__(128) float g_M[64 * 1024];
__device__ __align__(128) float g_outT[64 * 64];
__device__ __align__(128) float g_w3t[4 * 32 * 1500];    // [(g*32+cin)][tap*12+cc]
__device__ __align__(128) uint32_t g_w1f[1792];          // conv1 bf16x2 B-fragments
__device__ __align__(128) uint32_t g_w2f[32768];         // conv2 bf16x2 B-fragments (128 KB)

__device__ __forceinline__ float leaky(float v) {
    return v >= 0.f ? v : SLOPE * v;
}

__device__ __forceinline__ void cp16(void* dst, const void* src) {
    unsigned d = (unsigned)__cvta_generic_to_shared(dst);
    asm volatile("cp.async.cg.shared.global [%0], [%1], 16;" :: "r"(d), "l"(src));
}
__device__ __forceinline__ void cp8(void* dst, const void* src) {
    unsigned d = (unsigned)__cvta_generic_to_shared(dst);
    asm volatile("cp.async.ca.shared.global [%0], [%1], 8;" :: "r"(d), "l"(src));
}
#define CP_COMMIT() asm volatile("cp.async.commit_group;")
#define CP_WAIT1()  asm volatile("cp.async.wait_group 1;")
#define CP_WAIT0()  asm volatile("cp.async.wait_group 0;")

__device__ __forceinline__ uint32_t packbf(float hi, float lo) {
    uint32_t r;
    asm("cvt.rn.bf16x2.f32 %0, %1, %2;" : "=r"(r) : "f"(hi), "f"(lo));
    return r;
}
// two bf16 loads -> packed bf16x2 (lo = first)
__device__ __forceinline__ uint32_t ld2bf(const __nv_bfloat16* p, int i0, int i1) {
    uint32_t lo = *(const unsigned short*)(p + i0);
    uint32_t hi = *(const unsigned short*)(p + i1);
    return lo | (hi << 16);
}

// d += A(16x16 bf16, row) @ B(16x8 bf16, col)
__device__ __forceinline__ void mma16816(float* d,
    uint32_t a0, uint32_t a1, uint32_t a2, uint32_t a3,
    uint32_t b0, uint32_t b1) {
    asm volatile(
        "mma.sync.aligned.m16n8k16.row.col.f32.bf16.bf16.f32 "
        "{%0,%1,%2,%3}, {%4,%5,%6,%7}, {%8,%9}, {%0,%1,%2,%3};"
        : "+f"(d[0]), "+f"(d[1]), "+f"(d[2]), "+f"(d[3])
        : "r"(a0), "r"(a1), "r"(a2), "r"(a3), "r"(b0), "r"(b1));
}

// =======================================================================
// prep_w1f: conv1 B-fragments (zero for k>=216)
// =======================================================================
__global__ __launch_bounds__(256) void prep_w1f_kernel(const float* __restrict__ w1)
{
    int idx = blockIdx.x * 256 + threadIdx.x;
    if (idx >= 896) return;
    int lane = idx & 31;
    int nt = (idx >> 5) & 1;
    int chunk = idx >> 6;
    int g = lane >> 2, c = lane & 3;
    int n = nt * 8 + g;
    int k0 = chunk * 16 + 2 * c;
    int k2 = k0 + 8;
    float v00 = (k0     < 216) ? w1[n * 216 + k0]     : 0.f;
    float v01 = (k0 + 1 < 216) ? w1[n * 216 + k0 + 1] : 0.f;
    float v10 = (k2     < 216) ? w1[n * 216 + k2]     : 0.f;
    float v11 = (k2 + 1 < 216) ? w1[n * 216 + k2 + 1] : 0.f;
    g_w1f[idx * 2]     = packbf(v01, v00);
    g_w1f[idx * 2 + 1] = packbf(v11, v10);
}

// =======================================================================
// prep_w2f: conv2 B-fragments. idx = ((cin*8+ch)*4+nt)*32+lane.
// K per cin = 125 taps padded to 128 (zeros).
// =======================================================================
__global__ __launch_bounds__(256) void prep_w2f_kernel(const float* __restrict__ w2)
{
    int idx = blockIdx.x * 256 + threadIdx.x;
    if (idx >= 16384) return;
    int lane = idx & 31;
    int nt = (idx >> 5) & 3;
    int ch = (idx >> 7) & 7;
    int cin = idx >> 10;
    int g = lane >> 2, c = lane & 3;
    int n = nt * 8 + g;
    int k0 = ch * 16 + 2 * c;
    int k2 = k0 + 8;
    const float* wb = w2 + (size_t)(n * 16 + cin) * 125;
    float v00 = (k0     < 125) ? wb[k0]     : 0.f;
    float v01 = (k0 + 1 < 125) ? wb[k0 + 1] : 0.f;
    float v10 = (k2     < 125) ? wb[k2]     : 0.f;
    float v11 = (k2 + 1 < 125) ? wb[k2 + 1] : 0.f;
    g_w2f[idx * 2]     = packbf(v01, v00);
    g_w2f[idx * 2 + 1] = packbf(v11, v10);
}

// =======================================================================
// conv1 via mma.sync bf16 (paired gather), bf16 output
// =======================================================================
__global__ __launch_bounds__(256) void conv1_mma_kernel(
    const float* __restrict__ x, const float* __restrict__ b1)
{
    __shared__ int      sGoffE[112];
    __shared__ uint32_t sBfrag[1792];
    __shared__ float    sWin[8832];    // [8 d][12 h][92 w]

    const int bx = blockIdx.x;
    const int n  = blockIdx.y;
    const int tid = threadIdx.x;
    const int wid = tid >> 5, lane = tid & 31;
    const int g = lane >> 2, c4 = lane & 3;

    if (tid < 112) {
        int k = 2 * tid, o = 0;
        if (k < 216) {
            int kd = k / 36, r = k % 36;
            o = kd * 1104 + (r / 6) * 92 + (r % 6);
        }
        sGoffE[tid] = o;
    }
    for (int f = tid; f < 448; f += 256)
        cp16(sBfrag + f * 4, g_w1f + f * 4);
    CP_COMMIT();

    const float bv00 = __ldg(b1 + 2 * c4),     bv01 = __ldg(b1 + 2 * c4 + 1);
    const float bv10 = __ldg(b1 + 2 * c4 + 8), bv11 = __ldg(b1 + 2 * c4 + 9);

    const float* xb = x + (size_t)n * 778688 + (size_t)(4 * bx) * 8464;
    const size_t nBase = (size_t)(n * 16) * 85184;

    for (int grp = 0; grp < 11; grp++) {
        const float* xs = xb + (8 * grp) * 92;
        for (int f = tid; f < 2208; f += 256) {
            int row = f / 23, q = f - row * 23;
            int ld = row / 12, lh = row - ld * 12;
            cp16(sWin + row * 92 + q * 4, xs + (size_t)ld * 8464 + lh * 92 + q * 4);
        }
        CP_COMMIT(); CP_WAIT0();
        __syncthreads();

        for (int tt = wid; tt < 22; tt += 8) {
            const int pr0 = tt * 16 + g, pr1 = pr0 + 8;
            int odl0 = pr0 / 176, r0 = pr0 % 176, ohr0 = r0 / 44, ow0 = r0 % 44;
            int odl1 = pr1 / 176, r1 = pr1 % 176, ohr1 = r1 / 44, ow1 = r1 % 44;
            const int wb0 = odl0 * 2208 + ohr0 * 184 + 2 * ow0;
            const int wb1 = odl1 * 2208 + ohr1 * 184 + 2 * ow1;

            float d[8];
            #pragma unroll
            for (int i = 0; i < 8; i++) d[i] = 0.f;

            #pragma unroll
            for (int ch = 0; ch < 14; ch++) {
                int o0 = sGoffE[8 * ch + c4];
                int o2 = sGoffE[8 * ch + c4 + 4];
                float2 p00 = *(const float2*)(sWin + wb0 + o0);
                float2 p10 = *(const float2*)(sWin + wb1 + o0);
                float2 p02 = *(const float2*)(sWin + wb0 + o2);
                float2 p12 = *(const float2*)(sWin + wb1 + o2);
                uint32_t a0 = packbf(p00.y, p00.x);
                uint32_t a1 = packbf(p10.y, p10.x);
                uint32_t a2 = packbf(p02.y, p02.x);
                uint32_t a3 = packbf(p12.y, p12.x);
                uint2 bb0 = *(const uint2*)&sBfrag[(ch * 2 + 0) * 64 + lane * 2];
                uint2 bb1 = *(const uint2*)&sBfrag[(ch * 2 + 1) * 64 + lane * 2];
                mma16816(d,     a0, a1, a2, a3, bb0.x, bb0.y);
                mma16816(d + 4, a0, a1, a2, a3, bb1.x, bb1.y);
            }

            size_t ob0 = nBase + (size_t)(2 * bx + odl0) * 1936
                       + (4 * grp + ohr0) * 44 + ow0;
            size_t ob1 = nBase + (size_t)(2 * bx + odl1) * 1936
                       + (4 * grp + ohr1) * 44 + ow1;
            const int co = 2 * c4;
            g_c1b[ob0 + (size_t)(co)     * 85184] = __float2bfloat16(leaky(d[0] + bv00));
            g_c1b[ob0 + (size_t)(co + 1) * 85184] = __float2bfloat16(leaky(d[1] + bv01));
            g_c1b[ob1 + (size_t)(co)     * 85184] = __float2bfloat16(leaky(d[2] + bv00));
            g_c1b[ob1 + (size_t)(co + 1) * 85184] = __float2bfloat16(leaky(d[3] + bv01));
            g_c1b[ob0 + (size_t)(co + 8) * 85184] = __float2bfloat16(leaky(d[4] + bv10));
            g_c1b[ob0 + (size_t)(co + 9) * 85184] = __float2bfloat16(leaky(d[5] + bv11));
            g_c1b[ob1 + (size_t)(co + 8) * 85184] = __float2bfloat16(leaky(d[6] + bv10));
            g_c1b[ob1 + (size_t)(co + 9) * 85184] = __float2bfloat16(leaky(d[7] + bv11));
        }
        __syncthreads();
    }
}

// =======================================================================
// conv2 via mma.sync bf16: block = (od, n). 196 positions = 13 m16-tiles.
// K = 16 cin x 128 (125 taps zero-padded). Double-buffered cp.async.
// smem: goff 512 + sW 2x8192 + sIn 2x19360 = 55616 B
// =======================================================================
__global__ __launch_bounds__(256) void conv2_mma_kernel(const float* __restrict__ b2)
{
    extern __shared__ char smemc[];
    int*            sGoff2 = (int*)smemc;                       // 128
    uint32_t*       sWf = (uint32_t*)(smemc + 512);             // 2 x 2048
    __nv_bfloat16*  sIn = (__nv_bfloat16*)(smemc + 16896);      // 2 x 9680

    const int od = blockIdx.x;
    const int n  = blockIdx.y;
    const int tid = threadIdx.x;
    const int wid = tid >> 5, lane = tid & 31;
    const int g = lane >> 2, c4 = lane & 3;

    if (tid < 128) {
        int tap = tid, o = 0;
        if (tap < 125) {
            int kd = tap / 25, r = tap % 25;
            o = kd * 1936 + (r / 5) * 44 + (r % 5);
        }
        sGoff2[tid] = o;
    }

    auto issue = [&](int cin) {
        int buf = cin & 1;
        const __nv_bfloat16* srcI =
            g_c1b + (size_t)(n * 16 + cin) * 85184 + (size_t)(3 * od) * 1936;
        __nv_bfloat16* dI = sIn + buf * 9680;
        for (int f = tid; f < 2420; f += 256)
            cp8(dI + f * 4, srcI + f * 4);
        const uint32_t* srcW = g_w2f + cin * 2048;
        uint32_t* dW = sWf + buf * 2048;
        for (int f = tid; f < 512; f += 256)
            cp16(dW + f * 4, srcW + f * 4);
    };

    float acc[2][16];
    #pragma unroll
    for (int t = 0; t < 2; t++)
        #pragma unroll
        for (int i = 0; i < 16; i++) acc[t][i] = 0.f;

    issue(0);
    CP_COMMIT();

    for (int cin = 0; cin < 16; cin++) {
        if (cin < 15) {
            issue(cin + 1);
            CP_COMMIT();
            CP_WAIT1();
        } else {
            CP_WAIT0();
        }
        __syncthreads();

        const int buf = cin & 1;
        const __nv_bfloat16* In = sIn + buf * 9680;
        const uint32_t* Wf = sWf + buf * 2048;

        #pragma unroll
        for (int ti = 0; ti < 2; ti++) {
            const int tile = wid + ti * 8;
            if (tile >= 13) break;
            const int pr0 = tile * 16 + g, pr1 = pr0 + 8;
            const int p0 = pr0 < 196 ? pr0 : 195;
            const int p1 = pr1 < 196 ? pr1 : 195;
            const int b0 = (p0 / 14) * 132 + (p0 % 14) * 3;
            const int b1 = (p1 / 14) * 132 + (p1 % 14) * 3;

            #pragma unroll
            for (int ch = 0; ch < 8; ch++) {
                const int kb = ch * 16;
                int o0 = sGoff2[kb + 2 * c4],     o1 = sGoff2[kb + 2 * c4 + 1];
                int o2 = sGoff2[kb + 2 * c4 + 8], o3 = sGoff2[kb + 2 * c4 + 9];
                uint32_t a0 = ld2bf(In, b0 + o0, b0 + o1);
                uint32_t a1 = ld2bf(In, b1 + o0, b1 + o1);
                uint32_t a2 = ld2bf(In, b0 + o2, b0 + o3);
                uint32_t a3 = ld2bf(In, b1 + o2, b1 + o3);
                #pragma unroll
                for (int nt = 0; nt < 4; nt++) {
                    uint2 bb = *(const uint2*)&Wf[((ch * 4 + nt) * 32 + lane) * 2];
                    mma16816(acc[ti] + nt * 4, a0, a1, a2, a3, bb.x, bb.y);
                }
            }
        }
        __syncthreads();
    }

    // epilogue: bias + leaky + store fp32
    #pragma unroll
    for (int ti = 0; ti < 2; ti++) {
        const int tile = wid + ti * 8;
        if (tile >= 13) break;
        const int pr0 = tile * 16 + g, pr1 = pr0 + 8;
        #pragma unroll
        for (int nt = 0; nt < 4; nt++) {
            const int c0 = nt * 8 + 2 * c4;
            const float bb0 = __ldg(b2 + c0), bb1 = __ldg(b2 + c0 + 1);
            if (pr0 < 196) {
                size_t o = (size_t)(n * 32 + c0) * 2744 + od * 196 + pr0;
                g_c2[o]        = leaky(acc[ti][nt * 4 + 0] + bb0);
                g_c2[o + 2744] = leaky(acc[ti][nt * 4 + 1] + bb1);
            }
            if (pr1 < 196) {
                size_t o = (size_t)(n * 32 + c0) * 2744 + od * 196 + pr1;
                g_c2[o]        = leaky(acc[ti][nt * 4 + 2] + bb0);
                g_c2[o + 2744] = leaky(acc[ti][nt * 4 + 3] + bb1);
            }
        }
    }
}

// =======================================================================
// prep_w3
// =======================================================================
__global__ __launch_bounds__(256) void prep_w3_kernel(const float* __restrict__ w3)
{
    int idx = blockIdx.x * 256 + threadIdx.x;
    if (idx >= 192000) return;
    int gcin = idx / 1500;
    int r    = idx % 1500;
    int tap = r / 12, cc = r % 12;
    int g = gcin / 32, cin = gcin % 32;
    g_w3t[idx] = w3[((g * 12 + cc) * 32 + cin) * 125 + tap];
}

// =======================================================================
// conv3: grid(4, 64); block 256 = pos(64) x cin-quarter(4)
// =======================================================================
__global__ __launch_bounds__(256) void conv3_kernel(const float* __restrict__ b3)
{
    extern __shared__ float smemf[];

    const int g = blockIdx.x;
    const int n = blockIdx.y;
    const int tid = threadIdx.x;
    const int pos = tid & 63;
    const int sub = tid >> 6;
    const int od = pos >> 4, oh = (pos >> 2) & 3, ow = pos & 3;

    float* myIn = smemf + sub * 2744;
    const float4* sW4 = (const float4*)(smemf + 10976 + sub * 1500);

    float acc[12];
    #pragma unroll
    for (int c = 0; c < 12; c++) acc[c] = 0.f;

    for (int ci = 0; ci < 8; ci++) {
        const int cin = sub * 8 + ci;
        {
            const float* sI = g_c2 + (size_t)(n * 32 + cin) * 2744;
            for (int f = pos; f < 686; f += 64) cp16(myIn + f * 4, sI + f * 4);
            float* dW = smemf + 10976 + sub * 1500;
            const float* sWsrc = g_w3t + (size_t)(g * 32 + cin) * 1500;
            for (int f = pos; f < 375; f += 64) cp16(dW + f * 4, sWsrc + f * 4);
        }
        CP_COMMIT();
        CP_WAIT0();
        __syncthreads();

        #pragma unroll 1
        for (int kd = 0; kd < 5; kd++) {
            const float* sr = myIn + (3 * od + kd) * 196 + 3 * oh * 14 + 3 * ow;
            #pragma unroll
            for (int kh = 0; kh < 5; kh++) {
                #pragma unroll
                for (int kw = 0; kw < 5; kw++) {
                    float v = sr[kh * 14 + kw];
                    const int tap = (kd * 5 + kh) * 5 + kw;
                    #pragma unroll
                    for (int q = 0; q < 3; q++) {
                        float4 w = sW4[tap * 3 + q];
                        acc[q * 4 + 0] = fmaf(v, w.x, acc[q * 4 + 0]);
                        acc[q * 4 + 1] = fmaf(v, w.y, acc[q * 4 + 1]);
                        acc[q * 4 + 2] = fmaf(v, w.z, acc[q * 4 + 2]);
                        acc[q * 4 + 3] = fmaf(v, w.w, acc[q * 4 + 3]);
                    }
                }
            }
        }
        __syncthreads();
    }

    float* sStage = smemf;
    #pragma unroll
    for (int c = 0; c < 12; c++) sStage[tid * 12 + c] = acc[c];
    __syncthreads();
    if (sub == 0) {
        #pragma unroll
        for (int c = 0; c < 12; c++) {
            float s = sStage[pos * 12 + c] + sStage[(64 + pos) * 12 + c]
                    + sStage[(128 + pos) * 12 + c] + sStage[(192 + pos) * 12 + c];
            g_c3[(size_t)(n * 48 + g * 12 + c) * 64 + pos] = leaky(s + b3[g * 12 + c]);
        }
    }
}

// =======================================================================
// conv4 + feature
// =======================================================================
__global__ __launch_bounds__(256) void conv4_kernel(
    const float* __restrict__ w4, const float* __restrict__ b4)
{
    const int n  = blockIdx.x;
    const int c0 = blockIdx.y * 8;

    __shared__ float sIn[48 * 64];
    __shared__ float sRed[256];

    const int tid = threadIdx.x;
    const float* src = g_c3 + (size_t)n * 3072;
    for (int idx = tid; idx < 3072; idx += 256) sIn[idx] = src[idx];
    __syncthreads();

    const int sub = tid >> 6;
    const int loc = tid & 63;
    const int c   = loc >> 3;
    const int p   = loc & 7;
    const int od = p >> 2, oh = (p >> 1) & 1, ow = p & 1;

    float acc = 0.f;
    const float* wb = w4 + (size_t)(c0 + c) * 48 * 27;
    #pragma unroll
    for (int ci = 0; ci < 12; ci++) {
        int cin = sub * 12 + ci;
        const float* s  = sIn + cin * 64;
        const float* wk = wb + cin * 27;
        #pragma unroll
        for (int kd = 0; kd < 3; kd++)
            #pragma unroll
            for (int kh = 0; kh < 3; kh++)
                #pragma unroll
                for (int kw = 0; kw < 3; kw++)
                    acc = fmaf(s[(od + kd) * 16 + (oh + kh) * 4 + (ow + kw)],
                               __ldg(wk + kd * 9 + kh * 3 + kw), acc);
    }
    sRed[tid] = acc;
    __syncthreads();
    if (sub == 0) {
        float v = sRed[loc] + sRed[loc + 64] + sRed[loc + 128] + sRed[loc + 192];
        g_feat[n * 512 + (c0 + c) * 8 + p] = leaky(v + b4[c0 + c]);
    }
}

// =======================================================================
// M = feature @ T
// =======================================================================
__global__ __launch_bounds__(256) void mmul_kernel(const float* __restrict__ T)
{
    const int i = blockIdx.x;
    __shared__ float sF[512];
    const int tid = threadIdx.x;
    for (int k = tid; k < 512; k += 256) sF[k] = g_feat[i * 512 + k];
    __syncthreads();

    float acc0 = 0.f, acc1 = 0.f, acc2 = 0.f, acc3 = 0.f;
    for (int k = 0; k < 512; k++) {
        float v = sF[k];
        const float* tr = T + (size_t)k * 1024;
        acc0 = fmaf(v, tr[tid], acc0);
        acc1 = fmaf(v, tr[tid + 256], acc1);
        acc2 = fmaf(v, tr[tid + 512], acc2);
        acc3 = fmaf(v, tr[tid + 768], acc3);
    }
    g_M[i * 1024 + tid] = acc0;
    g_M[i * 1024 + tid + 256] = acc1;
    g_M[i * 1024 + tid + 512] = acc2;
    g_M[i * 1024 + tid + 768] = acc3;
}

// =======================================================================
// out_T[i,c] = sum_j exp( sum_k |M[i,c,k]-M[j,c,k]| )
// =======================================================================
__global__ __launch_bounds__(256) void mbd_kernel()
{
    const int i = blockIdx.x;
    __shared__ float sMi[1024];
    __shared__ float sRed[256];
    const int tid = threadIdx.x;
    const int c = tid & 63;
    const int js = tid >> 6;

    for (int k = tid; k < 1024; k += 256) sMi[k] = g_M[i * 1024 + k];
    __syncthreads();

    const float4* mi4 = (const float4*)(sMi + c * 16);
    float4 a0 = mi4[0], a1 = mi4[1], a2 = mi4[2], a3 = mi4[3];

    float acc = 0.f;
    for (int j = js; j < 64; j += 4) {
        const float4* mj4 = (const float4*)(g_M + j * 1024 + c * 16);
        float4 b0 = mj4[0], b1 = mj4[1], b2 = mj4[2], b3 = mj4[3];
        float d =
            fabsf(a0.x - b0.x) + fabsf(a0.y - b0.y) + fabsf(a0.z - b0.z) + fabsf(a0.w - b0.w) +
            fabsf(a1.x - b1.x) + fabsf(a1.y - b1.y) + fabsf(a1.z - b1.z) + fabsf(a1.w - b1.w) +
            fabsf(a2.x - b2.x) + fabsf(a2.y - b2.y) + fabsf(a2.z - b2.z) + fabsf(a2.w - b2.w) +
            fabsf(a3.x - b3.x) + fabsf(a3.y - b3.y) + fabsf(a3.z - b3.z) + fabsf(a3.w - b3.w);
        acc += expf(d);
    }
    sRed[tid] = acc;
    __syncthreads();
    if (js == 0) {
        float s = sRed[c] + sRed[c + 64] + sRed[c + 128] + sRed[c + 192];
        g_outT[i * 64 + c] = s;
    }
}

// =======================================================================
// final
// =======================================================================
__global__ __launch_bounds__(64) void final_kernel(
    const float* __restrict__ Wm, const float* __restrict__ bm,
    float* __restrict__ out)
{
    const int i = threadIdx.x;
    float z = bm[0];
    const float* f = g_feat + i * 512;
    #pragma unroll 8
    for (int k = 0; k < 512; k++) z = fmaf(f[k], Wm[k], z);
    const float* t = g_outT + i * 64;
    #pragma unroll 8
    for (int c = 0; c < 64; c++) z = fmaf(t[c], Wm[512 + c], z);
    out[i] = 1.f / (1.f + expf(-z));
}

// =======================================================================
extern "C" void kernel_launch(void* const* d_in, const int* in_sizes, int n_in,
                              void* d_out, int out_size)
{
    const float* x  = (const float*)d_in[0];
    const float* w1 = (const float*)d_in[1];
    const float* b1 = (const float*)d_in[2];
    const float* w2 = (const float*)d_in[3];
    const float* b2 = (const float*)d_in[4];
    const float* w3 = (const float*)d_in[5];
    const float* b3 = (const float*)d_in[6];
    const float* w4 = (const float*)d_in[7];
    const float* b4 = (const float*)d_in[8];
    const float* T  = (const float*)d_in[9];
    const float* Wm = (const float*)d_in[10];
    const float* bm = (const float*)d_in[11];
    float* out = (float*)d_out;

    const int conv2_smem = 16896 + 2 * 19360;           // 55616 B
    const int conv3_smem = 16976 * (int)sizeof(float);  // 67904 B
    cudaFuncSetAttribute(conv2_mma_kernel,
                         cudaFuncAttributeMaxDynamicSharedMemorySize, conv2_smem);
    cudaFuncSetAttribute(conv3_kernel,
                         cudaFuncAttributeMaxDynamicSharedMemorySize, conv3_smem);

    prep_w1f_kernel<<<4, 256>>>(w1);
    prep_w2f_kernel<<<64, 256>>>(w2);
    prep_w3_kernel<<<750, 256>>>(w3);
    conv1_mma_kernel<<<dim3(22, 64), 256>>>(x, b1);
    conv2_mma_kernel<<<dim3(14, 64), 256, conv2_smem>>>(b2);
    conv3_kernel<<<dim3(4, 64), 256, conv3_smem>>>(b3);
    conv4_kernel<<<dim3(64, 8), 256>>>(w4, b4);
    mmul_kernel<<<64, 256>>>(T);
    mbd_kernel<<<64, 256>>>();
    final_kernel<<<1, 64>>>(Wm, bm, out);
}

// round 14
// speedup vs baseline: 4.1981x; 1.2149x over previous
#include <cuda_runtime.h>
#include <cuda_bf16.h>
#include <math.h>
#include <stdint.h>

// ---------------- problem constants ----------------
#define SLOPE 0.01f

// conv1: in [64,1,92,92,92] w[16,1,6,6,6] s2 -> [64,16,44,44,44]
// conv2: in [64,16,44,44,44] w[32,16,5,5,5] s3 -> [64,32,14,14,14]
// conv3: in [64,32,14,14,14] w[48,32,5,5,5] s3 -> [64,48,4,4,4]
// conv4: in [64,48,4,4,4]  w[64,48,3,3,3] s1 -> [64,64,2,2,2]

// ---------------- scratch (static device globals; no cudaMalloc) ----------
__device__ __align__(128) __nv_bfloat16 g_xb[64ull * 778688];           // 100 MB
__device__ __align__(128) __nv_bfloat16 g_c1b[64ull * 16 * 85184 + 64]; // 175 MB
__device__ __align__(128) float g_c2[64 * 32 * 14 * 14 * 14];      // 22.5 MB
__device__ __align__(128) float g_c3[64 * 48 * 64];
__device__ __align__(128) float g_feat[64 * 512];
__device__ __align__(128) float g_M[64 * 1024];
__device__ __align__(128) float g_outT[64 * 64];
__device__ __align__(128) float g_w3t[4 * 32 * 1500];    // [(g*32+cin)][tap*12+cc]
__device__ __align__(128) uint32_t g_w1f[1792];          // conv1 bf16x2 B-fragments
__device__ __align__(128) uint32_t g_w2f[32768];         // conv2 bf16x2 B-fragments

__device__ __forceinline__ float leaky(float v) {
    return v >= 0.f ? v : SLOPE * v;
}

__device__ __forceinline__ void cp16(void* dst, const void* src) {
    unsigned d = (unsigned)__cvta_generic_to_shared(dst);
    asm volatile("cp.async.cg.shared.global [%0], [%1], 16;" :: "r"(d), "l"(src));
}
__device__ __forceinline__ void cp8(void* dst, const void* src) {
    unsigned d = (unsigned)__cvta_generic_to_shared(dst);
    asm volatile("cp.async.ca.shared.global [%0], [%1], 8;" :: "r"(d), "l"(src));
}
#define CP_COMMIT() asm volatile("cp.async.commit_group;")
#define CP_WAIT1()  asm volatile("cp.async.wait_group 1;")
#define CP_WAIT0()  asm volatile("cp.async.wait_group 0;")

__device__ __forceinline__ uint32_t packbf(float hi, float lo) {
    uint32_t r;
    asm("cvt.rn.bf16x2.f32 %0, %1, %2;" : "=r"(r) : "f"(hi), "f"(lo));
    return r;
}
__device__ __forceinline__ uint32_t ld2bf(const __nv_bfloat16* p, int i0, int i1) {
    uint32_t lo = *(const unsigned short*)(p + i0);
    uint32_t hi = *(const unsigned short*)(p + i1);
    return lo | (hi << 16);
}

// d += A(16x16 bf16, row) @ B(16x8 bf16, col)
__device__ __forceinline__ void mma16816(float* d,
    uint32_t a0, uint32_t a1, uint32_t a2, uint32_t a3,
    uint32_t b0, uint32_t b1) {
    asm volatile(
        "mma.sync.aligned.m16n8k16.row.col.f32.bf16.bf16.f32 "
        "{%0,%1,%2,%3}, {%4,%5,%6,%7}, {%8,%9}, {%0,%1,%2,%3};"
        : "+f"(d[0]), "+f"(d[1]), "+f"(d[2]), "+f"(d[3])
        : "r"(a0), "r"(a1), "r"(a2), "r"(a3), "r"(b0), "r"(b1));
}

// =======================================================================
// prep_xb: x fp32 -> bf16 (12,459,008 float4 -> uint2)
// =======================================================================
__global__ __launch_bounds__(256) void prep_xb_kernel(const float* __restrict__ x)
{
    size_t idx = (size_t)blockIdx.x * 256 + threadIdx.x;
    if (idx >= 12459008ull) return;
    float4 v = ((const float4*)x)[idx];
    uint2 o;
    o.x = packbf(v.y, v.x);
    o.y = packbf(v.w, v.z);
    ((uint2*)g_xb)[idx] = o;
}

// =======================================================================
// prep_w1f: conv1 B-fragments (zero for k>=216)
// =======================================================================
__global__ __launch_bounds__(256) void prep_w1f_kernel(const float* __restrict__ w1)
{
    int idx = blockIdx.x * 256 + threadIdx.x;
    if (idx >= 896) return;
    int lane = idx & 31;
    int nt = (idx >> 5) & 1;
    int chunk = idx >> 6;
    int g = lane >> 2, c = lane & 3;
    int n = nt * 8 + g;
    int k0 = chunk * 16 + 2 * c;
    int k2 = k0 + 8;
    float v00 = (k0     < 216) ? w1[n * 216 + k0]     : 0.f;
    float v01 = (k0 + 1 < 216) ? w1[n * 216 + k0 + 1] : 0.f;
    float v10 = (k2     < 216) ? w1[n * 216 + k2]     : 0.f;
    float v11 = (k2 + 1 < 216) ? w1[n * 216 + k2 + 1] : 0.f;
    g_w1f[idx * 2]     = packbf(v01, v00);
    g_w1f[idx * 2 + 1] = packbf(v11, v10);
}

// =======================================================================
// prep_w2f: conv2 B-fragments (125 taps padded to 128)
// =======================================================================
__global__ __launch_bounds__(256) void prep_w2f_kernel(const float* __restrict__ w2)
{
    int idx = blockIdx.x * 256 + threadIdx.x;
    if (idx >= 16384) return;
    int lane = idx & 31;
    int nt = (idx >> 5) & 3;
    int ch = (idx >> 7) & 7;
    int cin = idx >> 10;
    int g = lane >> 2, c = lane & 3;
    int n = nt * 8 + g;
    int k0 = ch * 16 + 2 * c;
    int k2 = k0 + 8;
    const float* wb = w2 + (size_t)(n * 16 + cin) * 125;
    float v00 = (k0     < 125) ? wb[k0]     : 0.f;
    float v01 = (k0 + 1 < 125) ? wb[k0 + 1] : 0.f;
    float v10 = (k2     < 125) ? wb[k2]     : 0.f;
    float v11 = (k2 + 1 < 125) ? wb[k2 + 1] : 0.f;
    g_w2f[idx * 2]     = packbf(v01, v00);
    g_w2f[idx * 2 + 1] = packbf(v11, v10);
}

// =======================================================================
// conv1 via mma.sync bf16, bf16 window (double-buffered), aligned u32 gather
// =======================================================================
__global__ __launch_bounds__(256) void conv1_mma_kernel(const float* __restrict__ b1)
{
    __shared__ uint32_t sGoffP[56];              // (o_even | o_even+8k << 16)
    __shared__ uint32_t sBfrag[1792];
    __shared__ __nv_bfloat16 sWinB[2][8832];     // [8 d][12 h][92 w] bf16

    const int bx = blockIdx.x;                   // od pair
    const int n  = blockIdx.y;
    const int tid = threadIdx.x;
    const int wid = tid >> 5, lane = tid & 31;
    const int g = lane >> 2, c4 = lane & 3;

    if (tid < 56) {
        int ch = tid >> 2, cc = tid & 3;
        int kb = ch * 16;
        auto off = [](int k) -> int {
            if (k >= 216) return 0;
            int kd = k / 36, r = k % 36;
            return kd * 1104 + (r / 6) * 92 + (r % 6);
        };
        uint32_t o0 = (uint32_t)off(kb + 2 * cc);
        uint32_t o2 = (uint32_t)off(kb + 2 * cc + 8);
        sGoffP[tid] = o0 | (o2 << 16);
    }
    for (int f = tid; f < 448; f += 256)
        cp16(sBfrag + f * 4, g_w1f + f * 4);

    const float bv00 = __ldg(b1 + 2 * c4),     bv01 = __ldg(b1 + 2 * c4 + 1);
    const float bv10 = __ldg(b1 + 2 * c4 + 8), bv11 = __ldg(b1 + 2 * c4 + 9);

    const __nv_bfloat16* xb = g_xb + (size_t)n * 778688 + (size_t)(4 * bx) * 8464;
    const size_t nBase = (size_t)(n * 16) * 85184;

    auto issue = [&](int grp) {
        __nv_bfloat16* dst = sWinB[grp & 1];
        const __nv_bfloat16* xs = xb + (8 * grp) * 92;
        for (int f = tid; f < 2208; f += 256) {
            int row = f / 23, q = f - row * 23;
            int ld = row / 12, lh = row - ld * 12;
            cp8(dst + row * 92 + q * 4, xs + (size_t)ld * 8464 + lh * 92 + q * 4);
        }
    };

    issue(0);
    CP_COMMIT();

    for (int grp = 0; grp < 11; grp++) {
        if (grp < 10) {
            issue(grp + 1);
            CP_COMMIT();
            CP_WAIT1();
        } else {
            CP_WAIT0();
        }
        __syncthreads();
        const __nv_bfloat16* Win = sWinB[grp & 1];

        for (int tt = wid; tt < 22; tt += 8) {
            const int pr0 = tt * 16 + g, pr1 = pr0 + 8;
            int odl0 = pr0 / 176, r0 = pr0 % 176, ohr0 = r0 / 44, ow0 = r0 % 44;
            int odl1 = pr1 / 176, r1 = pr1 % 176, ohr1 = r1 / 44, ow1 = r1 % 44;
            const int wb0 = odl0 * 2208 + ohr0 * 184 + 2 * ow0;
            const int wb1 = odl1 * 2208 + ohr1 * 184 + 2 * ow1;

            float d[8];
            #pragma unroll
            for (int i = 0; i < 8; i++) d[i] = 0.f;

            #pragma unroll
            for (int ch = 0; ch < 14; ch++) {
                uint32_t op = sGoffP[ch * 4 + c4];
                int o0 = (int)(op & 0xFFFFu);
                int o2 = (int)(op >> 16);
                uint32_t a0 = *(const uint32_t*)(Win + wb0 + o0);
                uint32_t a1 = *(const uint32_t*)(Win + wb1 + o0);
                uint32_t a2 = *(const uint32_t*)(Win + wb0 + o2);
                uint32_t a3 = *(const uint32_t*)(Win + wb1 + o2);
                uint2 bb0 = *(const uint2*)&sBfrag[(ch * 2 + 0) * 64 + lane * 2];
                uint2 bb1 = *(const uint2*)&sBfrag[(ch * 2 + 1) * 64 + lane * 2];
                mma16816(d,     a0, a1, a2, a3, bb0.x, bb0.y);
                mma16816(d + 4, a0, a1, a2, a3, bb1.x, bb1.y);
            }

            size_t ob0 = nBase + (size_t)(2 * bx + odl0) * 1936
                       + (4 * grp + ohr0) * 44 + ow0;
            size_t ob1 = nBase + (size_t)(2 * bx + odl1) * 1936
                       + (4 * grp + ohr1) * 44 + ow1;
            const int co = 2 * c4;
            g_c1b[ob0 + (size_t)(co)     * 85184] = __float2bfloat16(leaky(d[0] + bv00));
            g_c1b[ob0 + (size_t)(co + 1) * 85184] = __float2bfloat16(leaky(d[1] + bv01));
            g_c1b[ob1 + (size_t)(co)     * 85184] = __float2bfloat16(leaky(d[2] + bv00));
            g_c1b[ob1 + (size_t)(co + 1) * 85184] = __float2bfloat16(leaky(d[3] + bv01));
            g_c1b[ob0 + (size_t)(co + 8) * 85184] = __float2bfloat16(leaky(d[4] + bv10));
            g_c1b[ob0 + (size_t)(co + 9) * 85184] = __float2bfloat16(leaky(d[5] + bv11));
            g_c1b[ob1 + (size_t)(co + 8) * 85184] = __float2bfloat16(leaky(d[6] + bv10));
            g_c1b[ob1 + (size_t)(co + 9) * 85184] = __float2bfloat16(leaky(d[7] + bv11));
        }
        __syncthreads();
    }
}

// =======================================================================
// conv2 via mma.sync bf16 (unchanged from R13)
// =======================================================================
__global__ __launch_bounds__(256) void conv2_mma_kernel(const float* __restrict__ b2)
{
    extern __shared__ char smemc[];
    int*            sGoff2 = (int*)smemc;                       // 128
    uint32_t*       sWf = (uint32_t*)(smemc + 512);             // 2 x 2048
    __nv_bfloat16*  sIn = (__nv_bfloat16*)(smemc + 16896);      // 2 x 9680

    const int od = blockIdx.x;
    const int n  = blockIdx.y;
    const int tid = threadIdx.x;
    const int wid = tid >> 5, lane = tid & 31;
    const int g = lane >> 2, c4 = lane & 3;

    if (tid < 128) {
        int tap = tid, o = 0;
        if (tap < 125) {
            int kd = tap / 25, r = tap % 25;
            o = kd * 1936 + (r / 5) * 44 + (r % 5);
        }
        sGoff2[tid] = o;
    }

    auto issue = [&](int cin) {
        int buf = cin & 1;
        const __nv_bfloat16* srcI =
            g_c1b + (size_t)(n * 16 + cin) * 85184 + (size_t)(3 * od) * 1936;
        __nv_bfloat16* dI = sIn + buf * 9680;
        for (int f = tid; f < 2420; f += 256)
            cp8(dI + f * 4, srcI + f * 4);
        const uint32_t* srcW = g_w2f + cin * 2048;
        uint32_t* dW = sWf + buf * 2048;
        for (int f = tid; f < 512; f += 256)
            cp16(dW + f * 4, srcW + f * 4);
    };

    float acc[2][16];
    #pragma unroll
    for (int t = 0; t < 2; t++)
        #pragma unroll
        for (int i = 0; i < 16; i++) acc[t][i] = 0.f;

    issue(0);
    CP_COMMIT();

    for (int cin = 0; cin < 16; cin++) {
        if (cin < 15) {
            issue(cin + 1);
            CP_COMMIT();
            CP_WAIT1();
        } else {
            CP_WAIT0();
        }
        __syncthreads();

        const int buf = cin & 1;
        const __nv_bfloat16* In = sIn + buf * 9680;
        const uint32_t* Wf = sWf + buf * 2048;

        #pragma unroll
        for (int ti = 0; ti < 2; ti++) {
            const int tile = wid + ti * 8;
            if (tile >= 13) break;
            const int pr0 = tile * 16 + g, pr1 = pr0 + 8;
            const int p0 = pr0 < 196 ? pr0 : 195;
            const int p1 = pr1 < 196 ? pr1 : 195;
            const int b0 = (p0 / 14) * 132 + (p0 % 14) * 3;
            const int b1 = (p1 / 14) * 132 + (p1 % 14) * 3;

            #pragma unroll
            for (int ch = 0; ch < 8; ch++) {
                const int kb = ch * 16;
                int o0 = sGoff2[kb + 2 * c4],     o1 = sGoff2[kb + 2 * c4 + 1];
                int o2 = sGoff2[kb + 2 * c4 + 8], o3 = sGoff2[kb + 2 * c4 + 9];
                uint32_t a0 = ld2bf(In, b0 + o0, b0 + o1);
                uint32_t a1 = ld2bf(In, b1 + o0, b1 + o1);
                uint32_t a2 = ld2bf(In, b0 + o2, b0 + o3);
                uint32_t a3 = ld2bf(In, b1 + o2, b1 + o3);
                #pragma unroll
                for (int nt = 0; nt < 4; nt++) {
                    uint2 bb = *(const uint2*)&Wf[((ch * 4 + nt) * 32 + lane) * 2];
                    mma16816(acc[ti] + nt * 4, a0, a1, a2, a3, bb.x, bb.y);
                }
            }
        }
        __syncthreads();
    }

    #pragma unroll
    for (int ti = 0; ti < 2; ti++) {
        const int tile = wid + ti * 8;
        if (tile >= 13) break;
        const int pr0 = tile * 16 + g, pr1 = pr0 + 8;
        #pragma unroll
        for (int nt = 0; nt < 4; nt++) {
            const int c0 = nt * 8 + 2 * c4;
            const float bb0 = __ldg(b2 + c0), bb1 = __ldg(b2 + c0 + 1);
            if (pr0 < 196) {
                size_t o = (size_t)(n * 32 + c0) * 2744 + od * 196 + pr0;
                g_c2[o]        = leaky(acc[ti][nt * 4 + 0] + bb0);
                g_c2[o + 2744] = leaky(acc[ti][nt * 4 + 1] + bb1);
            }
            if (pr1 < 196) {
                size_t o = (size_t)(n * 32 + c0) * 2744 + od * 196 + pr1;
                g_c2[o]        = leaky(acc[ti][nt * 4 + 2] + bb0);
                g_c2[o + 2744] = leaky(acc[ti][nt * 4 + 3] + bb1);
            }
        }
    }
}

// =======================================================================
// prep_w3
// =======================================================================
__global__ __launch_bounds__(256) void prep_w3_kernel(const float* __restrict__ w3)
{
    int idx = blockIdx.x * 256 + threadIdx.x;
    if (idx >= 192000) return;
    int gcin = idx / 1500;
    int r    = idx % 1500;
    int tap = r / 12, cc = r % 12;
    int g = gcin / 32, cin = gcin % 32;
    g_w3t[idx] = w3[((g * 12 + cc) * 32 + cin) * 125 + tap];
}

// =======================================================================
// conv3: grid(4, 64); block 256 = pos(64) x cin-quarter(4)
// =======================================================================
__global__ __launch_bounds__(256) void conv3_kernel(const float* __restrict__ b3)
{
    extern __shared__ float smemf[];

    const int g = blockIdx.x;
    const int n = blockIdx.y;
    const int tid = threadIdx.x;
    const int pos = tid & 63;
    const int sub = tid >> 6;
    const int od = pos >> 4, oh = (pos >> 2) & 3, ow = pos & 3;

    float* myIn = smemf + sub * 2744;
    const float4* sW4 = (const float4*)(smemf + 10976 + sub * 1500);

    float acc[12];
    #pragma unroll
    for (int c = 0; c < 12; c++) acc[c] = 0.f;

    for (int ci = 0; ci < 8; ci++) {
        const int cin = sub * 8 + ci;
        {
            const float* sI = g_c2 + (size_t)(n * 32 + cin) * 2744;
            for (int f = pos; f < 686; f += 64) cp16(myIn + f * 4, sI + f * 4);
            float* dW = smemf + 10976 + sub * 1500;
            const float* sWsrc = g_w3t + (size_t)(g * 32 + cin) * 1500;
            for (int f = pos; f < 375; f += 64) cp16(dW + f * 4, sWsrc + f * 4);
        }
        CP_COMMIT();
        CP_WAIT0();
        __syncthreads();

        #pragma unroll 1
        for (int kd = 0; kd < 5; kd++) {
            const float* sr = myIn + (3 * od + kd) * 196 + 3 * oh * 14 + 3 * ow;
            #pragma unroll
            for (int kh = 0; kh < 5; kh++) {
                #pragma unroll
                for (int kw = 0; kw < 5; kw++) {
                    float v = sr[kh * 14 + kw];
                    const int tap = (kd * 5 + kh) * 5 + kw;
                    #pragma unroll
                    for (int q = 0; q < 3; q++) {
                        float4 w = sW4[tap * 3 + q];
                        acc[q * 4 + 0] = fmaf(v, w.x, acc[q * 4 + 0]);
                        acc[q * 4 + 1] = fmaf(v, w.y, acc[q * 4 + 1]);
                        acc[q * 4 + 2] = fmaf(v, w.z, acc[q * 4 + 2]);
                        acc[q * 4 + 3] = fmaf(v, w.w, acc[q * 4 + 3]);
                    }
                }
            }
        }
        __syncthreads();
    }

    float* sStage = smemf;
    #pragma unroll
    for (int c = 0; c < 12; c++) sStage[tid * 12 + c] = acc[c];
    __syncthreads();
    if (sub == 0) {
        #pragma unroll
        for (int c = 0; c < 12; c++) {
            float s = sStage[pos * 12 + c] + sStage[(64 + pos) * 12 + c]
                    + sStage[(128 + pos) * 12 + c] + sStage[(192 + pos) * 12 + c];
            g_c3[(size_t)(n * 48 + g * 12 + c) * 64 + pos] = leaky(s + b3[g * 12 + c]);
        }
    }
}

// =======================================================================
// conv4 + feature
// =======================================================================
__global__ __launch_bounds__(256) void conv4_kernel(
    const float* __restrict__ w4, const float* __restrict__ b4)
{
    const int n  = blockIdx.x;
    const int c0 = blockIdx.y * 8;

    __shared__ float sIn[48 * 64];
    __shared__ float sRed[256];

    const int tid = threadIdx.x;
    const float* src = g_c3 + (size_t)n * 3072;
    for (int idx = tid; idx < 3072; idx += 256) sIn[idx] = src[idx];
    __syncthreads();

    const int sub = tid >> 6;
    const int loc = tid & 63;
    const int c   = loc >> 3;
    const int p   = loc & 7;
    const int od = p >> 2, oh = (p >> 1) & 1, ow = p & 1;

    float acc = 0.f;
    const float* wb = w4 + (size_t)(c0 + c) * 48 * 27;
    #pragma unroll
    for (int ci = 0; ci < 12; ci++) {
        int cin = sub * 12 + ci;
        const float* s  = sIn + cin * 64;
        const float* wk = wb + cin * 27;
        #pragma unroll
        for (int kd = 0; kd < 3; kd++)
            #pragma unroll
            for (int kh = 0; kh < 3; kh++)
                #pragma unroll
                for (int kw = 0; kw < 3; kw++)
                    acc = fmaf(s[(od + kd) * 16 + (oh + kh) * 4 + (ow + kw)],
                               __ldg(wk + kd * 9 + kh * 3 + kw), acc);
    }
    sRed[tid] = acc;
    __syncthreads();
    if (sub == 0) {
        float v = sRed[loc] + sRed[loc + 64] + sRed[loc + 128] + sRed[loc + 192];
        g_feat[n * 512 + (c0 + c) * 8 + p] = leaky(v + b4[c0 + c]);
    }
}

// =======================================================================
// M = feature @ T
// =======================================================================
__global__ __launch_bounds__(256) void mmul_kernel(const float* __restrict__ T)
{
    const int i = blockIdx.x;
    __shared__ float sF[512];
    const int tid = threadIdx.x;
    for (int k = tid; k < 512; k += 256) sF[k] = g_feat[i * 512 + k];
    __syncthreads();

    float acc0 = 0.f, acc1 = 0.f, acc2 = 0.f, acc3 = 0.f;
    for (int k = 0; k < 512; k++) {
        float v = sF[k];
        const float* tr = T + (size_t)k * 1024;
        acc0 = fmaf(v, tr[tid], acc0);
        acc1 = fmaf(v, tr[tid + 256], acc1);
        acc2 = fmaf(v, tr[tid + 512], acc2);
        acc3 = fmaf(v, tr[tid + 768], acc3);
    }
    g_M[i * 1024 + tid] = acc0;
    g_M[i * 1024 + tid + 256] = acc1;
    g_M[i * 1024 + tid + 512] = acc2;
    g_M[i * 1024 + tid + 768] = acc3;
}

// =======================================================================
// out_T[i,c] = sum_j exp( sum_k |M[i,c,k]-M[j,c,k]| )
// =======================================================================
__global__ __launch_bounds__(256) void mbd_kernel()
{
    const int i = blockIdx.x;
    __shared__ float sMi[1024];
    __shared__ float sRed[256];
    const int tid = threadIdx.x;
    const int c = tid & 63;
    const int js = tid >> 6;

    for (int k = tid; k < 1024; k += 256) sMi[k] = g_M[i * 1024 + k];
    __syncthreads();

    const float4* mi4 = (const float4*)(sMi + c * 16);
    float4 a0 = mi4[0], a1 = mi4[1], a2 = mi4[2], a3 = mi4[3];

    float acc = 0.f;
    for (int j = js; j < 64; j += 4) {
        const float4* mj4 = (const float4*)(g_M + j * 1024 + c * 16);
        float4 b0 = mj4[0], b1 = mj4[1], b2 = mj4[2], b3 = mj4[3];
        float d =
            fabsf(a0.x - b0.x) + fabsf(a0.y - b0.y) + fabsf(a0.z - b0.z) + fabsf(a0.w - b0.w) +
            fabsf(a1.x - b1.x) + fabsf(a1.y - b1.y) + fabsf(a1.z - b1.z) + fabsf(a1.w - b1.w) +
            fabsf(a2.x - b2.x) + fabsf(a2.y - b2.y) + fabsf(a2.z - b2.z) + fabsf(a2.w - b2.w) +
            fabsf(a3.x - b3.x) + fabsf(a3.y - b3.y) + fabsf(a3.z - b3.z) + fabsf(a3.w - b3.w);
        acc += expf(d);
    }
    sRed[tid] = acc;
    __syncthreads();
    if (js == 0) {
        float s = sRed[c] + sRed[c + 64] + sRed[c + 128] + sRed[c + 192];
        g_outT[i * 64 + c] = s;
    }
}

// =======================================================================
// final
// =======================================================================
__global__ __launch_bounds__(64) void final_kernel(
    const float* __restrict__ Wm, const float* __restrict__ bm,
    float* __restrict__ out)
{
    const int i = threadIdx.x;
    float z = bm[0];
    const float* f = g_feat + i * 512;
    #pragma unroll 8
    for (int k = 0; k < 512; k++) z = fmaf(f[k], Wm[k], z);
    const float* t = g_outT + i * 64;
    #pragma unroll 8
    for (int c = 0; c < 64; c++) z = fmaf(t[c], Wm[512 + c], z);
    out[i] = 1.f / (1.f + expf(-z));
}

// =======================================================================
extern "C" void kernel_launch(void* const* d_in, const int* in_sizes, int n_in,
                              void* d_out, int out_size)
{
    const float* x  = (const float*)d_in[0];
    const float* w1 = (const float*)d_in[1];
    const float* b1 = (const float*)d_in[2];
    const float* w2 = (const float*)d_in[3];
    const float* b2 = (const float*)d_in[4];
    const float* w3 = (const float*)d_in[5];
    const float* b3 = (const float*)d_in[6];
    const float* w4 = (const float*)d_in[7];
    const float* b4 = (const float*)d_in[8];
    const float* T  = (const float*)d_in[9];
    const float* Wm = (const float*)d_in[10];
    const float* bm = (const float*)d_in[11];
    float* out = (float*)d_out;

    const int conv2_smem = 16896 + 2 * 19360;           // 55616 B
    const int conv3_smem = 16976 * (int)sizeof(float);  // 67904 B
    cudaFuncSetAttribute(conv2_mma_kernel,
                         cudaFuncAttributeMaxDynamicSharedMemorySize, conv2_smem);
    cudaFuncSetAttribute(conv3_kernel,
                         cudaFuncAttributeMaxDynamicSharedMemorySize, conv3_smem);

    prep_xb_kernel<<<48672, 256>>>(x);
    prep_w1f_kernel<<<4, 256>>>(w1);
    prep_w2f_kernel<<<64, 256>>>(w2);
    prep_w3_kernel<<<750, 256>>>(w3);
    conv1_mma_kernel<<<dim3(22, 64), 256>>>(b1);
    conv2_mma_kernel<<<dim3(14, 64), 256, conv2_smem>>>(b2);
    conv3_kernel<<<dim3(4, 64), 256, conv3_smem>>>(b3);
    conv4_kernel<<<dim3(64, 8), 256>>>(w4, b4);
    mmul_kernel<<<64, 256>>>(T);
    mbd_kernel<<<64, 256>>>();
    final_kernel<<<1, 64>>>(Wm, bm, out);
}

// round 16
// speedup vs baseline: 4.3525x; 1.0368x over previous
#include <cuda_runtime.h>
#include <cuda_bf16.h>
#include <math.h>
#include <stdint.h>

// ---------------- problem constants ----------------
#define SLOPE 0.01f

// conv1: in [64,1,92,92,92] w[16,1,6,6,6] s2 -> [64,16,44,44,44]
// conv2: in [64,16,44,44,44] w[32,16,5,5,5] s3 -> [64,32,14,14,14]
// conv3: in [64,32,14,14,14] w[48,32,5,5,5] s3 -> [64,48,4,4,4]
// conv4: in [64,48,4,4,4]  w[64,48,3,3,3] s1 -> [64,64,2,2,2]

// ---------------- scratch (static device globals; no cudaMalloc) ----------
__device__ __align__(128) __nv_bfloat16 g_xb[64ull * 778688];           // 100 MB
__device__ __align__(128) __nv_bfloat16 g_c1b[64ull * 16 * 85184 + 64]; // 175 MB
__device__ __align__(128) __nv_bfloat16 g_c2b[64 * 32 * 2744 + 64];     // 11.2 MB
__device__ __align__(128) float g_c3[64 * 48 * 64];
__device__ __align__(128) float g_feat[64 * 512];
__device__ __align__(128) float g_M[64 * 1024];
__device__ __align__(128) float g_outT[64 * 64];
__device__ __align__(128) uint32_t g_w1f[1792];          // conv1 bf16x2 B-fragments
__device__ __align__(128) uint32_t g_w2f[32768];         // conv2 bf16x2 B-fragments
__device__ __align__(128) uint32_t g_w3f[98304];         // conv3 bf16x2 B-fragments

__device__ __forceinline__ float leaky(float v) {
    return v >= 0.f ? v : SLOPE * v;
}

__device__ __forceinline__ void cp16(void* dst, const void* src) {
    unsigned d = (unsigned)__cvta_generic_to_shared(dst);
    asm volatile("cp.async.cg.shared.global [%0], [%1], 16;" :: "r"(d), "l"(src));
}
__device__ __forceinline__ void cp8(void* dst, const void* src) {
    unsigned d = (unsigned)__cvta_generic_to_shared(dst);
    asm volatile("cp.async.ca.shared.global [%0], [%1], 8;" :: "r"(d), "l"(src));
}
#define CP_COMMIT() asm volatile("cp.async.commit_group;")
#define CP_WAIT1()  asm volatile("cp.async.wait_group 1;")
#define CP_WAIT0()  asm volatile("cp.async.wait_group 0;")

__device__ __forceinline__ uint32_t packbf(float hi, float lo) {
    uint32_t r;
    asm("cvt.rn.bf16x2.f32 %0, %1, %2;" : "=r"(r) : "f"(hi), "f"(lo));
    return r;
}
__device__ __forceinline__ uint32_t ld2bf(const __nv_bfloat16* p, int i0, int i1) {
    uint32_t lo = *(const unsigned short*)(p + i0);
    uint32_t hi = *(const unsigned short*)(p + i1);
    return lo | (hi << 16);
}

// d += A(16x16 bf16, row) @ B(16x8 bf16, col)
__device__ __forceinline__ void mma16816(float* d,
    uint32_t a0, uint32_t a1, uint32_t a2, uint32_t a3,
    uint32_t b0, uint32_t b1) {
    asm volatile(
        "mma.sync.aligned.m16n8k16.row.col.f32.bf16.bf16.f32 "
        "{%0,%1,%2,%3}, {%4,%5,%6,%7}, {%8,%9}, {%0,%1,%2,%3};"
        : "+f"(d[0]), "+f"(d[1]), "+f"(d[2]), "+f"(d[3])
        : "r"(a0), "r"(a1), "r"(a2), "r"(a3), "r"(b0), "r"(b1));
}

// =======================================================================
// prep_xb: x fp32 -> bf16
// =======================================================================
__global__ __launch_bounds__(256) void prep_xb_kernel(const float* __restrict__ x)
{
    size_t idx = (size_t)blockIdx.x * 256 + threadIdx.x;
    if (idx >= 12459008ull) return;
    float4 v = ((const float4*)x)[idx];
    uint2 o;
    o.x = packbf(v.y, v.x);
    o.y = packbf(v.w, v.z);
    ((uint2*)g_xb)[idx] = o;
}

// =======================================================================
// prep_w1f: conv1 B-fragments (zero for k>=216)
// =======================================================================
__global__ __launch_bounds__(256) void prep_w1f_kernel(const float* __restrict__ w1)
{
    int idx = blockIdx.x * 256 + threadIdx.x;
    if (idx >= 896) return;
    int lane = idx & 31;
    int nt = (idx >> 5) & 1;
    int chunk = idx >> 6;
    int g = lane >> 2, c = lane & 3;
    int n = nt * 8 + g;
    int k0 = chunk * 16 + 2 * c;
    int k2 = k0 + 8;
    float v00 = (k0     < 216) ? w1[n * 216 + k0]     : 0.f;
    float v01 = (k0 + 1 < 216) ? w1[n * 216 + k0 + 1] : 0.f;
    float v10 = (k2     < 216) ? w1[n * 216 + k2]     : 0.f;
    float v11 = (k2 + 1 < 216) ? w1[n * 216 + k2 + 1] : 0.f;
    g_w1f[idx * 2]     = packbf(v01, v00);
    g_w1f[idx * 2 + 1] = packbf(v11, v10);
}

// =======================================================================
// prep_w2f: conv2 B-fragments (125 taps padded to 128)
// =======================================================================
__global__ __launch_bounds__(256) void prep_w2f_kernel(const float* __restrict__ w2)
{
    int idx = blockIdx.x * 256 + threadIdx.x;
    if (idx >= 16384) return;
    int lane = idx & 31;
    int nt = (idx >> 5) & 3;
    int ch = (idx >> 7) & 7;
    int cin = idx >> 10;
    int g = lane >> 2, c = lane & 3;
    int n = nt * 8 + g;
    int k0 = ch * 16 + 2 * c;
    int k2 = k0 + 8;
    const float* wb = w2 + (size_t)(n * 16 + cin) * 125;
    float v00 = (k0     < 125) ? wb[k0]     : 0.f;
    float v01 = (k0 + 1 < 125) ? wb[k0 + 1] : 0.f;
    float v10 = (k2     < 125) ? wb[k2]     : 0.f;
    float v11 = (k2 + 1 < 125) ? wb[k2 + 1] : 0.f;
    g_w2f[idx * 2]     = packbf(v01, v00);
    g_w2f[idx * 2 + 1] = packbf(v11, v10);
}

// =======================================================================
// prep_w3f: conv3 B-fragments. idx = ((cin*8+ch)*6+nt)*32+lane
// =======================================================================
__global__ __launch_bounds__(256) void prep_w3f_kernel(const float* __restrict__ w3)
{
    int idx = blockIdx.x * 256 + threadIdx.x;
    if (idx >= 49152) return;
    int lane = idx & 31;
    int nt = (idx >> 5) % 6;
    int ch = (idx / 192) & 7;
    int cin = idx / 1536;
    int g = lane >> 2, c = lane & 3;
    int n = nt * 8 + g;
    int k0 = ch * 16 + 2 * c;
    int k2 = k0 + 8;
    const float* wb = w3 + (size_t)(n * 32 + cin) * 125;
    float v00 = (k0     < 125) ? wb[k0]     : 0.f;
    float v01 = (k0 + 1 < 125) ? wb[k0 + 1] : 0.f;
    float v10 = (k2     < 125) ? wb[k2]     : 0.f;
    float v11 = (k2 + 1 < 125) ? wb[k2 + 1] : 0.f;
    g_w3f[idx * 2]     = packbf(v01, v00);
    g_w3f[idx * 2 + 1] = packbf(v11, v10);
}

// =======================================================================
// conv1 via mma.sync bf16, chunk-outer 3-tile ILP
// =======================================================================
__global__ __launch_bounds__(256) void conv1_mma_kernel(const float* __restrict__ b1)
{
    __shared__ uint32_t sGoffP[56];
    __shared__ uint32_t sBfrag[1792];
    __shared__ __align__(16) __nv_bfloat16 sWinB[2][8832];

    const int bx = blockIdx.x;                   // od pair
    const int n  = blockIdx.y;
    const int tid = threadIdx.x;
    const int wid = tid >> 5, lane = tid & 31;
    const int g = lane >> 2, c4 = lane & 3;

    if (tid < 56) {
        int ch = tid >> 2, cc = tid & 3;
        int kb = ch * 16;
        auto off = [](int k) -> int {
            if (k >= 216) return 0;
            int kd = k / 36, r = k % 36;
            return kd * 1104 + (r / 6) * 92 + (r % 6);
        };
        uint32_t o0 = (uint32_t)off(kb + 2 * cc);
        uint32_t o2 = (uint32_t)off(kb + 2 * cc + 8);
        sGoffP[tid] = o0 | (o2 << 16);
    }
    for (int f = tid; f < 448; f += 256)
        cp16(sBfrag + f * 4, g_w1f + f * 4);

    const float bv00 = __ldg(b1 + 2 * c4),     bv01 = __ldg(b1 + 2 * c4 + 1);
    const float bv10 = __ldg(b1 + 2 * c4 + 8), bv11 = __ldg(b1 + 2 * c4 + 9);

    const __nv_bfloat16* xb = g_xb + (size_t)n * 778688 + (size_t)(4 * bx) * 8464;
    const size_t nBase = (size_t)(n * 16) * 85184;

    auto issue = [&](int grp) {
        __nv_bfloat16* dst = sWinB[grp & 1];
        const __nv_bfloat16* xs = xb + (8 * grp) * 92;
        for (int f = tid; f < 2208; f += 256) {
            int row = f / 23, q = f - row * 23;
            int ld = row / 12, lh = row - ld * 12;
            cp8(dst + row * 92 + q * 4, xs + (size_t)ld * 8464 + lh * 92 + q * 4);
        }
    };

    // grp-invariant per-tile window bases (tt clamped to 21 for wid>=6, t=2)
    int wb0[3], wb1[3];
    #pragma unroll
    for (int t = 0; t < 3; t++) {
        int tt = wid + 8 * t; if (tt > 21) tt = 21;
        int pr0 = tt * 16 + g, pr1 = pr0 + 8;
        int odl0 = pr0 / 176, r0 = pr0 % 176;
        int odl1 = pr1 / 176, r1 = pr1 % 176;
        wb0[t] = odl0 * 2208 + (r0 / 44) * 184 + 2 * (r0 % 44);
        wb1[t] = odl1 * 2208 + (r1 / 44) * 184 + 2 * (r1 % 44);
    }

    issue(0);
    CP_COMMIT();
    __syncthreads();     // sGoffP visible

    uint32_t op[14];
    #pragma unroll
    for (int ch = 0; ch < 14; ch++) op[ch] = sGoffP[ch * 4 + c4];

    for (int grp = 0; grp < 11; grp++) {
        if (grp < 10) {
            issue(grp + 1);
            CP_COMMIT();
            CP_WAIT1();
        } else {
            CP_WAIT0();
        }
        __syncthreads();
        const __nv_bfloat16* Win = sWinB[grp & 1];

        float d[3][8];
        #pragma unroll
        for (int t = 0; t < 3; t++)
            #pragma unroll
            for (int i = 0; i < 8; i++) d[t][i] = 0.f;

        #pragma unroll
        for (int ch = 0; ch < 14; ch++) {
            int o0 = (int)(op[ch] & 0xFFFFu);
            int o2 = (int)(op[ch] >> 16);
            uint2 bb0 = *(const uint2*)&sBfrag[(ch * 2 + 0) * 64 + lane * 2];
            uint2 bb1 = *(const uint2*)&sBfrag[(ch * 2 + 1) * 64 + lane * 2];
            #pragma unroll
            for (int t = 0; t < 3; t++) {
                uint32_t a0 = *(const uint32_t*)(Win + wb0[t] + o0);
                uint32_t a1 = *(const uint32_t*)(Win + wb1[t] + o0);
                uint32_t a2 = *(const uint32_t*)(Win + wb0[t] + o2);
                uint32_t a3 = *(const uint32_t*)(Win + wb1[t] + o2);
                mma16816(d[t],     a0, a1, a2, a3, bb0.x, bb0.y);
                mma16816(d[t] + 4, a0, a1, a2, a3, bb1.x, bb1.y);
            }
        }

        #pragma unroll
        for (int t = 0; t < 3; t++) {
            int tt = wid + 8 * t;
            if (tt >= 22) continue;
            int pr0 = tt * 16 + g, pr1 = pr0 + 8;
            int odl0 = pr0 / 176, r0 = pr0 % 176, ohr0 = r0 / 44, ow0 = r0 % 44;
            int odl1 = pr1 / 176, r1 = pr1 % 176, ohr1 = r1 / 44, ow1 = r1 % 44;
            size_t ob0 = nBase + (size_t)(2 * bx + odl0) * 1936
                       + (4 * grp + ohr0) * 44 + ow0;
            size_t ob1 = nBase + (size_t)(2 * bx + odl1) * 1936
                       + (4 * grp + ohr1) * 44 + ow1;
            const int co = 2 * c4;
            g_c1b[ob0 + (size_t)(co)     * 85184] = __float2bfloat16(leaky(d[t][0] + bv00));
            g_c1b[ob0 + (size_t)(co + 1) * 85184] = __float2bfloat16(leaky(d[t][1] + bv01));
            g_c1b[ob1 + (size_t)(co)     * 85184] = __float2bfloat16(leaky(d[t][2] + bv00));
            g_c1b[ob1 + (size_t)(co + 1) * 85184] = __float2bfloat16(leaky(d[t][3] + bv01));
            g_c1b[ob0 + (size_t)(co + 8) * 85184] = __float2bfloat16(leaky(d[t][4] + bv10));
            g_c1b[ob0 + (size_t)(co + 9) * 85184] = __float2bfloat16(leaky(d[t][5] + bv11));
            g_c1b[ob1 + (size_t)(co + 8) * 85184] = __float2bfloat16(leaky(d[t][6] + bv10));
            g_c1b[ob1 + (size_t)(co + 9) * 85184] = __float2bfloat16(leaky(d[t][7] + bv11));
        }
        __syncthreads();
    }
}

// =======================================================================
// conv2 via mma.sync bf16; output stored bf16 (g_c2b)
// =======================================================================
__global__ __launch_bounds__(256) void conv2_mma_kernel(const float* __restrict__ b2)
{
    extern __shared__ char smemc[];
    int*            sGoff2 = (int*)smemc;                       // 128
    uint32_t*       sWf = (uint32_t*)(smemc + 512);             // 2 x 2048
    __nv_bfloat16*  sIn = (__nv_bfloat16*)(smemc + 16896);      // 2 x 9680

    const int od = blockIdx.x;
    const int n  = blockIdx.y;
    const int tid = threadIdx.x;
    const int wid = tid >> 5, lane = tid & 31;
    const int g = lane >> 2, c4 = lane & 3;

    if (tid < 128) {
        int tap = tid, o = 0;
        if (tap < 125) {
            int kd = tap / 25, r = tap % 25;
            o = kd * 1936 + (r / 5) * 44 + (r % 5);
        }
        sGoff2[tid] = o;
    }

    auto issue = [&](int cin) {
        int buf = cin & 1;
        const __nv_bfloat16* srcI =
            g_c1b + (size_t)(n * 16 + cin) * 85184 + (size_t)(3 * od) * 1936;
        __nv_bfloat16* dI = sIn + buf * 9680;
        for (int f = tid; f < 2420; f += 256)
            cp8(dI + f * 4, srcI + f * 4);
        const uint32_t* srcW = g_w2f + cin * 2048;
        uint32_t* dW = sWf + buf * 2048;
        for (int f = tid; f < 512; f += 256)
            cp16(dW + f * 4, srcW + f * 4);
    };

    float acc[2][16];
    #pragma unroll
    for (int t = 0; t < 2; t++)
        #pragma unroll
        for (int i = 0; i < 16; i++) acc[t][i] = 0.f;

    issue(0);
    CP_COMMIT();

    for (int cin = 0; cin < 16; cin++) {
        if (cin < 15) {
            issue(cin + 1);
            CP_COMMIT();
            CP_WAIT1();
        } else {
            CP_WAIT0();
        }
        __syncthreads();

        const int buf = cin & 1;
        const __nv_bfloat16* In = sIn + buf * 9680;
        const uint32_t* Wf = sWf + buf * 2048;

        #pragma unroll
        for (int ti = 0; ti < 2; ti++) {
            const int tile = wid + ti * 8;
            if (tile >= 13) break;
            const int pr0 = tile * 16 + g, pr1 = pr0 + 8;
            const int p0 = pr0 < 196 ? pr0 : 195;
            const int p1 = pr1 < 196 ? pr1 : 195;
            const int b0 = (p0 / 14) * 132 + (p0 % 14) * 3;
            const int b1 = (p1 / 14) * 132 + (p1 % 14) * 3;

            #pragma unroll
            for (int ch = 0; ch < 8; ch++) {
                const int kb = ch * 16;
                int o0 = sGoff2[kb + 2 * c4],     o1 = sGoff2[kb + 2 * c4 + 1];
                int o2 = sGoff2[kb + 2 * c4 + 8], o3 = sGoff2[kb + 2 * c4 + 9];
                uint32_t a0 = ld2bf(In, b0 + o0, b0 + o1);
                uint32_t a1 = ld2bf(In, b1 + o0, b1 + o1);
                uint32_t a2 = ld2bf(In, b0 + o2, b0 + o3);
                uint32_t a3 = ld2bf(In, b1 + o2, b1 + o3);
                #pragma unroll
                for (int nt = 0; nt < 4; nt++) {
                    uint2 bb = *(const uint2*)&Wf[((ch * 4 + nt) * 32 + lane) * 2];
                    mma16816(acc[ti] + nt * 4, a0, a1, a2, a3, bb.x, bb.y);
                }
            }
        }
        __syncthreads();
    }

    #pragma unroll
    for (int ti = 0; ti < 2; ti++) {
        const int tile = wid + ti * 8;
        if (tile >= 13) break;
        const int pr0 = tile * 16 + g, pr1 = pr0 + 8;
        #pragma unroll
        for (int nt = 0; nt < 4; nt++) {
            const int c0 = nt * 8 + 2 * c4;
            const float bb0 = __ldg(b2 + c0), bb1 = __ldg(b2 + c0 + 1);
            if (pr0 < 196) {
                size_t o = (size_t)(n * 32 + c0) * 2744 + od * 196 + pr0;
                g_c2b[o]        = __float2bfloat16(leaky(acc[ti][nt * 4 + 0] + bb0));
                g_c2b[o + 2744] = __float2bfloat16(leaky(acc[ti][nt * 4 + 1] + bb1));
            }
            if (pr1 < 196) {
                size_t o = (size_t)(n * 32 + c0) * 2744 + od * 196 + pr1;
                g_c2b[o]        = __float2bfloat16(leaky(acc[ti][nt * 4 + 2] + bb0));
                g_c2b[o + 2744] = __float2bfloat16(leaky(acc[ti][nt * 4 + 3] + bb1));
            }
        }
    }
}

// =======================================================================
// conv3 via mma.sync bf16: block per n. M=64 pos (4 m-tiles), N=48 (6 n8).
// warp = (m-tile, n-half): 4 x 2. K = 32 cin x 128. Double-buffered.
// =======================================================================
__global__ __launch_bounds__(256) void conv3_mma_kernel(const float* __restrict__ b3)
{
    __shared__ int sGoff3[128];
    __shared__ __align__(16) uint32_t sWf3[2][3072];
    __shared__ __align__(16) __nv_bfloat16 sIn3[2][2744];

    const int n = blockIdx.x;
    const int tid = threadIdx.x;
    const int wid = tid >> 5, lane = tid & 31;
    const int g = lane >> 2, c4 = lane & 3;
    const int mt = wid & 3, nh = wid >> 2;

    if (tid < 128) {
        int tap = tid, o = 0;
        if (tap < 125) {
            int kd = tap / 25, r = tap % 25;
            o = kd * 196 + (r / 5) * 14 + (r % 5);
        }
        sGoff3[tid] = o;
    }

    auto issue = [&](int cin) {
        int buf = cin & 1;
        const __nv_bfloat16* srcI = g_c2b + (size_t)(n * 32 + cin) * 2744;
        __nv_bfloat16* dI = sIn3[buf];
        for (int f = tid; f < 686; f += 256)
            cp8(dI + f * 4, srcI + f * 4);
        const uint32_t* srcW = g_w3f + (size_t)cin * 3072;
        uint32_t* dW = sWf3[buf];
        for (int f = tid; f < 768; f += 256)
            cp16(dW + f * 4, srcW + f * 4);
    };

    // rows for this warp's m-tile
    const int pr0 = mt * 16 + g, pr1 = pr0 + 8;
    const int b0 = 588 * (pr0 >> 4) + 42 * ((pr0 >> 2) & 3) + 3 * (pr0 & 3);
    const int b1 = 588 * (pr1 >> 4) + 42 * ((pr1 >> 2) & 3) + 3 * (pr1 & 3);

    float acc[3][4];
    #pragma unroll
    for (int j = 0; j < 3; j++)
        #pragma unroll
        for (int i = 0; i < 4; i++) acc[j][i] = 0.f;

    issue(0);
    CP_COMMIT();

    for (int cin = 0; cin < 32; cin++) {
        if (cin < 31) {
            issue(cin + 1);
            CP_COMMIT();
            CP_WAIT1();
        } else {
            CP_WAIT0();
        }
        __syncthreads();

        const int buf = cin & 1;
        const __nv_bfloat16* In = sIn3[buf];
        const uint32_t* Wf = sWf3[buf];

        #pragma unroll
        for (int ch = 0; ch < 8; ch++) {
            const int kb = ch * 16;
            int o0 = sGoff3[kb + 2 * c4],     o1 = sGoff3[kb + 2 * c4 + 1];
            int o2 = sGoff3[kb + 2 * c4 + 8], o3 = sGoff3[kb + 2 * c4 + 9];
            uint32_t a0 = ld2bf(In, b0 + o0, b0 + o1);
            uint32_t a1 = ld2bf(In, b1 + o0, b1 + o1);
            uint32_t a2 = ld2bf(In, b0 + o2, b0 + o3);
            uint32_t a3 = ld2bf(In, b1 + o2, b1 + o3);
            #pragma unroll
            for (int j = 0; j < 3; j++) {
                const int nt = nh * 3 + j;
                uint2 bb = *(const uint2*)&Wf[((ch * 6 + nt) * 32 + lane) * 2];
                mma16816(acc[j], a0, a1, a2, a3, bb.x, bb.y);
            }
        }
        __syncthreads();
    }

    #pragma unroll
    for (int j = 0; j < 3; j++) {
        const int c0 = (nh * 3 + j) * 8 + 2 * c4;
        const float bb0 = __ldg(b3 + c0), bb1 = __ldg(b3 + c0 + 1);
        size_t o0 = (size_t)(n * 48 + c0) * 64;
        g_c3[o0 + pr0]      = leaky(acc[j][0] + bb0);
        g_c3[o0 + 64 + pr0] = leaky(acc[j][1] + bb1);
        g_c3[o0 + pr1]      = leaky(acc[j][2] + bb0);
        g_c3[o0 + 64 + pr1] = leaky(acc[j][3] + bb1);
    }
}

// =======================================================================
// conv4 + feature
// =======================================================================
__global__ __launch_bounds__(256) void conv4_kernel(
    const float* __restrict__ w4, const float* __restrict__ b4)
{
    const int n  = blockIdx.x;
    const int c0 = blockIdx.y * 8;

    __shared__ float sIn[48 * 64];
    __shared__ float sRed[256];

    const int tid = threadIdx.x;
    const float* src = g_c3 + (size_t)n * 3072;
    for (int idx = tid; idx < 3072; idx += 256) sIn[idx] = src[idx];
    __syncthreads();

    const int sub = tid >> 6;
    const int loc = tid & 63;
    const int c   = loc >> 3;
    const int p   = loc & 7;
    const int od = p >> 2, oh = (p >> 1) & 1, ow = p & 1;

    float acc = 0.f;
    const float* wb = w4 + (size_t)(c0 + c) * 48 * 27;
    #pragma unroll
    for (int ci = 0; ci < 12; ci++) {
        int cin = sub * 12 + ci;
        const float* s  = sIn + cin * 64;
        const float* wk = wb + cin * 27;
        #pragma unroll
        for (int kd = 0; kd < 3; kd++)
            #pragma unroll
            for (int kh = 0; kh < 3; kh++)
                #pragma unroll
                for (int kw = 0; kw < 3; kw++)
                    acc = fmaf(s[(od + kd) * 16 + (oh + kh) * 4 + (ow + kw)],
                               __ldg(wk + kd * 9 + kh * 3 + kw), acc);
    }
    sRed[tid] = acc;
    __syncthreads();
    if (sub == 0) {
        float v = sRed[loc] + sRed[loc + 64] + sRed[loc + 128] + sRed[loc + 192];
        g_feat[n * 512 + (c0 + c) * 8 + p] = leaky(v + b4[c0 + c]);
    }
}

// =======================================================================
// M = feature @ T
// =======================================================================
__global__ __launch_bounds__(256) void mmul_kernel(const float* __restrict__ T)
{
    const int i = blockIdx.x;
    __shared__ float sF[512];
    const int tid = threadIdx.x;
    for (int k = tid; k < 512; k += 256) sF[k] = g_feat[i * 512 + k];
    __syncthreads();

    float acc0 = 0.f, acc1 = 0.f, acc2 = 0.f, acc3 = 0.f;
    for (int k = 0; k < 512; k++) {
        float v = sF[k];
        const float* tr = T + (size_t)k * 1024;
        acc0 = fmaf(v, tr[tid], acc0);
        acc1 = fmaf(v, tr[tid + 256], acc1);
        acc2 = fmaf(v, tr[tid + 512], acc2);
        acc3 = fmaf(v, tr[tid + 768], acc3);
    }
    g_M[i * 1024 + tid] = acc0;
    g_M[i * 1024 + tid + 256] = acc1;
    g_M[i * 1024 + tid + 512] = acc2;
    g_M[i * 1024 + tid + 768] = acc3;
}

// =======================================================================
// out_T[i,c] = sum_j exp( sum_k |M[i,c,k]-M[j,c,k]| )
// =======================================================================
__global__ __launch_bounds__(256) void mbd_kernel()
{
    const int i = blockIdx.x;
    __shared__ float sMi[1024];
    __shared__ float sRed[256];
    const int tid = threadIdx.x;
    const int c = tid & 63;
    const int js = tid >> 6;

    for (int k = tid; k < 1024; k += 256) sMi[k] = g_M[i * 1024 + k];
    __syncthreads();

    const float4* mi4 = (const float4*)(sMi + c * 16);
    float4 a0 = mi4[0], a1 = mi4[1], a2 = mi4[2], a3 = mi4[3];

    float acc = 0.f;
    for (int j = js; j < 64; j += 4) {
        const float4* mj4 = (const float4*)(g_M + j * 1024 + c * 16);
        float4 b0 = mj4[0], b1 = mj4[1], b2 = mj4[2], b3 = mj4[3];
        float d =
            fabsf(a0.x - b0.x) + fabsf(a0.y - b0.y) + fabsf(a0.z - b0.z) + fabsf(a0.w - b0.w) +
            fabsf(a1.x - b1.x) + fabsf(a1.y - b1.y) + fabsf(a1.z - b1.z) + fabsf(a1.w - b1.w) +
            fabsf(a2.x - b2.x) + fabsf(a2.y - b2.y) + fabsf(a2.z - b2.z) + fabsf(a2.w - b2.w) +
            fabsf(a3.x - b3.x) + fabsf(a3.y - b3.y) + fabsf(a3.z - b3.z) + fabsf(a3.w - b3.w);
        acc += expf(d);
    }
    sRed[tid] = acc;
    __syncthreads();
    if (js == 0) {
        float s = sRed[c] + sRed[c + 64] + sRed[c + 128] + sRed[c + 192];
        g_outT[i * 64 + c] = s;
    }
}

// =======================================================================
// final
// =======================================================================
__global__ __launch_bounds__(64) void final_kernel(
    const float* __restrict__ Wm, const float* __restrict__ bm,
    float* __restrict__ out)
{
    const int i = threadIdx.x;
    float z = bm[0];
    const float* f = g_feat + i * 512;
    #pragma unroll 8
    for (int k = 0; k < 512; k++) z = fmaf(f[k], Wm[k], z);
    const float* t = g_outT + i * 64;
    #pragma unroll 8
    for (int c = 0; c < 64; c++) z = fmaf(t[c], Wm[512 + c], z);
    out[i] = 1.f / (1.f + expf(-z));
}

// =======================================================================
extern "C" void kernel_launch(void* const* d_in, const int* in_sizes, int n_in,
                              void* d_out, int out_size)
{
    const float* x  = (const float*)d_in[0];
    const float* w1 = (const float*)d_in[1];
    const float* b1 = (const float*)d_in[2];
    const float* w2 = (const float*)d_in[3];
    const float* b2 = (const float*)d_in[4];
    const float* w3 = (const float*)d_in[5];
    const float* b3 = (const float*)d_in[6];
    const float* w4 = (const float*)d_in[7];
    const float* b4 = (const float*)d_in[8];
    const float* T  = (const float*)d_in[9];
    const float* Wm = (const float*)d_in[10];
    const float* bm = (const float*)d_in[11];
    float* out = (float*)d_out;

    const int conv2_smem = 16896 + 2 * 19360;           // 55616 B
    cudaFuncSetAttribute(conv2_mma_kernel,
                         cudaFuncAttributeMaxDynamicSharedMemorySize, conv2_smem);

    prep_xb_kernel<<<48672, 256>>>(x);
    prep_w1f_kernel<<<4, 256>>>(w1);
    prep_w2f_kernel<<<64, 256>>>(w2);
    prep_w3f_kernel<<<192, 256>>>(w3);
    conv1_mma_kernel<<<dim3(22, 64), 256>>>(b1);
    conv2_mma_kernel<<<dim3(14, 64), 256, conv2_smem>>>(b2);
    conv3_mma_kernel<<<64, 256>>>(b3);
    conv4_kernel<<<dim3(64, 8), 256>>>(w4, b4);
    mmul_kernel<<<64, 256>>>(T);
    mbd_kernel<<<64, 256>>>();
    final_kernel<<<1, 64>>>(Wm, bm, out);
}

// round 17
// speedup vs baseline: 4.6764x; 1.0744x over previous
#include <cuda_runtime.h>
#include <cuda_bf16.h>
#include <math.h>
#include <stdint.h>

// ---------------- problem constants ----------------
#define SLOPE 0.01f

// conv1: in [64,1,92,92,92] w[16,1,6,6,6] s2 -> [64,16,44,44,44]
// conv2: in [64,16,44,44,44] w[32,16,5,5,5] s3 -> [64,32,14,14,14]
// conv3: in [64,32,14,14,14] w[48,32,5,5,5] s3 -> [64,48,4,4,4]
// conv4: in [64,48,4,4,4]  w[64,48,3,3,3] s1 -> [64,64,2,2,2]

// ---------------- scratch (static device globals; no cudaMalloc) ----------
__device__ __align__(128) __nv_bfloat16 g_xb[64ull * 778688];           // 100 MB
__device__ __align__(128) __nv_bfloat16 g_c1b[64ull * 16 * 85184 + 64]; // 175 MB
__device__ __align__(128) __nv_bfloat16 g_c2b[64 * 32 * 2744 + 64];     // 11.2 MB
__device__ __align__(128) float g_c3[64 * 48 * 64];
__device__ __align__(128) float g_feat[64 * 512];
__device__ __align__(128) float g_M[64 * 1024];
__device__ __align__(128) float g_outT[64 * 64];
__device__ __align__(128) uint32_t g_w1f[1792];          // conv1 bf16x2 B-fragments
__device__ __align__(128) uint32_t g_w2f[32768];         // conv2 bf16x2 B-fragments
__device__ __align__(128) uint32_t g_w3f[98304];         // conv3 bf16x2 B-fragments

__device__ __forceinline__ float leaky(float v) {
    return v >= 0.f ? v : SLOPE * v;
}

__device__ __forceinline__ void cp16(void* dst, const void* src) {
    unsigned d = (unsigned)__cvta_generic_to_shared(dst);
    asm volatile("cp.async.cg.shared.global [%0], [%1], 16;" :: "r"(d), "l"(src));
}
__device__ __forceinline__ void cp8(void* dst, const void* src) {
    unsigned d = (unsigned)__cvta_generic_to_shared(dst);
    asm volatile("cp.async.ca.shared.global [%0], [%1], 8;" :: "r"(d), "l"(src));
}
#define CP_COMMIT() asm volatile("cp.async.commit_group;")
#define CP_WAIT1()  asm volatile("cp.async.wait_group 1;")
#define CP_WAIT0()  asm volatile("cp.async.wait_group 0;")

__device__ __forceinline__ uint32_t packbf(float hi, float lo) {
    uint32_t r;
    asm("cvt.rn.bf16x2.f32 %0, %1, %2;" : "=r"(r) : "f"(hi), "f"(lo));
    return r;
}
__device__ __forceinline__ uint32_t ld2bf(const __nv_bfloat16* p, int i0, int i1) {
    uint32_t lo = *(const unsigned short*)(p + i0);
    uint32_t hi = *(const unsigned short*)(p + i1);
    return lo | (hi << 16);
}

// d += A(16x16 bf16, row) @ B(16x8 bf16, col)
__device__ __forceinline__ void mma16816(float* d,
    uint32_t a0, uint32_t a1, uint32_t a2, uint32_t a3,
    uint32_t b0, uint32_t b1) {
    asm volatile(
        "mma.sync.aligned.m16n8k16.row.col.f32.bf16.bf16.f32 "
        "{%0,%1,%2,%3}, {%4,%5,%6,%7}, {%8,%9}, {%0,%1,%2,%3};"
        : "+f"(d[0]), "+f"(d[1]), "+f"(d[2]), "+f"(d[3])
        : "r"(a0), "r"(a1), "r"(a2), "r"(a3), "r"(b0), "r"(b1));
}

// =======================================================================
// prep_xb: x fp32 -> bf16
// =======================================================================
__global__ __launch_bounds__(256) void prep_xb_kernel(const float* __restrict__ x)
{
    size_t idx = (size_t)blockIdx.x * 256 + threadIdx.x;
    if (idx >= 12459008ull) return;
    float4 v = ((const float4*)x)[idx];
    uint2 o;
    o.x = packbf(v.y, v.x);
    o.y = packbf(v.w, v.z);
    ((uint2*)g_xb)[idx] = o;
}

// =======================================================================
// prep_w1f: conv1 B-fragments (zero for k>=216)
// =======================================================================
__global__ __launch_bounds__(256) void prep_w1f_kernel(const float* __restrict__ w1)
{
    int idx = blockIdx.x * 256 + threadIdx.x;
    if (idx >= 896) return;
    int lane = idx & 31;
    int nt = (idx >> 5) & 1;
    int chunk = idx >> 6;
    int g = lane >> 2, c = lane & 3;
    int n = nt * 8 + g;
    int k0 = chunk * 16 + 2 * c;
    int k2 = k0 + 8;
    float v00 = (k0     < 216) ? w1[n * 216 + k0]     : 0.f;
    float v01 = (k0 + 1 < 216) ? w1[n * 216 + k0 + 1] : 0.f;
    float v10 = (k2     < 216) ? w1[n * 216 + k2]     : 0.f;
    float v11 = (k2 + 1 < 216) ? w1[n * 216 + k2 + 1] : 0.f;
    g_w1f[idx * 2]     = packbf(v01, v00);
    g_w1f[idx * 2 + 1] = packbf(v11, v10);
}

// =======================================================================
// prep_w2f: conv2 B-fragments (125 taps padded to 128)
// =======================================================================
__global__ __launch_bounds__(256) void prep_w2f_kernel(const float* __restrict__ w2)
{
    int idx = blockIdx.x * 256 + threadIdx.x;
    if (idx >= 16384) return;
    int lane = idx & 31;
    int nt = (idx >> 5) & 3;
    int ch = (idx >> 7) & 7;
    int cin = idx >> 10;
    int g = lane >> 2, c = lane & 3;
    int n = nt * 8 + g;
    int k0 = ch * 16 + 2 * c;
    int k2 = k0 + 8;
    const float* wb = w2 + (size_t)(n * 16 + cin) * 125;
    float v00 = (k0     < 125) ? wb[k0]     : 0.f;
    float v01 = (k0 + 1 < 125) ? wb[k0 + 1] : 0.f;
    float v10 = (k2     < 125) ? wb[k2]     : 0.f;
    float v11 = (k2 + 1 < 125) ? wb[k2 + 1] : 0.f;
    g_w2f[idx * 2]     = packbf(v01, v00);
    g_w2f[idx * 2 + 1] = packbf(v11, v10);
}

// =======================================================================
// prep_w3f: conv3 B-fragments. idx = ((cin*8+ch)*6+nt)*32+lane
// =======================================================================
__global__ __launch_bounds__(256) void prep_w3f_kernel(const float* __restrict__ w3)
{
    int idx = blockIdx.x * 256 + threadIdx.x;
    if (idx >= 49152) return;
    int lane = idx & 31;
    int nt = (idx >> 5) % 6;
    int ch = (idx / 192) & 7;
    int cin = idx / 1536;
    int g = lane >> 2, c = lane & 3;
    int n = nt * 8 + g;
    int k0 = ch * 16 + 2 * c;
    int k2 = k0 + 8;
    const float* wb = w3 + (size_t)(n * 32 + cin) * 125;
    float v00 = (k0     < 125) ? wb[k0]     : 0.f;
    float v01 = (k0 + 1 < 125) ? wb[k0 + 1] : 0.f;
    float v10 = (k2     < 125) ? wb[k2]     : 0.f;
    float v11 = (k2 + 1 < 125) ? wb[k2 + 1] : 0.f;
    g_w3f[idx * 2]     = packbf(v01, v00);
    g_w3f[idx * 2 + 1] = packbf(v11, v10);
}

// =======================================================================
// conv1 via mma.sync bf16. B-fragments in REGISTERS (grp/tile-invariant),
// single-tile loop (R14 structure), bf16 window double-buffered.
// =======================================================================
__global__ __launch_bounds__(256) void conv1_mma_kernel(const float* __restrict__ b1)
{
    __shared__ uint32_t sGoffP[56];
    __shared__ __align__(16) __nv_bfloat16 sWinB[2][8832];

    const int bx = blockIdx.x;                   // od pair
    const int n  = blockIdx.y;
    const int tid = threadIdx.x;
    const int wid = tid >> 5, lane = tid & 31;
    const int g = lane >> 2, c4 = lane & 3;

    if (tid < 56) {
        int ch = tid >> 2, cc = tid & 3;
        int kb = ch * 16;
        auto off = [](int k) -> int {
            if (k >= 216) return 0;
            int kd = k / 36, r = k % 36;
            return kd * 1104 + (r / 6) * 92 + (r % 6);
        };
        uint32_t o0 = (uint32_t)off(kb + 2 * cc);
        uint32_t o2 = (uint32_t)off(kb + 2 * cc + 8);
        sGoffP[tid] = o0 | (o2 << 16);
    }

    // B-fragments: per-lane constants, loaded once from global
    uint2 bbA[14], bbB[14];
    #pragma unroll
    for (int ch = 0; ch < 14; ch++) {
        bbA[ch] = __ldg((const uint2*)(g_w1f + ((ch * 2 + 0) * 32 + lane) * 2));
        bbB[ch] = __ldg((const uint2*)(g_w1f + ((ch * 2 + 1) * 32 + lane) * 2));
    }

    const float bv00 = __ldg(b1 + 2 * c4),     bv01 = __ldg(b1 + 2 * c4 + 1);
    const float bv10 = __ldg(b1 + 2 * c4 + 8), bv11 = __ldg(b1 + 2 * c4 + 9);

    const __nv_bfloat16* xb = g_xb + (size_t)n * 778688 + (size_t)(4 * bx) * 8464;
    const size_t nBase = (size_t)(n * 16) * 85184;

    auto issue = [&](int grp) {
        __nv_bfloat16* dst = sWinB[grp & 1];
        const __nv_bfloat16* xs = xb + (8 * grp) * 92;
        for (int f = tid; f < 2208; f += 256) {
            int row = f / 23, q = f - row * 23;
            int ld = row / 12, lh = row - ld * 12;
            cp8(dst + row * 92 + q * 4, xs + (size_t)ld * 8464 + lh * 92 + q * 4);
        }
    };

    issue(0);
    CP_COMMIT();
    __syncthreads();                              // sGoffP visible

    uint32_t op[14];
    #pragma unroll
    for (int ch = 0; ch < 14; ch++) op[ch] = sGoffP[ch * 4 + c4];

    for (int grp = 0; grp < 11; grp++) {
        if (grp < 10) {
            issue(grp + 1);
            CP_COMMIT();
            CP_WAIT1();
        } else {
            CP_WAIT0();
        }
        __syncthreads();
        const __nv_bfloat16* Win = sWinB[grp & 1];

        for (int tt = wid; tt < 22; tt += 8) {
            const int pr0 = tt * 16 + g, pr1 = pr0 + 8;
            int odl0 = pr0 / 176, r0 = pr0 % 176, ohr0 = r0 / 44, ow0 = r0 % 44;
            int odl1 = pr1 / 176, r1 = pr1 % 176, ohr1 = r1 / 44, ow1 = r1 % 44;
            const int wb0 = odl0 * 2208 + ohr0 * 184 + 2 * ow0;
            const int wb1 = odl1 * 2208 + ohr1 * 184 + 2 * ow1;

            float d[8];
            #pragma unroll
            for (int i = 0; i < 8; i++) d[i] = 0.f;

            #pragma unroll
            for (int ch = 0; ch < 14; ch++) {
                int o0 = (int)(op[ch] & 0xFFFFu);
                int o2 = (int)(op[ch] >> 16);
                uint32_t a0 = *(const uint32_t*)(Win + wb0 + o0);
                uint32_t a1 = *(const uint32_t*)(Win + wb1 + o0);
                uint32_t a2 = *(const uint32_t*)(Win + wb0 + o2);
                uint32_t a3 = *(const uint32_t*)(Win + wb1 + o2);
                mma16816(d,     a0, a1, a2, a3, bbA[ch].x, bbA[ch].y);
                mma16816(d + 4, a0, a1, a2, a3, bbB[ch].x, bbB[ch].y);
            }

            size_t ob0 = nBase + (size_t)(2 * bx + odl0) * 1936
                       + (4 * grp + ohr0) * 44 + ow0;
            size_t ob1 = nBase + (size_t)(2 * bx + odl1) * 1936
                       + (4 * grp + ohr1) * 44 + ow1;
            const int co = 2 * c4;
            g_c1b[ob0 + (size_t)(co)     * 85184] = __float2bfloat16(leaky(d[0] + bv00));
            g_c1b[ob0 + (size_t)(co + 1) * 85184] = __float2bfloat16(leaky(d[1] + bv01));
            g_c1b[ob1 + (size_t)(co)     * 85184] = __float2bfloat16(leaky(d[2] + bv00));
            g_c1b[ob1 + (size_t)(co + 1) * 85184] = __float2bfloat16(leaky(d[3] + bv01));
            g_c1b[ob0 + (size_t)(co + 8) * 85184] = __float2bfloat16(leaky(d[4] + bv10));
            g_c1b[ob0 + (size_t)(co + 9) * 85184] = __float2bfloat16(leaky(d[5] + bv11));
            g_c1b[ob1 + (size_t)(co + 8) * 85184] = __float2bfloat16(leaky(d[6] + bv10));
            g_c1b[ob1 + (size_t)(co + 9) * 85184] = __float2bfloat16(leaky(d[7] + bv11));
        }
        __syncthreads();
    }
}

// =======================================================================
// conv2 via mma.sync bf16; goff pairs preloaded to registers
// =======================================================================
__global__ __launch_bounds__(256) void conv2_mma_kernel(const float* __restrict__ b2)
{
    extern __shared__ char smemc[];
    int*            sGoff2 = (int*)smemc;                       // 128
    uint32_t*       sWf = (uint32_t*)(smemc + 512);             // 2 x 2048
    __nv_bfloat16*  sIn = (__nv_bfloat16*)(smemc + 16896);      // 2 x 9680

    const int od = blockIdx.x;
    const int n  = blockIdx.y;
    const int tid = threadIdx.x;
    const int wid = tid >> 5, lane = tid & 31;
    const int g = lane >> 2, c4 = lane & 3;

    if (tid < 128) {
        int tap = tid, o = 0;
        if (tap < 125) {
            int kd = tap / 25, r = tap % 25;
            o = kd * 1936 + (r / 5) * 44 + (r % 5);
        }
        sGoff2[tid] = o;
    }

    auto issue = [&](int cin) {
        int buf = cin & 1;
        const __nv_bfloat16* srcI =
            g_c1b + (size_t)(n * 16 + cin) * 85184 + (size_t)(3 * od) * 1936;
        __nv_bfloat16* dI = sIn + buf * 9680;
        for (int f = tid; f < 2420; f += 256)
            cp8(dI + f * 4, srcI + f * 4);
        const uint32_t* srcW = g_w2f + cin * 2048;
        uint32_t* dW = sWf + buf * 2048;
        for (int f = tid; f < 512; f += 256)
            cp16(dW + f * 4, srcW + f * 4);
    };

    float acc[2][16];
    #pragma unroll
    for (int t = 0; t < 2; t++)
        #pragma unroll
        for (int i = 0; i < 16; i++) acc[t][i] = 0.f;

    issue(0);
    CP_COMMIT();
    __syncthreads();                              // sGoff2 visible

    // preload packed goff pairs (offsets < 2^16)
    uint32_t p01[8], p23[8];
    #pragma unroll
    for (int ch = 0; ch < 8; ch++) {
        int kb = ch * 16;
        p01[ch] = (uint32_t)sGoff2[kb + 2 * c4]
                | ((uint32_t)sGoff2[kb + 2 * c4 + 1] << 16);
        p23[ch] = (uint32_t)sGoff2[kb + 2 * c4 + 8]
                | ((uint32_t)sGoff2[kb + 2 * c4 + 9] << 16);
    }

    for (int cin = 0; cin < 16; cin++) {
        if (cin < 15) {
            issue(cin + 1);
            CP_COMMIT();
            CP_WAIT1();
        } else {
            CP_WAIT0();
        }
        __syncthreads();

        const int buf = cin & 1;
        const __nv_bfloat16* In = sIn + buf * 9680;
        const uint32_t* Wf = sWf + buf * 2048;

        #pragma unroll
        for (int ti = 0; ti < 2; ti++) {
            const int tile = wid + ti * 8;
            if (tile >= 13) break;
            const int pr0 = tile * 16 + g, pr1 = pr0 + 8;
            const int p0 = pr0 < 196 ? pr0 : 195;
            const int p1 = pr1 < 196 ? pr1 : 195;
            const int b0 = (p0 / 14) * 132 + (p0 % 14) * 3;
            const int b1 = (p1 / 14) * 132 + (p1 % 14) * 3;

            #pragma unroll
            for (int ch = 0; ch < 8; ch++) {
                int o0 = (int)(p01[ch] & 0xFFFFu), o1 = (int)(p01[ch] >> 16);
                int o2 = (int)(p23[ch] & 0xFFFFu), o3 = (int)(p23[ch] >> 16);
                uint32_t a0 = ld2bf(In, b0 + o0, b0 + o1);
                uint32_t a1 = ld2bf(In, b1 + o0, b1 + o1);
                uint32_t a2 = ld2bf(In, b0 + o2, b0 + o3);
                uint32_t a3 = ld2bf(In, b1 + o2, b1 + o3);
                #pragma unroll
                for (int nt = 0; nt < 4; nt++) {
                    uint2 bb = *(const uint2*)&Wf[((ch * 4 + nt) * 32 + lane) * 2];
                    mma16816(acc[ti] + nt * 4, a0, a1, a2, a3, bb.x, bb.y);
                }
            }
        }
        __syncthreads();
    }

    #pragma unroll
    for (int ti = 0; ti < 2; ti++) {
        const int tile = wid + ti * 8;
        if (tile >= 13) break;
        const int pr0 = tile * 16 + g, pr1 = pr0 + 8;
        #pragma unroll
        for (int nt = 0; nt < 4; nt++) {
            const int c0 = nt * 8 + 2 * c4;
            const float bb0 = __ldg(b2 + c0), bb1 = __ldg(b2 + c0 + 1);
            if (pr0 < 196) {
                size_t o = (size_t)(n * 32 + c0) * 2744 + od * 196 + pr0;
                g_c2b[o]        = __float2bfloat16(leaky(acc[ti][nt * 4 + 0] + bb0));
                g_c2b[o + 2744] = __float2bfloat16(leaky(acc[ti][nt * 4 + 1] + bb1));
            }
            if (pr1 < 196) {
                size_t o = (size_t)(n * 32 + c0) * 2744 + od * 196 + pr1;
                g_c2b[o]        = __float2bfloat16(leaky(acc[ti][nt * 4 + 2] + bb0));
                g_c2b[o + 2744] = __float2bfloat16(leaky(acc[ti][nt * 4 + 3] + bb1));
            }
        }
    }
}

// =======================================================================
// conv3 via mma.sync bf16: block per n. M=64 pos, N=48, K=32x128.
// =======================================================================
__global__ __launch_bounds__(256) void conv3_mma_kernel(const float* __restrict__ b3)
{
    __shared__ int sGoff3[128];
    __shared__ __align__(16) uint32_t sWf3[2][3072];
    __shared__ __align__(16) __nv_bfloat16 sIn3[2][2744];

    const int n = blockIdx.x;
    const int tid = threadIdx.x;
    const int wid = tid >> 5, lane = tid & 31;
    const int g = lane >> 2, c4 = lane & 3;
    const int mt = wid & 3, nh = wid >> 2;

    if (tid < 128) {
        int tap = tid, o = 0;
        if (tap < 125) {
            int kd = tap / 25, r = tap % 25;
            o = kd * 196 + (r / 5) * 14 + (r % 5);
        }
        sGoff3[tid] = o;
    }

    auto issue = [&](int cin) {
        int buf = cin & 1;
        const __nv_bfloat16* srcI = g_c2b + (size_t)(n * 32 + cin) * 2744;
        __nv_bfloat16* dI = sIn3[buf];
        for (int f = tid; f < 686; f += 256)
            cp8(dI + f * 4, srcI + f * 4);
        const uint32_t* srcW = g_w3f + (size_t)cin * 3072;
        uint32_t* dW = sWf3[buf];
        for (int f = tid; f < 768; f += 256)
            cp16(dW + f * 4, srcW + f * 4);
    };

    const int pr0 = mt * 16 + g, pr1 = pr0 + 8;
    const int b0 = 588 * (pr0 >> 4) + 42 * ((pr0 >> 2) & 3) + 3 * (pr0 & 3);
    const int b1 = 588 * (pr1 >> 4) + 42 * ((pr1 >> 2) & 3) + 3 * (pr1 & 3);

    float acc[3][4];
    #pragma unroll
    for (int j = 0; j < 3; j++)
        #pragma unroll
        for (int i = 0; i < 4; i++) acc[j][i] = 0.f;

    issue(0);
    CP_COMMIT();

    for (int cin = 0; cin < 32; cin++) {
        if (cin < 31) {
            issue(cin + 1);
            CP_COMMIT();
            CP_WAIT1();
        } else {
            CP_WAIT0();
        }
        __syncthreads();

        const int buf = cin & 1;
        const __nv_bfloat16* In = sIn3[buf];
        const uint32_t* Wf = sWf3[buf];

        #pragma unroll
        for (int ch = 0; ch < 8; ch++) {
            const int kb = ch * 16;
            int o0 = sGoff3[kb + 2 * c4],     o1 = sGoff3[kb + 2 * c4 + 1];
            int o2 = sGoff3[kb + 2 * c4 + 8], o3 = sGoff3[kb + 2 * c4 + 9];
            uint32_t a0 = ld2bf(In, b0 + o0, b0 + o1);
            uint32_t a1 = ld2bf(In, b1 + o0, b1 + o1);
            uint32_t a2 = ld2bf(In, b0 + o2, b0 + o3);
            uint32_t a3 = ld2bf(In, b1 + o2, b1 + o3);
            #pragma unroll
            for (int j = 0; j < 3; j++) {
                const int nt = nh * 3 + j;
                uint2 bb = *(const uint2*)&Wf[((ch * 6 + nt) * 32 + lane) * 2];
                mma16816(acc[j], a0, a1, a2, a3, bb.x, bb.y);
            }
        }
        __syncthreads();
    }

    #pragma unroll
    for (int j = 0; j < 3; j++) {
        const int c0 = (nh * 3 + j) * 8 + 2 * c4;
        const float bb0 = __ldg(b3 + c0), bb1 = __ldg(b3 + c0 + 1);
        size_t o0 = (size_t)(n * 48 + c0) * 64;
        g_c3[o0 + pr0]      = leaky(acc[j][0] + bb0);
        g_c3[o0 + 64 + pr0] = leaky(acc[j][1] + bb1);
        g_c3[o0 + pr1]      = leaky(acc[j][2] + bb0);
        g_c3[o0 + 64 + pr1] = leaky(acc[j][3] + bb1);
    }
}

// =======================================================================
// conv4 + feature
// =======================================================================
__global__ __launch_bounds__(256) void conv4_kernel(
    const float* __restrict__ w4, const float* __restrict__ b4)
{
    const int n  = blockIdx.x;
    const int c0 = blockIdx.y * 8;

    __shared__ float sIn[48 * 64];
    __shared__ float sRed[256];

    const int tid = threadIdx.x;
    const float* src = g_c3 + (size_t)n * 3072;
    for (int idx = tid; idx < 3072; idx += 256) sIn[idx] = src[idx];
    __syncthreads();

    const int sub = tid >> 6;
    const int loc = tid & 63;
    const int c   = loc >> 3;
    const int p   = loc & 7;
    const int od = p >> 2, oh = (p >> 1) & 1, ow = p & 1;

    float acc = 0.f;
    const float* wb = w4 + (size_t)(c0 + c) * 48 * 27;
    #pragma unroll
    for (int ci = 0; ci < 12; ci++) {
        int cin = sub * 12 + ci;
        const float* s  = sIn + cin * 64;
        const float* wk = wb + cin * 27;
        #pragma unroll
        for (int kd = 0; kd < 3; kd++)
            #pragma unroll
            for (int kh = 0; kh < 3; kh++)
                #pragma unroll
                for (int kw = 0; kw < 3; kw++)
                    acc = fmaf(s[(od + kd) * 16 + (oh + kh) * 4 + (ow + kw)],
                               __ldg(wk + kd * 9 + kh * 3 + kw), acc);
    }
    sRed[tid] = acc;
    __syncthreads();
    if (sub == 0) {
        float v = sRed[loc] + sRed[loc + 64] + sRed[loc + 128] + sRed[loc + 192];
        g_feat[n * 512 + (c0 + c) * 8 + p] = leaky(v + b4[c0 + c]);
    }
}

// =======================================================================
// M = feature @ T
// =======================================================================
__global__ __launch_bounds__(256) void mmul_kernel(const float* __restrict__ T)
{
    const int i = blockIdx.x;
    __shared__ float sF[512];
    const int tid = threadIdx.x;
    for (int k = tid; k < 512; k += 256) sF[k] = g_feat[i * 512 + k];
    __syncthreads();

    float acc0 = 0.f, acc1 = 0.f, acc2 = 0.f, acc3 = 0.f;
    for (int k = 0; k < 512; k++) {
        float v = sF[k];
        const float* tr = T + (size_t)k * 1024;
        acc0 = fmaf(v, tr[tid], acc0);
        acc1 = fmaf(v, tr[tid + 256], acc1);
        acc2 = fmaf(v, tr[tid + 512], acc2);
        acc3 = fmaf(v, tr[tid + 768], acc3);
    }
    g_M[i * 1024 + tid] = acc0;
    g_M[i * 1024 + tid + 256] = acc1;
    g_M[i * 1024 + tid + 512] = acc2;
    g_M[i * 1024 + tid + 768] = acc3;
}

// =======================================================================
// out_T[i,c] = sum_j exp( sum_k |M[i,c,k]-M[j,c,k]| )
// =======================================================================
__global__ __launch_bounds__(256) void mbd_kernel()
{
    const int i = blockIdx.x;
    __shared__ float sMi[1024];
    __shared__ float sRed[256];
    const int tid = threadIdx.x;
    const int c = tid & 63;
    const int js = tid >> 6;

    for (int k = tid; k < 1024; k += 256) sMi[k] = g_M[i * 1024 + k];
    __syncthreads();

    const float4* mi4 = (const float4*)(sMi + c * 16);
    float4 a0 = mi4[0], a1 = mi4[1], a2 = mi4[2], a3 = mi4[3];

    float acc = 0.f;
    for (int j = js; j < 64; j += 4) {
        const float4* mj4 = (const float4*)(g_M + j * 1024 + c * 16);
        float4 b0 = mj4[0], b1 = mj4[1], b2 = mj4[2], b3 = mj4[3];
        float d =
            fabsf(a0.x - b0.x) + fabsf(a0.y - b0.y) + fabsf(a0.z - b0.z) + fabsf(a0.w - b0.w) +
            fabsf(a1.x - b1.x) + fabsf(a1.y - b1.y) + fabsf(a1.z - b1.z) + fabsf(a1.w - b1.w) +
            fabsf(a2.x - b2.x) + fabsf(a2.y - b2.y) + fabsf(a2.z - b2.z) + fabsf(a2.w - b2.w) +
            fabsf(a3.x - b3.x) + fabsf(a3.y - b3.y) + fabsf(a3.z - b3.z) + fabsf(a3.w - b3.w);
        acc += expf(d);
    }
    sRed[tid] = acc;
    __syncthreads();
    if (js == 0) {
        float s = sRed[c] + sRed[c + 64] + sRed[c + 128] + sRed[c + 192];
        g_outT[i * 64 + c] = s;
    }
}

// =======================================================================
// final
// =======================================================================
__global__ __launch_bounds__(64) void final_kernel(
    const float* __restrict__ Wm, const float* __restrict__ bm,
    float* __restrict__ out)
{
    const int i = threadIdx.x;
    float z = bm[0];
    const float* f = g_feat + i * 512;
    #pragma unroll 8
    for (int k = 0; k < 512; k++) z = fmaf(f[k], Wm[k], z);
    const float* t = g_outT + i * 64;
    #pragma unroll 8
    for (int c = 0; c < 64; c++) z = fmaf(t[c], Wm[512 + c], z);
    out[i] = 1.f / (1.f + expf(-z));
}

// =======================================================================
extern "C" void kernel_launch(void* const* d_in, const int* in_sizes, int n_in,
                              void* d_out, int out_size)
{
    const float* x  = (const float*)d_in[0];
    const float* w1 = (const float*)d_in[1];
    const float* b1 = (const float*)d_in[2];
    const float* w2 = (const float*)d_in[3];
    const float* b2 = (const float*)d_in[4];
    const float* w3 = (const float*)d_in[5];
    const float* b3 = (const float*)d_in[6];
    const float* w4 = (const float*)d_in[7];
    const float* b4 = (const float*)d_in[8];
    const float* T  = (const float*)d_in[9];
    const float* Wm = (const float*)d_in[10];
    const float* bm = (const float*)d_in[11];
    float* out = (float*)d_out;

    const int conv2_smem = 16896 + 2 * 19360;           // 55616 B
    cudaFuncSetAttribute(conv2_mma_kernel,
                         cudaFuncAttributeMaxDynamicSharedMemorySize, conv2_smem);

    prep_xb_kernel<<<48672, 256>>>(x);
    prep_w1f_kernel<<<4, 256>>>(w1);
    prep_w2f_kernel<<<64, 256>>>(w2);
    prep_w3f_kernel<<<192, 256>>>(w3);
    conv1_mma_kernel<<<dim3(22, 64), 256>>>(b1);
    conv2_mma_kernel<<<dim3(14, 64), 256, conv2_smem>>>(b2);
    conv3_mma_kernel<<<64, 256>>>(b3);
    conv4_kernel<<<dim3(64, 8), 256>>>(w4, b4);
    mmul_kernel<<<64, 256>>>(T);
    mbd_kernel<<<64, 256>>>();
    final_kernel<<<1, 64>>>(Wm, bm, out);
}